// round 10
// baseline (speedup 1.0000x reference)
#include <cuda_runtime.h>
#include <cuda_bf16.h>
#include <cstdint>

#define MAXN 50000
#define MAXE 800000
#define GG   1024
#define DD   128
#define LL   3

// ---------------------------------------------------------------------------
// Static scratch
// ---------------------------------------------------------------------------
__device__ float g_h[MAXN * DD];
__device__ __nv_bfloat16 g_zhi[MAXN * DD];
__device__ __nv_bfloat16 g_zlo[MAXN * DD];
__device__ __nv_bfloat16 g_thi[MAXN * 2 * DD];
__device__ __nv_bfloat16 g_tlo[MAXN * 2 * DD];
__device__ float g_vn[GG * DD];
__device__ float g_gsum[GG * DD];
__device__ __nv_bfloat16 g_vthi[GG * 2 * DD];
__device__ __nv_bfloat16 g_vtlo[GG * 2 * DD];
__device__ int   g_cnt[MAXN];
__device__ int   g_off[MAXN + 1];
__device__ int   g_rank[MAXE];
__device__ int2  g_csr[MAXE];                  // packed {src, abits}
// Preconverted weights: B^T [N][K] bf16 hi/lo. 10 slots of 32768:
// W1 l0..2, W2 l0..2, vn1 l0..1, vn2 l0..1
__device__ __nv_bfloat16 g_Bhi[10 * 32768];
__device__ __nv_bfloat16 g_Blo[10 * 32768];

// ---------------------------------------------------------------------------
// PTX helpers
// ---------------------------------------------------------------------------
__device__ __forceinline__ uint32_t cvta_s(const void* p) {
    uint32_t a;
    asm("{ .reg .u64 t; cvta.to.shared.u64 t, %1; cvt.u32.u64 %0, t; }"
        : "=r"(a) : "l"(p));
    return a;
}
#define LDSM_X4(r0, r1, r2, r3, addr)                                          \
    asm volatile("ldmatrix.sync.aligned.m8n8.x4.shared.b16 {%0,%1,%2,%3}, [%4];"\
                 : "=r"(r0), "=r"(r1), "=r"(r2), "=r"(r3) : "r"(addr))
#define MMA_BF16(d0, d1, d2, d3, a0, a1, a2, a3, b0, b1)                       \
    asm volatile("mma.sync.aligned.m16n8k16.row.col.f32.bf16.bf16.f32 "        \
                 "{%0,%1,%2,%3}, {%4,%5,%6,%7}, {%8,%9}, {%0,%1,%2,%3};"       \
                 : "+f"(d0), "+f"(d1), "+f"(d2), "+f"(d3)                      \
                 : "r"(a0), "r"(a1), "r"(a2), "r"(a3), "r"(b0), "r"(b1))
#define CP_ASYNC16(dst, src, sz)                                               \
    asm volatile("cp.async.cg.shared.global [%0], [%1], 16, %2;"               \
                 :: "r"(dst), "l"(src), "r"(sz))
#define CP_COMMIT() asm volatile("cp.async.commit_group;" ::: "memory")
#define CP_WAIT1()  asm volatile("cp.async.wait_group 1;" ::: "memory")

__device__ __forceinline__ void split_bf16(float v, unsigned short& hi,
                                           unsigned short& lo) {
    __nv_bfloat16 h = __float2bfloat16_rn(v);
    hi = __bfloat16_as_ushort(h);
    lo = __bfloat16_as_ushort(__float2bfloat16_rn(v - __bfloat162float(h)));
}

// ---------------------------------------------------------------------------
// Mega-fused preprocessing (weights + cnt/gsum zero + atom encode + vn init)
// ---------------------------------------------------------------------------
__global__ void fused_pre_k(
    const float* __restrict__ W1, const float* __restrict__ W2,
    const float* __restrict__ vnW1, const float* __restrict__ vnW2,
    __nv_bfloat16* __restrict__ Bhi, __nv_bfloat16* __restrict__ Blo,
    int* __restrict__ cnt, float* __restrict__ gsum,
    const int* __restrict__ xa, const float* __restrict__ emb,
    float* __restrict__ h,
    const float* __restrict__ v0, float* __restrict__ vn,
    int n, int c1, int c3, int c4b, int c5) {
    int blk = blockIdx.x;
    int tid = threadIdx.x;
    if (blk < c1) {
        int idx = blk * 256 + tid;
        if (idx < 10 * 32768) {
            int slot = idx >> 15;
            int r = idx & 32767;
            const float* W;
            int Nd;
            if (slot < 3)      { W = W1 + (size_t)slot * 32768;         Nd = 256; }
            else if (slot < 6) { W = W2 + (size_t)(slot - 3) * 32768;   Nd = 128; }
            else if (slot < 8) { W = vnW1 + (size_t)(slot - 6) * 32768; Nd = 256; }
            else               { W = vnW2 + (size_t)(slot - 8) * 32768; Nd = 128; }
            int Kd = 32768 / Nd;
            int k = r / Nd, nn = r % Nd;
            unsigned short hi, lo;
            split_bf16(W[r], hi, lo);
            size_t o = (size_t)slot * 32768 + (size_t)nn * Kd + k;
            Bhi[o] = __ushort_as_bfloat16(hi);
            Blo[o] = __ushort_as_bfloat16(lo);
        }
    } else if (blk < c3) {
        int i = (blk - c1) * 256 + tid;
        if (i < n) cnt[i] = 0;
    } else if (blk < c4b) {
        int i = (blk - c3) * 256 + tid;
        if (i < GG * 32)
            *(float4*)(gsum + i * 4) = make_float4(0.f, 0.f, 0.f, 0.f);
    } else if (blk < c5) {
        int idx = (blk - c4b) * 256 + tid;
        if (idx < n * 32) {
            int node = idx >> 5;
            int cc4 = (idx & 31) << 2;
            float4 s = make_float4(0.f, 0.f, 0.f, 0.f);
#pragma unroll
            for (int f = 0; f < 9; f++) {
                int v = xa[node * 9 + f];
                float4 e = *(const float4*)(emb + (f * 100 + v) * DD + cc4);
                s.x += e.x; s.y += e.y; s.z += e.z; s.w += e.w;
            }
            *(float4*)(h + node * DD + cc4) = s;
        }
    } else {
        int idx = (blk - c5) * 256 + tid;
        if (idx < GG * 32) {
            int cc4 = (idx & 31) << 2;
            *(float4*)(vn + idx * 4) = *(const float4*)(v0 + cc4);
        }
    }
}

// ---------------------------------------------------------------------------
// CSR build: count also records each edge's rank within its dst bucket.
// ---------------------------------------------------------------------------
__global__ void count_k(const int* __restrict__ ei, int* __restrict__ cnt,
                        int* __restrict__ rank, int ecnt) {
    int j = (blockIdx.x * blockDim.x + threadIdx.x) * 4;
    if (j + 3 < ecnt) {
        int4 d = *(const int4*)(ei + ecnt + j);
        rank[j + 0] = atomicAdd(&cnt[d.x], 1);
        rank[j + 1] = atomicAdd(&cnt[d.y], 1);
        rank[j + 2] = atomicAdd(&cnt[d.z], 1);
        rank[j + 3] = atomicAdd(&cnt[d.w], 1);
    } else {
        for (int q = j; q < ecnt; q++)
            rank[q] = atomicAdd(&cnt[ei[ecnt + q]], 1);
    }
}
__global__ void scan_k(const int* __restrict__ cnt, int* __restrict__ off,
                       int n, int ecnt) {
    __shared__ int part[1024];
    int t = threadIdx.x;
    int chunk = (n + 1023) >> 10;
    int beg = t * chunk;
    int end = min(beg + chunk, n);
    int s = 0;
    for (int i = beg; i < end; i++) s += cnt[i];
    part[t] = s;
    __syncthreads();
    for (int d = 1; d < 1024; d <<= 1) {
        int v = (t >= d) ? part[t - d] : 0;
        __syncthreads();
        if (t >= d) part[t] += v;
        __syncthreads();
    }
    int run = (t == 0) ? 0 : part[t - 1];
    for (int i = beg; i < end; i++) {
        off[i] = run;
        run += cnt[i];
    }
    if (t == 0) off[n] = ecnt;
}
__global__ void scatter_k(const int* __restrict__ ei, const int* __restrict__ ea,
                          const int* __restrict__ off, const int* __restrict__ rank,
                          int2* __restrict__ csr, int ecnt) {
    int j = blockIdx.x * blockDim.x + threadIdx.x;
    if (j >= ecnt) return;
    int dst = ei[ecnt + j];
    int cm = (ea[j * 3] << 8) | (ea[j * 3 + 1] << 4) | ea[j * 3 + 2];
    csr[off[dst] + rank[j]] = make_int2(ei[j], cm);
}

// ---------------------------------------------------------------------------
// h += vn[batch]; optionally gsum[batch] += h (post-update)
// ---------------------------------------------------------------------------
__global__ void add_vn_k(float* __restrict__ h, const float* __restrict__ vn,
                         const int* __restrict__ batch,
                         float* __restrict__ gsum, int n, int dosum) {
    int idx = blockIdx.x * blockDim.x + threadIdx.x;
    if (idx >= n * 32) return;
    int node = idx >> 5;
    int c4 = (idx & 31) << 2;
    int g = batch[node];
    float4 hv = *(float4*)(h + idx * 4);
    float4 vv = *(const float4*)(vn + g * DD + c4);
    hv.x += vv.x; hv.y += vv.y; hv.z += vv.z; hv.w += vv.w;
    *(float4*)(h + idx * 4) = hv;
    if (dosum) {
        float* p = gsum + g * DD + c4;
        asm volatile("red.global.add.v4.f32 [%0], {%1,%2,%3,%4};"
                     :: "l"(p), "f"(hv.x), "f"(hv.y), "f"(hv.z), "f"(hv.w)
                     : "memory");
    }
}

// ---------------------------------------------------------------------------
// Edge gather (CSR): bond tables cached in SMEM (15 KB), halving L2 traffic.
//   z[node] = (1+eps)*h[node] + sum relu(h[src] + b0[a0]+b1[a1]+b2[a2])
// ---------------------------------------------------------------------------
__global__ void edge_csr_k(const int* __restrict__ off,
                           const int2* __restrict__ csr,
                           const float* __restrict__ bond_l,  // [3][10][128]
                           const float* __restrict__ h,
                           const float* __restrict__ eps_p,
                           __nv_bfloat16* __restrict__ zhi,
                           __nv_bfloat16* __restrict__ zlo, int n) {
    __shared__ __align__(16) float tbl[3 * 10 * DD];
    for (int i = threadIdx.x; i < 960; i += 256)
        ((float4*)tbl)[i] = ((const float4*)bond_l)[i];
    __syncthreads();

    int warp = (blockIdx.x * blockDim.x + threadIdx.x) >> 5;
    if (warp >= n) return;
    int lane = threadIdx.x & 31;
    int c4 = lane << 2;
    const float* t0 = tbl + c4;
    const float* t1 = tbl + 10 * DD + c4;
    const float* t2 = tbl + 20 * DD + c4;

    float4 acc = make_float4(0.f, 0.f, 0.f, 0.f);
    int beg = off[warp], end = off[warp + 1];
    const unsigned FULL = 0xffffffffu;
    for (int base = beg; base < end; base += 32) {
        int m = min(32, end - base);
        int s = 0, cm = 0;
        if (base + lane < end) {
            int2 e = csr[base + lane];
            s = e.x; cm = e.y;
        }
        int k = 0;
        for (; k + 4 <= m; k += 4) {
            int s0 = __shfl_sync(FULL, s, k),     c0 = __shfl_sync(FULL, cm, k);
            int s1 = __shfl_sync(FULL, s, k + 1), c1 = __shfl_sync(FULL, cm, k + 1);
            int s2 = __shfl_sync(FULL, s, k + 2), c2 = __shfl_sync(FULL, cm, k + 2);
            int s3 = __shfl_sync(FULL, s, k + 3), c3 = __shfl_sync(FULL, cm, k + 3);
            float4 h0 = *(const float4*)(h + (size_t)s0 * DD + c4);
            float4 h1 = *(const float4*)(h + (size_t)s1 * DD + c4);
            float4 h2 = *(const float4*)(h + (size_t)s2 * DD + c4);
            float4 h3 = *(const float4*)(h + (size_t)s3 * DD + c4);
#define EVAL(HH, CC)                                                            \
            {                                                                   \
                float4 ea_ = *(const float4*)(t0 + ((CC) >> 8) * DD);           \
                float4 eb_ = *(const float4*)(t1 + (((CC) >> 4) & 15) * DD);    \
                float4 ec_ = *(const float4*)(t2 + ((CC) & 15) * DD);           \
                acc.x += fmaxf(HH.x + (ea_.x + eb_.x + ec_.x), 0.f);            \
                acc.y += fmaxf(HH.y + (ea_.y + eb_.y + ec_.y), 0.f);            \
                acc.z += fmaxf(HH.z + (ea_.z + eb_.z + ec_.z), 0.f);            \
                acc.w += fmaxf(HH.w + (ea_.w + eb_.w + ec_.w), 0.f);            \
            }
            EVAL(h0, c0) EVAL(h1, c1) EVAL(h2, c2) EVAL(h3, c3)
        }
        for (; k < m; k++) {
            int ss = __shfl_sync(FULL, s, k);
            int cc = __shfl_sync(FULL, cm, k);
            float4 hv = *(const float4*)(h + (size_t)ss * DD + c4);
            EVAL(hv, cc)
        }
#undef EVAL
    }
    float al = 1.0f + *eps_p;
    float4 hv = *(const float4*)(h + (size_t)warp * DD + c4);
    unsigned short h0, h1, h2, h3, l0, l1, l2, l3;
    split_bf16(al * hv.x + acc.x, h0, l0);
    split_bf16(al * hv.y + acc.y, h1, l1);
    split_bf16(al * hv.z + acc.z, h2, l2);
    split_bf16(al * hv.w + acc.w, h3, l3);
    uint2 hp = make_uint2((uint32_t)h0 | ((uint32_t)h1 << 16),
                          (uint32_t)h2 | ((uint32_t)h3 << 16));
    uint2 lp = make_uint2((uint32_t)l0 | ((uint32_t)l1 << 16),
                          (uint32_t)l2 | ((uint32_t)l3 << 16));
    *(uint2*)(zhi + (size_t)warp * DD + c4) = hp;
    *(uint2*)(zlo + (size_t)warp * DD + c4) = lp;
}

// ---------------------------------------------------------------------------
// Persistent unified GEMM with vn rider tiles, cp.async 2-stage, BK=32.
// ---------------------------------------------------------------------------
#define ASTR 40
#define STG_A_HI 0
#define STG_A_LO 10240
#define STG_B_HI 20480
#define STG_B_LO 25600
#define STG_SZ   30720
#define SM_TOT   61440

__global__ void __launch_bounds__(256, 2)
gemm_uni_k(int gx0, int ny0, int M0,
           const __nv_bfloat16* __restrict__ A0hi,
           const __nv_bfloat16* __restrict__ A0lo,
           const __nv_bfloat16* __restrict__ B0hi,
           const __nv_bfloat16* __restrict__ B0lo,
           const float* __restrict__ lb0, const float* __restrict__ g0,
           const float* __restrict__ be0, const float* __restrict__ m0,
           const float* __restrict__ vv0,
           float* __restrict__ C0f,
           __nv_bfloat16* __restrict__ C0hi, __nv_bfloat16* __restrict__ C0lo,
           int gx1, int ny1, int M1,
           const float* __restrict__ A1f, const float* __restrict__ A1f2,
           const __nv_bfloat16* __restrict__ A1hi,
           const __nv_bfloat16* __restrict__ A1lo,
           const __nv_bfloat16* __restrict__ B1hi,
           const __nv_bfloat16* __restrict__ B1lo,
           const float* __restrict__ lb1, const float* __restrict__ g1,
           const float* __restrict__ be1, const float* __restrict__ m1,
           const float* __restrict__ vv1,
           float* __restrict__ C1f,
           __nv_bfloat16* __restrict__ C1hi, __nv_bfloat16* __restrict__ C1lo,
           float4* __restrict__ zbuf, int zcnt4,
           int N, int K, int do_relu) {
    extern __shared__ char dsm[];
    __shared__ float s_sc[64], s_sb[64];

    int tid = threadIdx.x;
    int lane = tid & 31, wid = tid >> 5;
    uint32_t smbase = cvta_s(dsm);

    if (zbuf) {
        for (int i = blockIdx.x * 256 + tid; i < zcnt4; i += gridDim.x * 256)
            zbuf[i] = make_float4(0.f, 0.f, 0.f, 0.f);
    }

    int ntile0 = gx0 * ny0;
    int total = ntile0 + gx1 * ny1;

    int wm = (wid >> 1) * 32;
    int wn = (wid & 1) * 32;
    int r8 = lane & 7, g = lane >> 3;
    int acolg = (g >> 1) << 3;
    int bcolg = (g & 1) << 3;
    int nch = K >> 5;

    for (int tile = blockIdx.x; tile < total; tile += gridDim.x) {
        int part = 0, bx, by;
        int q = tile;
        if (q < ntile0) { bx = q / ny0; by = q % ny0; }
        else { part = 1; q -= ntile0; bx = q / ny1; by = q % ny1; }

        int M = part ? M1 : M0;
        const __nv_bfloat16* Ahi = part ? A1hi : A0hi;
        const __nv_bfloat16* Alo = part ? A1lo : A0lo;
        const __nv_bfloat16* Bh  = part ? B1hi : B0hi;
        const __nv_bfloat16* Bl  = part ? B1lo : B0lo;
        const float* lb = part ? lb1 : lb0;
        const float* gg = part ? g1 : g0;
        const float* bbp = part ? be1 : be0;
        const float* mmp = part ? m1 : m0;
        const float* vvp = part ? vv1 : vv0;
        float* Cf = part ? C1f : C0f;
        __nv_bfloat16* Chi = part ? C1hi : C0hi;
        __nv_bfloat16* Clo = part ? C1lo : C0lo;
        const float* Af  = part ? A1f  : (const float*)0;
        const float* Af2 = part ? A1f2 : (const float*)0;
        bool fp32A = (part && Af);

        int bm = bx * 128;
        int bn = by * 64;

        __syncthreads();   // guard s_sc reuse vs previous tile's epilogue
        if (tid < 64) {
            int col = bn + tid;
            float s = gg[col] * rsqrtf(vvp[col] + 1e-5f);
            s_sc[tid] = s;
            s_sb[tid] = (lb[col] - mmp[col]) * s + bbp[col];
        }

        float acc[2][4][4];
#pragma unroll
        for (int a = 0; a < 2; a++)
#pragma unroll
            for (int b = 0; b < 4; b++)
#pragma unroll
                for (int qq = 0; qq < 4; qq++) acc[a][b][qq] = 0.f;

        int arow = wm + ((g & 1) << 3) + r8;
        int brow = wn + ((g >> 1) << 3) + r8;

        auto issue_async = [&](int ch, int stg) {
            int cc = ch << 5;
            uint32_t sb = smbase + stg * STG_SZ;
#pragma unroll
            for (int it = 0; it < 2; it++) {
                int i = tid + it * 256;
                int row = i >> 2, c8 = (i & 3) << 3;
                int sz = (bm + row < M) ? 16 : 0;
                const __nv_bfloat16* sh = Ahi + (size_t)(bm + row) * K + cc + c8;
                const __nv_bfloat16* sl = Alo + (size_t)(bm + row) * K + cc + c8;
                uint32_t doff = (uint32_t)(row * ASTR + c8) * 2;
                CP_ASYNC16(sb + STG_A_HI + doff, sh, sz);
                CP_ASYNC16(sb + STG_A_LO + doff, sl, sz);
            }
            {
                int row = tid >> 2, c8 = (tid & 3) << 3;
                const __nv_bfloat16* sh = Bh + (size_t)(bn + row) * K + cc + c8;
                const __nv_bfloat16* sl = Bl + (size_t)(bn + row) * K + cc + c8;
                uint32_t doff = (uint32_t)(row * ASTR + c8) * 2;
                CP_ASYNC16(sb + STG_B_HI + doff, sh, 16);
                CP_ASYNC16(sb + STG_B_LO + doff, sl, 16);
            }
        };
        auto issue_sync = [&](int ch, int stg) {
            int cc = ch << 5;
            char* sb = dsm + stg * STG_SZ;
#pragma unroll
            for (int it = 0; it < 4; it++) {
                int i = tid + it * 256;
                int row = i >> 3, c4 = (i & 7) << 2;
                float4 v = make_float4(0.f, 0.f, 0.f, 0.f);
                if (bm + row < M) {
                    v = *(const float4*)(Af + (size_t)(bm + row) * K + cc + c4);
                    float4 w = *(const float4*)(Af2 + (size_t)(bm + row) * K + cc + c4);
                    v.x += w.x; v.y += w.y; v.z += w.z; v.w += w.w;
                }
                unsigned short h0, h1, h2, h3, l0, l1, l2, l3;
                split_bf16(v.x, h0, l0); split_bf16(v.y, h1, l1);
                split_bf16(v.z, h2, l2); split_bf16(v.w, h3, l3);
                int off = (row * ASTR + c4) * 2;
                *(uint2*)(sb + STG_A_HI + off) = make_uint2(
                    (uint32_t)h0 | ((uint32_t)h1 << 16),
                    (uint32_t)h2 | ((uint32_t)h3 << 16));
                *(uint2*)(sb + STG_A_LO + off) = make_uint2(
                    (uint32_t)l0 | ((uint32_t)l1 << 16),
                    (uint32_t)l2 | ((uint32_t)l3 << 16));
            }
            {
                int row = tid >> 2, c8 = (tid & 3) << 3;
                uint4 vh = *(const uint4*)(Bh + (size_t)(bn + row) * K + cc + c8);
                uint4 vl = *(const uint4*)(Bl + (size_t)(bn + row) * K + cc + c8);
                int off = (row * ASTR + c8) * 2;
                *(uint4*)(sb + STG_B_HI + off) = vh;
                *(uint4*)(sb + STG_B_LO + off) = vl;
            }
        };

        if (fp32A) issue_sync(0, 0);
        else       issue_async(0, 0);
        CP_COMMIT();

        for (int ch = 0; ch < nch; ch++) {
            if (ch + 1 < nch) {
                if (fp32A) issue_sync(ch + 1, (ch + 1) & 1);
                else       issue_async(ch + 1, (ch + 1) & 1);
            }
            CP_COMMIT();
            CP_WAIT1();
            __syncthreads();

            uint32_t sb = smbase + (ch & 1) * STG_SZ;
#pragma unroll
            for (int ks = 0; ks < 2; ks++) {
                int kk = ks << 4;
                uint32_t ah0, ah1, ah2, ah3, ah4, ah5, ah6, ah7;
                uint32_t am0, am1, am2, am3, am4, am5, am6, am7;
                uint32_t bh0, bh1, bh2, bh3, bh4, bh5, bh6, bh7;
                uint32_t bm0, bm1, bm2, bm3, bm4, bm5, bm6, bm7;
                {
                    uint32_t ad0 = sb + STG_A_HI + ((arow) * ASTR + kk + acolg) * 2;
                    uint32_t ad1 = sb + STG_A_HI + ((arow + 16) * ASTR + kk + acolg) * 2;
                    LDSM_X4(ah0, ah1, ah2, ah3, ad0);
                    LDSM_X4(ah4, ah5, ah6, ah7, ad1);
                    LDSM_X4(am0, am1, am2, am3, ad0 + (STG_A_LO - STG_A_HI));
                    LDSM_X4(am4, am5, am6, am7, ad1 + (STG_A_LO - STG_A_HI));
                    uint32_t bd0 = sb + STG_B_HI + ((brow) * ASTR + kk + bcolg) * 2;
                    uint32_t bd1 = sb + STG_B_HI + ((brow + 16) * ASTR + kk + bcolg) * 2;
                    LDSM_X4(bh0, bh1, bh2, bh3, bd0);
                    LDSM_X4(bh4, bh5, bh6, bh7, bd1);
                    LDSM_X4(bm0, bm1, bm2, bm3, bd0 + (STG_B_LO - STG_B_HI));
                    LDSM_X4(bm4, bm5, bm6, bm7, bd1 + (STG_B_LO - STG_B_HI));
                }
#define DO_NT(mt, nt, B0, B1, BL0, BL1, A0, A1, A2_, A3, AL0, AL1, AL2, AL3)    \
                MMA_BF16(acc[mt][nt][0], acc[mt][nt][1], acc[mt][nt][2],        \
                         acc[mt][nt][3], A0, A1, A2_, A3, B0, B1);              \
                MMA_BF16(acc[mt][nt][0], acc[mt][nt][1], acc[mt][nt][2],        \
                         acc[mt][nt][3], A0, A1, A2_, A3, BL0, BL1);            \
                MMA_BF16(acc[mt][nt][0], acc[mt][nt][1], acc[mt][nt][2],        \
                         acc[mt][nt][3], AL0, AL1, AL2, AL3, B0, B1);
                DO_NT(0, 0, bh0, bh1, bm0, bm1, ah0, ah1, ah2, ah3, am0, am1, am2, am3)
                DO_NT(0, 1, bh2, bh3, bm2, bm3, ah0, ah1, ah2, ah3, am0, am1, am2, am3)
                DO_NT(0, 2, bh4, bh5, bm4, bm5, ah0, ah1, ah2, ah3, am0, am1, am2, am3)
                DO_NT(0, 3, bh6, bh7, bm6, bm7, ah0, ah1, ah2, ah3, am0, am1, am2, am3)
                DO_NT(1, 0, bh0, bh1, bm0, bm1, ah4, ah5, ah6, ah7, am4, am5, am6, am7)
                DO_NT(1, 1, bh2, bh3, bm2, bm3, ah4, ah5, ah6, ah7, am4, am5, am6, am7)
                DO_NT(1, 2, bh4, bh5, bm4, bm5, ah4, ah5, ah6, ah7, am4, am5, am6, am7)
                DO_NT(1, 3, bh6, bh7, bm6, bm7, ah4, ah5, ah6, ah7, am4, am5, am6, am7)
#undef DO_NT
            }
            __syncthreads();
        }

        // ---- epilogue
        int rq = lane >> 2, cq = (lane & 3) * 2;
        bool outBF = (Chi != (__nv_bfloat16*)0);
#pragma unroll
        for (int mt = 0; mt < 2; mt++) {
            int r0 = bm + wm + mt * 16 + rq;
#pragma unroll
            for (int nt = 0; nt < 4; nt++) {
                int c0 = wn + nt * 8 + cq;
                float s0 = s_sc[c0], s1 = s_sc[c0 + 1];
                float t0 = s_sb[c0], t1 = s_sb[c0 + 1];
                float v0 = acc[mt][nt][0] * s0 + t0;
                float v1 = acc[mt][nt][1] * s1 + t1;
                float v2 = acc[mt][nt][2] * s0 + t0;
                float v3 = acc[mt][nt][3] * s1 + t1;
                if (do_relu) {
                    v0 = fmaxf(v0, 0.f); v1 = fmaxf(v1, 0.f);
                    v2 = fmaxf(v2, 0.f); v3 = fmaxf(v3, 0.f);
                }
                if (outBF) {
                    unsigned short h0, h1, h2, h3, l0, l1, l2, l3;
                    split_bf16(v0, h0, l0); split_bf16(v1, h1, l1);
                    split_bf16(v2, h2, l2); split_bf16(v3, h3, l3);
                    if (r0 < M) {
                        *(uint32_t*)(Chi + (size_t)r0 * N + bn + c0) =
                            (uint32_t)h0 | ((uint32_t)h1 << 16);
                        *(uint32_t*)(Clo + (size_t)r0 * N + bn + c0) =
                            (uint32_t)l0 | ((uint32_t)l1 << 16);
                    }
                    if (r0 + 8 < M) {
                        *(uint32_t*)(Chi + (size_t)(r0 + 8) * N + bn + c0) =
                            (uint32_t)h2 | ((uint32_t)h3 << 16);
                        *(uint32_t*)(Clo + (size_t)(r0 + 8) * N + bn + c0) =
                            (uint32_t)l2 | ((uint32_t)l3 << 16);
                    }
                } else {
                    if (r0 < M)
                        *(float2*)(Cf + (size_t)r0 * N + bn + c0) = make_float2(v0, v1);
                    if (r0 + 8 < M)
                        *(float2*)(Cf + (size_t)(r0 + 8) * N + bn + c0) = make_float2(v2, v3);
                }
            }
        }
    }
}

// ---------------------------------------------------------------------------
// Host driver
// ---------------------------------------------------------------------------
extern "C" void kernel_launch(void* const* d_in, const int* in_sizes, int n_in,
                              void* d_out, int out_size) {
    const int*   x_atom  = (const int*)d_in[0];
    const int*   ei      = (const int*)d_in[1];
    const int*   ea      = (const int*)d_in[2];
    const int*   batch   = (const int*)d_in[3];
    const float* atomemb = (const float*)d_in[4];
    const float* vn0     = (const float*)d_in[5];
    const float* bond    = (const float*)d_in[6];
    const float* eps     = (const float*)d_in[7];
    const float* W1      = (const float*)d_in[8];
    const float* b1v     = (const float*)d_in[9];
    const float* bn1g    = (const float*)d_in[10];
    const float* bn1b    = (const float*)d_in[11];
    const float* bn1m    = (const float*)d_in[12];
    const float* bn1v    = (const float*)d_in[13];
    const float* W2      = (const float*)d_in[14];
    const float* b2v     = (const float*)d_in[15];
    const float* bng     = (const float*)d_in[16];
    const float* bnb     = (const float*)d_in[17];
    const float* bnm     = (const float*)d_in[18];
    const float* bnv     = (const float*)d_in[19];
    const float* vnW1    = (const float*)d_in[20];
    const float* vnb1    = (const float*)d_in[21];
    const float* vbn1g   = (const float*)d_in[22];
    const float* vbn1b   = (const float*)d_in[23];
    const float* vbn1m   = (const float*)d_in[24];
    const float* vbn1v   = (const float*)d_in[25];
    const float* vnW2    = (const float*)d_in[26];
    const float* vnb2    = (const float*)d_in[27];
    const float* vbn2g   = (const float*)d_in[28];
    const float* vbn2b   = (const float*)d_in[29];
    const float* vbn2m   = (const float*)d_in[30];
    const float* vbn2v   = (const float*)d_in[31];

    int n = in_sizes[3];
    int ecnt = in_sizes[1] / 2;

    float *h, *vn, *gsum;
    __nv_bfloat16 *zhi, *zlo, *thi, *tlo, *vthi, *vtlo, *Bhi, *Blo;
    int *cnt, *off, *rank;
    int2* csr;
    cudaGetSymbolAddress((void**)&h, g_h);
    cudaGetSymbolAddress((void**)&zhi, g_zhi);
    cudaGetSymbolAddress((void**)&zlo, g_zlo);
    cudaGetSymbolAddress((void**)&thi, g_thi);
    cudaGetSymbolAddress((void**)&tlo, g_tlo);
    cudaGetSymbolAddress((void**)&vn, g_vn);
    cudaGetSymbolAddress((void**)&gsum, g_gsum);
    cudaGetSymbolAddress((void**)&vthi, g_vthi);
    cudaGetSymbolAddress((void**)&vtlo, g_vtlo);
    cudaGetSymbolAddress((void**)&cnt, g_cnt);
    cudaGetSymbolAddress((void**)&off, g_off);
    cudaGetSymbolAddress((void**)&rank, g_rank);
    cudaGetSymbolAddress((void**)&csr, g_csr);
    cudaGetSymbolAddress((void**)&Bhi, g_Bhi);
    cudaGetSymbolAddress((void**)&Blo, g_Blo);

    cudaFuncSetAttribute(gemm_uni_k, cudaFuncAttributeMaxDynamicSharedMemorySize,
                         SM_TOT);

    const int WSLOT = 32768;
    int gridND = (n * 32 + 255) / 256;

    int c1 = (10 * 32768 + 255) / 256;
    int c3 = c1 + (n + 255) / 256;
    int c4b = c3 + (GG * 32 + 255) / 256;
    int c5 = c4b + gridND;
    int c6 = c5 + (GG * 32 + 255) / 256;
    fused_pre_k<<<c6, 256>>>(W1, W2, vnW1, vnW2, Bhi, Blo,
                             cnt, gsum, x_atom, atomemb, h, vn0, vn,
                             n, c1, c3, c4b, c5);
    count_k<<<(ecnt / 4 + 255) / 256, 256>>>(ei, cnt, rank, ecnt);
    scan_k<<<1, 1024>>>(cnt, off, n, ecnt);
    scatter_k<<<(ecnt + 255) / 256, 256>>>(ei, ea, off, rank, csr, ecnt);

    int gridM = (n + 127) / 128;
    int gxv = GG / 128;
    const int PERSIST = 296;   // 148 SMs x 2 CTAs
    for (int l = 0; l < LL; l++) {
        int hasVN = (l < LL - 1) ? 1 : 0;
        add_vn_k<<<gridND, 256>>>(h, vn, batch, gsum, n, hasVN);
        edge_csr_k<<<gridND, 256>>>(off, csr, bond + (size_t)l * 3 * 10 * DD, h,
                                    eps + l, zhi, zlo, n);
        {
            int ny0 = 4, ny1 = 4;
            int gx1 = hasVN ? gxv : 0;
            int total = gridM * ny0 + gx1 * ny1;
            int grid = total < PERSIST ? total : PERSIST;
            gemm_uni_k<<<grid, 256, SM_TOT>>>(
                gridM, ny0, n,
                zhi, zlo,
                Bhi + (size_t)l * WSLOT, Blo + (size_t)l * WSLOT,
                b1v + l * 256, bn1g + l * 256, bn1b + l * 256,
                bn1m + l * 256, bn1v + l * 256,
                nullptr, thi, tlo,
                gx1, ny1, hasVN ? GG : 0,
                vn, gsum, nullptr, nullptr,
                Bhi + (size_t)(6 + l) * WSLOT, Blo + (size_t)(6 + l) * WSLOT,
                vnb1 + l * 256, vbn1g + l * 256, vbn1b + l * 256,
                vbn1m + l * 256, vbn1v + l * 256,
                nullptr, vthi, vtlo,
                nullptr, 0,
                256, 128, 1);
        }
        {
            float* outp = (l == LL - 1) ? (float*)d_out : h;
            int ny0 = 2, ny1 = 2;
            int gx1 = hasVN ? gxv : 0;
            int total = gridM * ny0 + gx1 * ny1;
            int grid = total < PERSIST ? total : PERSIST;
            gemm_uni_k<<<grid, 256, SM_TOT>>>(
                gridM, ny0, n,
                thi, tlo,
                Bhi + (size_t)(3 + l) * WSLOT, Blo + (size_t)(3 + l) * WSLOT,
                b2v + l * 128, bng + l * 128, bnb + l * 128,
                bnm + l * 128, bnv + l * 128,
                outp, nullptr, nullptr,
                gx1, ny1, hasVN ? GG : 0,
                nullptr, nullptr, vthi, vtlo,
                Bhi + (size_t)(8 + l) * WSLOT, Blo + (size_t)(8 + l) * WSLOT,
                vnb2 + l * 128, vbn2g + l * 128, vbn2b + l * 128,
                vbn2m + l * 128, vbn2v + l * 128,
                vn, nullptr, nullptr,
                (l == 0) ? (float4*)gsum : nullptr, GG * 32,
                128, 256, hasVN);
        }
    }
}

// round 11
// speedup vs baseline: 1.0814x; 1.0814x over previous
#include <cuda_runtime.h>
#include <cuda_bf16.h>
#include <cstdint>

#define MAXN 50000
#define MAXE 800000
#define GG   1024
#define DD   128
#define LL   3

// ---------------------------------------------------------------------------
// Static scratch
// ---------------------------------------------------------------------------
__device__ float g_h[MAXN * DD];
__device__ __nv_bfloat16 g_zhi[MAXN * DD];
__device__ __nv_bfloat16 g_zlo[MAXN * DD];
__device__ __nv_bfloat16 g_thi[MAXN * 2 * DD];
__device__ __nv_bfloat16 g_tlo[MAXN * 2 * DD];
__device__ float g_vn[GG * DD];
__device__ float g_gsum[GG * DD];
__device__ __nv_bfloat16 g_vthi[GG * 2 * DD];
__device__ __nv_bfloat16 g_vtlo[GG * 2 * DD];
__device__ float g_cb[LL * 1000 * DD];
__device__ int   g_cnt[MAXN];
__device__ int   g_off[MAXN + 1];
__device__ int   g_rank[MAXE];
__device__ int2  g_csr[MAXE];                  // packed {src, combo}
// Preconverted weights: B^T [N][K] bf16 hi/lo. 10 slots of 32768:
// W1 l0..2, W2 l0..2, vn1 l0..1, vn2 l0..1
__device__ __nv_bfloat16 g_Bhi[10 * 32768];
__device__ __nv_bfloat16 g_Blo[10 * 32768];

// ---------------------------------------------------------------------------
// PTX helpers
// ---------------------------------------------------------------------------
__device__ __forceinline__ uint32_t cvta_s(const void* p) {
    uint32_t a;
    asm("{ .reg .u64 t; cvta.to.shared.u64 t, %1; cvt.u32.u64 %0, t; }"
        : "=r"(a) : "l"(p));
    return a;
}
#define LDSM_X4(r0, r1, r2, r3, addr)                                          \
    asm volatile("ldmatrix.sync.aligned.m8n8.x4.shared.b16 {%0,%1,%2,%3}, [%4];"\
                 : "=r"(r0), "=r"(r1), "=r"(r2), "=r"(r3) : "r"(addr))
#define MMA_BF16(d0, d1, d2, d3, a0, a1, a2, a3, b0, b1)                       \
    asm volatile("mma.sync.aligned.m16n8k16.row.col.f32.bf16.bf16.f32 "        \
                 "{%0,%1,%2,%3}, {%4,%5,%6,%7}, {%8,%9}, {%0,%1,%2,%3};"       \
                 : "+f"(d0), "+f"(d1), "+f"(d2), "+f"(d3)                      \
                 : "r"(a0), "r"(a1), "r"(a2), "r"(a3), "r"(b0), "r"(b1))
#define CP_ASYNC16(dst, src, sz)                                               \
    asm volatile("cp.async.cg.shared.global [%0], [%1], 16, %2;"               \
                 :: "r"(dst), "l"(src), "r"(sz))
#define CP_COMMIT() asm volatile("cp.async.commit_group;" ::: "memory")
#define CP_WAIT1()  asm volatile("cp.async.wait_group 1;" ::: "memory")

__device__ __forceinline__ void split_bf16(float v, unsigned short& hi,
                                           unsigned short& lo) {
    __nv_bfloat16 h = __float2bfloat16_rn(v);
    hi = __bfloat16_as_ushort(h);
    lo = __bfloat16_as_ushort(__float2bfloat16_rn(v - __bfloat162float(h)));
}

// ---------------------------------------------------------------------------
// Mega-fused preprocessing (weights + combo table + zeros + atom + vn init)
// ---------------------------------------------------------------------------
__global__ void fused_pre_k(
    const float* __restrict__ W1, const float* __restrict__ W2,
    const float* __restrict__ vnW1, const float* __restrict__ vnW2,
    __nv_bfloat16* __restrict__ Bhi, __nv_bfloat16* __restrict__ Blo,
    const float* __restrict__ bond, float* __restrict__ cb,
    int* __restrict__ cnt, float* __restrict__ gsum,
    const int* __restrict__ xa, const float* __restrict__ emb,
    float* __restrict__ h,
    const float* __restrict__ v0, float* __restrict__ vn,
    int n, int c1, int c2, int c3, int c4b, int c5) {
    int blk = blockIdx.x;
    int tid = threadIdx.x;
    if (blk < c1) {
        int idx = blk * 256 + tid;
        if (idx < 10 * 32768) {
            int slot = idx >> 15;
            int r = idx & 32767;
            const float* W;
            int Nd;
            if (slot < 3)      { W = W1 + (size_t)slot * 32768;         Nd = 256; }
            else if (slot < 6) { W = W2 + (size_t)(slot - 3) * 32768;   Nd = 128; }
            else if (slot < 8) { W = vnW1 + (size_t)(slot - 6) * 32768; Nd = 256; }
            else               { W = vnW2 + (size_t)(slot - 8) * 32768; Nd = 128; }
            int Kd = 32768 / Nd;
            int k = r / Nd, nn = r % Nd;
            unsigned short hi, lo;
            split_bf16(W[r], hi, lo);
            size_t o = (size_t)slot * 32768 + (size_t)nn * Kd + k;
            Bhi[o] = __ushort_as_bfloat16(hi);
            Blo[o] = __ushort_as_bfloat16(lo);
        }
    } else if (blk < c2) {
        int idx = (blk - c1) * 256 + tid;
        if (idx < LL * 1000 * 32) {
            int cc4 = (idx & 31) << 2;
            int i = (idx >> 5) % 1000;
            int l = (idx >> 5) / 1000;
            int f0 = i / 100, f1 = (i / 10) % 10, f2 = i % 10;
            float4 a = *(const float4*)(bond + ((size_t)(l * 3 + 0) * 10 + f0) * DD + cc4);
            float4 b = *(const float4*)(bond + ((size_t)(l * 3 + 1) * 10 + f1) * DD + cc4);
            float4 c = *(const float4*)(bond + ((size_t)(l * 3 + 2) * 10 + f2) * DD + cc4);
            float4 o;
            o.x = a.x + b.x + c.x; o.y = a.y + b.y + c.y;
            o.z = a.z + b.z + c.z; o.w = a.w + b.w + c.w;
            *(float4*)(cb + ((size_t)(l * 1000 + i)) * DD + cc4) = o;
        }
    } else if (blk < c3) {
        int i = (blk - c2) * 256 + tid;
        if (i < n) cnt[i] = 0;
    } else if (blk < c4b) {
        int i = (blk - c3) * 256 + tid;
        if (i < GG * 32)
            *(float4*)(gsum + i * 4) = make_float4(0.f, 0.f, 0.f, 0.f);
    } else if (blk < c5) {
        int idx = (blk - c4b) * 256 + tid;
        if (idx < n * 32) {
            int node = idx >> 5;
            int cc4 = (idx & 31) << 2;
            float4 s = make_float4(0.f, 0.f, 0.f, 0.f);
#pragma unroll
            for (int f = 0; f < 9; f++) {
                int v = xa[node * 9 + f];
                float4 e = *(const float4*)(emb + (f * 100 + v) * DD + cc4);
                s.x += e.x; s.y += e.y; s.z += e.z; s.w += e.w;
            }
            *(float4*)(h + node * DD + cc4) = s;
        }
    } else {
        int idx = (blk - c5) * 256 + tid;
        if (idx < GG * 32) {
            int cc4 = (idx & 31) << 2;
            *(float4*)(vn + idx * 4) = *(const float4*)(v0 + cc4);
        }
    }
}

// ---------------------------------------------------------------------------
// CSR build: count also records each edge's rank within its dst bucket.
// ---------------------------------------------------------------------------
__global__ void count_k(const int* __restrict__ ei, int* __restrict__ cnt,
                        int* __restrict__ rank, int ecnt) {
    int j = (blockIdx.x * blockDim.x + threadIdx.x) * 4;
    if (j + 3 < ecnt) {
        int4 d = *(const int4*)(ei + ecnt + j);
        rank[j + 0] = atomicAdd(&cnt[d.x], 1);
        rank[j + 1] = atomicAdd(&cnt[d.y], 1);
        rank[j + 2] = atomicAdd(&cnt[d.z], 1);
        rank[j + 3] = atomicAdd(&cnt[d.w], 1);
    } else {
        for (int q = j; q < ecnt; q++)
            rank[q] = atomicAdd(&cnt[ei[ecnt + q]], 1);
    }
}
__global__ void scan_k(const int* __restrict__ cnt, int* __restrict__ off,
                       int n, int ecnt) {
    __shared__ int part[1024];
    int t = threadIdx.x;
    int chunk = (n + 1023) >> 10;
    int beg = t * chunk;
    int end = min(beg + chunk, n);
    int s = 0;
    for (int i = beg; i < end; i++) s += cnt[i];
    part[t] = s;
    __syncthreads();
    for (int d = 1; d < 1024; d <<= 1) {
        int v = (t >= d) ? part[t - d] : 0;
        __syncthreads();
        if (t >= d) part[t] += v;
        __syncthreads();
    }
    int run = (t == 0) ? 0 : part[t - 1];
    for (int i = beg; i < end; i++) {
        off[i] = run;
        run += cnt[i];
    }
    if (t == 0) off[n] = ecnt;
}
__global__ void scatter_k(const int* __restrict__ ei, const int* __restrict__ ea,
                          const int* __restrict__ off, const int* __restrict__ rank,
                          int2* __restrict__ csr, int ecnt) {
    int j = blockIdx.x * blockDim.x + threadIdx.x;
    if (j >= ecnt) return;
    int dst = ei[ecnt + j];
    int cm = ea[j * 3] * 100 + ea[j * 3 + 1] * 10 + ea[j * 3 + 2];
    csr[off[dst] + rank[j]] = make_int2(ei[j], cm);
}

// ---------------------------------------------------------------------------
// h += vn[batch]; optionally gsum[batch] += h (post-update)
// ---------------------------------------------------------------------------
__global__ void add_vn_k(float* __restrict__ h, const float* __restrict__ vn,
                         const int* __restrict__ batch,
                         float* __restrict__ gsum, int n, int dosum) {
    int idx = blockIdx.x * blockDim.x + threadIdx.x;
    if (idx >= n * 32) return;
    int node = idx >> 5;
    int c4 = (idx & 31) << 2;
    int g = batch[node];
    float4 hv = *(float4*)(h + idx * 4);
    float4 vv = *(const float4*)(vn + g * DD + c4);
    hv.x += vv.x; hv.y += vv.y; hv.z += vv.z; hv.w += vv.w;
    *(float4*)(h + idx * 4) = hv;
    if (dosum) {
        float* p = gsum + g * DD + c4;
        asm volatile("red.global.add.v4.f32 [%0], {%1,%2,%3,%4};"
                     :: "l"(p), "f"(hv.x), "f"(hv.y), "f"(hv.z), "f"(hv.w)
                     : "memory");
    }
}

// ---------------------------------------------------------------------------
// Edge gather (CSR, packed int2, combined cb table), 8x unrolled
// ---------------------------------------------------------------------------
__global__ void edge_csr_k(const int* __restrict__ off,
                           const int2* __restrict__ csr,
                           const float* __restrict__ cb,
                           const float* __restrict__ h,
                           const float* __restrict__ eps_p,
                           __nv_bfloat16* __restrict__ zhi,
                           __nv_bfloat16* __restrict__ zlo, int n) {
    int warp = (blockIdx.x * blockDim.x + threadIdx.x) >> 5;
    if (warp >= n) return;
    int lane = threadIdx.x & 31;
    int c4 = lane << 2;
    float4 acc = make_float4(0.f, 0.f, 0.f, 0.f);
    int beg = off[warp], end = off[warp + 1];
    const unsigned FULL = 0xffffffffu;
    for (int base = beg; base < end; base += 32) {
        int m = min(32, end - base);
        int s = 0, cm = 0;
        if (base + lane < end) {
            int2 e = csr[base + lane];
            s = e.x; cm = e.y;
        }
        int k = 0;
        for (; k + 8 <= m; k += 8) {
            int sx[8], cx[8];
#pragma unroll
            for (int u = 0; u < 8; u++) {
                sx[u] = __shfl_sync(FULL, s, k + u);
                cx[u] = __shfl_sync(FULL, cm, k + u);
            }
            float4 hh[8], ee[8];
#pragma unroll
            for (int u = 0; u < 8; u++) {
                hh[u] = *(const float4*)(h + (size_t)sx[u] * DD + c4);
                ee[u] = *(const float4*)(cb + (size_t)cx[u] * DD + c4);
            }
#pragma unroll
            for (int u = 0; u < 8; u++) {
                acc.x += fmaxf(hh[u].x + ee[u].x, 0.f);
                acc.y += fmaxf(hh[u].y + ee[u].y, 0.f);
                acc.z += fmaxf(hh[u].z + ee[u].z, 0.f);
                acc.w += fmaxf(hh[u].w + ee[u].w, 0.f);
            }
        }
        for (; k < m; k++) {
            int ss = __shfl_sync(FULL, s, k);
            int cc = __shfl_sync(FULL, cm, k);
            float4 hv = *(const float4*)(h + (size_t)ss * DD + c4);
            float4 ev = *(const float4*)(cb + (size_t)cc * DD + c4);
            acc.x += fmaxf(hv.x + ev.x, 0.f);
            acc.y += fmaxf(hv.y + ev.y, 0.f);
            acc.z += fmaxf(hv.z + ev.z, 0.f);
            acc.w += fmaxf(hv.w + ev.w, 0.f);
        }
    }
    float al = 1.0f + *eps_p;
    float4 hv = *(const float4*)(h + (size_t)warp * DD + c4);
    unsigned short h0, h1, h2, h3, l0, l1, l2, l3;
    split_bf16(al * hv.x + acc.x, h0, l0);
    split_bf16(al * hv.y + acc.y, h1, l1);
    split_bf16(al * hv.z + acc.z, h2, l2);
    split_bf16(al * hv.w + acc.w, h3, l3);
    uint2 hp = make_uint2((uint32_t)h0 | ((uint32_t)h1 << 16),
                          (uint32_t)h2 | ((uint32_t)h3 << 16));
    uint2 lp = make_uint2((uint32_t)l0 | ((uint32_t)l1 << 16),
                          (uint32_t)l2 | ((uint32_t)l3 << 16));
    *(uint2*)(zhi + (size_t)warp * DD + c4) = hp;
    *(uint2*)(zlo + (size_t)warp * DD + c4) = lp;
}

// ---------------------------------------------------------------------------
// Persistent unified GEMM with vn rider tiles, cp.async 2-stage, BK=32.
// ---------------------------------------------------------------------------
#define ASTR 40
#define STG_A_HI 0
#define STG_A_LO 10240
#define STG_B_HI 20480
#define STG_B_LO 25600
#define STG_SZ   30720
#define SM_TOT   61440

__global__ void __launch_bounds__(256, 2)
gemm_uni_k(int gx0, int ny0, int M0,
           const __nv_bfloat16* __restrict__ A0hi,
           const __nv_bfloat16* __restrict__ A0lo,
           const __nv_bfloat16* __restrict__ B0hi,
           const __nv_bfloat16* __restrict__ B0lo,
           const float* __restrict__ lb0, const float* __restrict__ g0,
           const float* __restrict__ be0, const float* __restrict__ m0,
           const float* __restrict__ vv0,
           float* __restrict__ C0f,
           __nv_bfloat16* __restrict__ C0hi, __nv_bfloat16* __restrict__ C0lo,
           int gx1, int ny1, int M1,
           const float* __restrict__ A1f, const float* __restrict__ A1f2,
           const __nv_bfloat16* __restrict__ A1hi,
           const __nv_bfloat16* __restrict__ A1lo,
           const __nv_bfloat16* __restrict__ B1hi,
           const __nv_bfloat16* __restrict__ B1lo,
           const float* __restrict__ lb1, const float* __restrict__ g1,
           const float* __restrict__ be1, const float* __restrict__ m1,
           const float* __restrict__ vv1,
           float* __restrict__ C1f,
           __nv_bfloat16* __restrict__ C1hi, __nv_bfloat16* __restrict__ C1lo,
           float4* __restrict__ zbuf, int zcnt4,
           int N, int K, int do_relu) {
    extern __shared__ char dsm[];
    __shared__ float s_sc[64], s_sb[64];

    int tid = threadIdx.x;
    int lane = tid & 31, wid = tid >> 5;
    uint32_t smbase = cvta_s(dsm);

    if (zbuf) {
        for (int i = blockIdx.x * 256 + tid; i < zcnt4; i += gridDim.x * 256)
            zbuf[i] = make_float4(0.f, 0.f, 0.f, 0.f);
    }

    int ntile0 = gx0 * ny0;
    int total = ntile0 + gx1 * ny1;

    int wm = (wid >> 1) * 32;
    int wn = (wid & 1) * 32;
    int r8 = lane & 7, g = lane >> 3;
    int acolg = (g >> 1) << 3;
    int bcolg = (g & 1) << 3;
    int nch = K >> 5;

    for (int tile = blockIdx.x; tile < total; tile += gridDim.x) {
        int part = 0, bx, by;
        int q = tile;
        if (q < ntile0) { bx = q / ny0; by = q % ny0; }
        else { part = 1; q -= ntile0; bx = q / ny1; by = q % ny1; }

        int M = part ? M1 : M0;
        const __nv_bfloat16* Ahi = part ? A1hi : A0hi;
        const __nv_bfloat16* Alo = part ? A1lo : A0lo;
        const __nv_bfloat16* Bh  = part ? B1hi : B0hi;
        const __nv_bfloat16* Bl  = part ? B1lo : B0lo;
        const float* lb = part ? lb1 : lb0;
        const float* gg = part ? g1 : g0;
        const float* bbp = part ? be1 : be0;
        const float* mmp = part ? m1 : m0;
        const float* vvp = part ? vv1 : vv0;
        float* Cf = part ? C1f : C0f;
        __nv_bfloat16* Chi = part ? C1hi : C0hi;
        __nv_bfloat16* Clo = part ? C1lo : C0lo;
        const float* Af  = part ? A1f  : (const float*)0;
        const float* Af2 = part ? A1f2 : (const float*)0;
        bool fp32A = (part && Af);

        int bm = bx * 128;
        int bn = by * 64;

        __syncthreads();   // guard s_sc reuse vs previous tile's epilogue
        if (tid < 64) {
            int col = bn + tid;
            float s = gg[col] * rsqrtf(vvp[col] + 1e-5f);
            s_sc[tid] = s;
            s_sb[tid] = (lb[col] - mmp[col]) * s + bbp[col];
        }

        float acc[2][4][4];
#pragma unroll
        for (int a = 0; a < 2; a++)
#pragma unroll
            for (int b = 0; b < 4; b++)
#pragma unroll
                for (int qq = 0; qq < 4; qq++) acc[a][b][qq] = 0.f;

        int arow = wm + ((g & 1) << 3) + r8;
        int brow = wn + ((g >> 1) << 3) + r8;

        auto issue_async = [&](int ch, int stg) {
            int cc = ch << 5;
            uint32_t sb = smbase + stg * STG_SZ;
#pragma unroll
            for (int it = 0; it < 2; it++) {
                int i = tid + it * 256;
                int row = i >> 2, c8 = (i & 3) << 3;
                int sz = (bm + row < M) ? 16 : 0;
                const __nv_bfloat16* sh = Ahi + (size_t)(bm + row) * K + cc + c8;
                const __nv_bfloat16* sl = Alo + (size_t)(bm + row) * K + cc + c8;
                uint32_t doff = (uint32_t)(row * ASTR + c8) * 2;
                CP_ASYNC16(sb + STG_A_HI + doff, sh, sz);
                CP_ASYNC16(sb + STG_A_LO + doff, sl, sz);
            }
            {
                int row = tid >> 2, c8 = (tid & 3) << 3;
                const __nv_bfloat16* sh = Bh + (size_t)(bn + row) * K + cc + c8;
                const __nv_bfloat16* sl = Bl + (size_t)(bn + row) * K + cc + c8;
                uint32_t doff = (uint32_t)(row * ASTR + c8) * 2;
                CP_ASYNC16(sb + STG_B_HI + doff, sh, 16);
                CP_ASYNC16(sb + STG_B_LO + doff, sl, 16);
            }
        };
        auto issue_sync = [&](int ch, int stg) {
            int cc = ch << 5;
            char* sb = dsm + stg * STG_SZ;
#pragma unroll
            for (int it = 0; it < 4; it++) {
                int i = tid + it * 256;
                int row = i >> 3, c4 = (i & 7) << 2;
                float4 v = make_float4(0.f, 0.f, 0.f, 0.f);
                if (bm + row < M) {
                    v = *(const float4*)(Af + (size_t)(bm + row) * K + cc + c4);
                    float4 w = *(const float4*)(Af2 + (size_t)(bm + row) * K + cc + c4);
                    v.x += w.x; v.y += w.y; v.z += w.z; v.w += w.w;
                }
                unsigned short h0, h1, h2, h3, l0, l1, l2, l3;
                split_bf16(v.x, h0, l0); split_bf16(v.y, h1, l1);
                split_bf16(v.z, h2, l2); split_bf16(v.w, h3, l3);
                int off = (row * ASTR + c4) * 2;
                *(uint2*)(sb + STG_A_HI + off) = make_uint2(
                    (uint32_t)h0 | ((uint32_t)h1 << 16),
                    (uint32_t)h2 | ((uint32_t)h3 << 16));
                *(uint2*)(sb + STG_A_LO + off) = make_uint2(
                    (uint32_t)l0 | ((uint32_t)l1 << 16),
                    (uint32_t)l2 | ((uint32_t)l3 << 16));
            }
            {
                int row = tid >> 2, c8 = (tid & 3) << 3;
                uint4 vh = *(const uint4*)(Bh + (size_t)(bn + row) * K + cc + c8);
                uint4 vl = *(const uint4*)(Bl + (size_t)(bn + row) * K + cc + c8);
                int off = (row * ASTR + c8) * 2;
                *(uint4*)(sb + STG_B_HI + off) = vh;
                *(uint4*)(sb + STG_B_LO + off) = vl;
            }
        };

        if (fp32A) issue_sync(0, 0);
        else       issue_async(0, 0);
        CP_COMMIT();

        for (int ch = 0; ch < nch; ch++) {
            if (ch + 1 < nch) {
                if (fp32A) issue_sync(ch + 1, (ch + 1) & 1);
                else       issue_async(ch + 1, (ch + 1) & 1);
            }
            CP_COMMIT();
            CP_WAIT1();
            __syncthreads();

            uint32_t sb = smbase + (ch & 1) * STG_SZ;
#pragma unroll
            for (int ks = 0; ks < 2; ks++) {
                int kk = ks << 4;
                uint32_t ah0, ah1, ah2, ah3, ah4, ah5, ah6, ah7;
                uint32_t am0, am1, am2, am3, am4, am5, am6, am7;
                uint32_t bh0, bh1, bh2, bh3, bh4, bh5, bh6, bh7;
                uint32_t bm0, bm1, bm2, bm3, bm4, bm5, bm6, bm7;
                {
                    uint32_t ad0 = sb + STG_A_HI + ((arow) * ASTR + kk + acolg) * 2;
                    uint32_t ad1 = sb + STG_A_HI + ((arow + 16) * ASTR + kk + acolg) * 2;
                    LDSM_X4(ah0, ah1, ah2, ah3, ad0);
                    LDSM_X4(ah4, ah5, ah6, ah7, ad1);
                    LDSM_X4(am0, am1, am2, am3, ad0 + (STG_A_LO - STG_A_HI));
                    LDSM_X4(am4, am5, am6, am7, ad1 + (STG_A_LO - STG_A_HI));
                    uint32_t bd0 = sb + STG_B_HI + ((brow) * ASTR + kk + bcolg) * 2;
                    uint32_t bd1 = sb + STG_B_HI + ((brow + 16) * ASTR + kk + bcolg) * 2;
                    LDSM_X4(bh0, bh1, bh2, bh3, bd0);
                    LDSM_X4(bh4, bh5, bh6, bh7, bd1);
                    LDSM_X4(bm0, bm1, bm2, bm3, bd0 + (STG_B_LO - STG_B_HI));
                    LDSM_X4(bm4, bm5, bm6, bm7, bd1 + (STG_B_LO - STG_B_HI));
                }
#define DO_NT(mt, nt, B0, B1, BL0, BL1, A0, A1, A2_, A3, AL0, AL1, AL2, AL3)    \
                MMA_BF16(acc[mt][nt][0], acc[mt][nt][1], acc[mt][nt][2],        \
                         acc[mt][nt][3], A0, A1, A2_, A3, B0, B1);              \
                MMA_BF16(acc[mt][nt][0], acc[mt][nt][1], acc[mt][nt][2],        \
                         acc[mt][nt][3], A0, A1, A2_, A3, BL0, BL1);            \
                MMA_BF16(acc[mt][nt][0], acc[mt][nt][1], acc[mt][nt][2],        \
                         acc[mt][nt][3], AL0, AL1, AL2, AL3, B0, B1);
                DO_NT(0, 0, bh0, bh1, bm0, bm1, ah0, ah1, ah2, ah3, am0, am1, am2, am3)
                DO_NT(0, 1, bh2, bh3, bm2, bm3, ah0, ah1, ah2, ah3, am0, am1, am2, am3)
                DO_NT(0, 2, bh4, bh5, bm4, bm5, ah0, ah1, ah2, ah3, am0, am1, am2, am3)
                DO_NT(0, 3, bh6, bh7, bm6, bm7, ah0, ah1, ah2, ah3, am0, am1, am2, am3)
                DO_NT(1, 0, bh0, bh1, bm0, bm1, ah4, ah5, ah6, ah7, am4, am5, am6, am7)
                DO_NT(1, 1, bh2, bh3, bm2, bm3, ah4, ah5, ah6, ah7, am4, am5, am6, am7)
                DO_NT(1, 2, bh4, bh5, bm4, bm5, ah4, ah5, ah6, ah7, am4, am5, am6, am7)
                DO_NT(1, 3, bh6, bh7, bm6, bm7, ah4, ah5, ah6, ah7, am4, am5, am6, am7)
#undef DO_NT
            }
            __syncthreads();
        }

        // ---- epilogue
        int rq = lane >> 2, cq = (lane & 3) * 2;
        bool outBF = (Chi != (__nv_bfloat16*)0);
#pragma unroll
        for (int mt = 0; mt < 2; mt++) {
            int r0 = bm + wm + mt * 16 + rq;
#pragma unroll
            for (int nt = 0; nt < 4; nt++) {
                int c0 = wn + nt * 8 + cq;
                float s0 = s_sc[c0], s1 = s_sc[c0 + 1];
                float t0 = s_sb[c0], t1 = s_sb[c0 + 1];
                float v0 = acc[mt][nt][0] * s0 + t0;
                float v1 = acc[mt][nt][1] * s1 + t1;
                float v2 = acc[mt][nt][2] * s0 + t0;
                float v3 = acc[mt][nt][3] * s1 + t1;
                if (do_relu) {
                    v0 = fmaxf(v0, 0.f); v1 = fmaxf(v1, 0.f);
                    v2 = fmaxf(v2, 0.f); v3 = fmaxf(v3, 0.f);
                }
                if (outBF) {
                    unsigned short h0, h1, h2, h3, l0, l1, l2, l3;
                    split_bf16(v0, h0, l0); split_bf16(v1, h1, l1);
                    split_bf16(v2, h2, l2); split_bf16(v3, h3, l3);
                    if (r0 < M) {
                        *(uint32_t*)(Chi + (size_t)r0 * N + bn + c0) =
                            (uint32_t)h0 | ((uint32_t)h1 << 16);
                        *(uint32_t*)(Clo + (size_t)r0 * N + bn + c0) =
                            (uint32_t)l0 | ((uint32_t)l1 << 16);
                    }
                    if (r0 + 8 < M) {
                        *(uint32_t*)(Chi + (size_t)(r0 + 8) * N + bn + c0) =
                            (uint32_t)h2 | ((uint32_t)h3 << 16);
                        *(uint32_t*)(Clo + (size_t)(r0 + 8) * N + bn + c0) =
                            (uint32_t)l2 | ((uint32_t)l3 << 16);
                    }
                } else {
                    if (r0 < M)
                        *(float2*)(Cf + (size_t)r0 * N + bn + c0) = make_float2(v0, v1);
                    if (r0 + 8 < M)
                        *(float2*)(Cf + (size_t)(r0 + 8) * N + bn + c0) = make_float2(v2, v3);
                }
            }
        }
    }
}

// ---------------------------------------------------------------------------
// Host driver
// ---------------------------------------------------------------------------
extern "C" void kernel_launch(void* const* d_in, const int* in_sizes, int n_in,
                              void* d_out, int out_size) {
    const int*   x_atom  = (const int*)d_in[0];
    const int*   ei      = (const int*)d_in[1];
    const int*   ea      = (const int*)d_in[2];
    const int*   batch   = (const int*)d_in[3];
    const float* atomemb = (const float*)d_in[4];
    const float* vn0     = (const float*)d_in[5];
    const float* bond    = (const float*)d_in[6];
    const float* eps     = (const float*)d_in[7];
    const float* W1      = (const float*)d_in[8];
    const float* b1v     = (const float*)d_in[9];
    const float* bn1g    = (const float*)d_in[10];
    const float* bn1b    = (const float*)d_in[11];
    const float* bn1m    = (const float*)d_in[12];
    const float* bn1v    = (const float*)d_in[13];
    const float* W2      = (const float*)d_in[14];
    const float* b2v     = (const float*)d_in[15];
    const float* bng     = (const float*)d_in[16];
    const float* bnb     = (const float*)d_in[17];
    const float* bnm     = (const float*)d_in[18];
    const float* bnv     = (const float*)d_in[19];
    const float* vnW1    = (const float*)d_in[20];
    const float* vnb1    = (const float*)d_in[21];
    const float* vbn1g   = (const float*)d_in[22];
    const float* vbn1b   = (const float*)d_in[23];
    const float* vbn1m   = (const float*)d_in[24];
    const float* vbn1v   = (const float*)d_in[25];
    const float* vnW2    = (const float*)d_in[26];
    const float* vnb2    = (const float*)d_in[27];
    const float* vbn2g   = (const float*)d_in[28];
    const float* vbn2b   = (const float*)d_in[29];
    const float* vbn2m   = (const float*)d_in[30];
    const float* vbn2v   = (const float*)d_in[31];

    int n = in_sizes[3];
    int ecnt = in_sizes[1] / 2;

    float *h, *vn, *gsum, *cb;
    __nv_bfloat16 *zhi, *zlo, *thi, *tlo, *vthi, *vtlo, *Bhi, *Blo;
    int *cnt, *off, *rank;
    int2* csr;
    cudaGetSymbolAddress((void**)&h, g_h);
    cudaGetSymbolAddress((void**)&zhi, g_zhi);
    cudaGetSymbolAddress((void**)&zlo, g_zlo);
    cudaGetSymbolAddress((void**)&thi, g_thi);
    cudaGetSymbolAddress((void**)&tlo, g_tlo);
    cudaGetSymbolAddress((void**)&vn, g_vn);
    cudaGetSymbolAddress((void**)&gsum, g_gsum);
    cudaGetSymbolAddress((void**)&vthi, g_vthi);
    cudaGetSymbolAddress((void**)&vtlo, g_vtlo);
    cudaGetSymbolAddress((void**)&cb, g_cb);
    cudaGetSymbolAddress((void**)&cnt, g_cnt);
    cudaGetSymbolAddress((void**)&off, g_off);
    cudaGetSymbolAddress((void**)&rank, g_rank);
    cudaGetSymbolAddress((void**)&csr, g_csr);
    cudaGetSymbolAddress((void**)&Bhi, g_Bhi);
    cudaGetSymbolAddress((void**)&Blo, g_Blo);

    cudaFuncSetAttribute(gemm_uni_k, cudaFuncAttributeMaxDynamicSharedMemorySize,
                         SM_TOT);

    const int WSLOT = 32768;
    int gridND = (n * 32 + 255) / 256;

    int c1 = (10 * 32768 + 255) / 256;
    int c2 = c1 + (LL * 1000 * 32 + 255) / 256;
    int c3 = c2 + (n + 255) / 256;
    int c4b = c3 + (GG * 32 + 255) / 256;
    int c5 = c4b + gridND;
    int c6 = c5 + (GG * 32 + 255) / 256;
    fused_pre_k<<<c6, 256>>>(W1, W2, vnW1, vnW2, Bhi, Blo, bond, cb,
                             cnt, gsum, x_atom, atomemb, h, vn0, vn,
                             n, c1, c2, c3, c4b, c5);
    count_k<<<(ecnt / 4 + 255) / 256, 256>>>(ei, cnt, rank, ecnt);
    scan_k<<<1, 1024>>>(cnt, off, n, ecnt);
    scatter_k<<<(ecnt + 255) / 256, 256>>>(ei, ea, off, rank, csr, ecnt);

    int gridM = (n + 127) / 128;
    int gxv = GG / 128;
    const int PERSIST = 296;   // 148 SMs x 2 CTAs
    for (int l = 0; l < LL; l++) {
        int hasVN = (l < LL - 1) ? 1 : 0;
        add_vn_k<<<gridND, 256>>>(h, vn, batch, gsum, n, hasVN);
        edge_csr_k<<<gridND, 256>>>(off, csr, cb + (size_t)l * 1000 * DD, h,
                                    eps + l, zhi, zlo, n);
        {
            int ny0 = 4, ny1 = 4;
            int gx1 = hasVN ? gxv : 0;
            int total = gridM * ny0 + gx1 * ny1;
            int grid = total < PERSIST ? total : PERSIST;
            gemm_uni_k<<<grid, 256, SM_TOT>>>(
                gridM, ny0, n,
                zhi, zlo,
                Bhi + (size_t)l * WSLOT, Blo + (size_t)l * WSLOT,
                b1v + l * 256, bn1g + l * 256, bn1b + l * 256,
                bn1m + l * 256, bn1v + l * 256,
                nullptr, thi, tlo,
                gx1, ny1, hasVN ? GG : 0,
                vn, gsum, nullptr, nullptr,
                Bhi + (size_t)(6 + l) * WSLOT, Blo + (size_t)(6 + l) * WSLOT,
                vnb1 + l * 256, vbn1g + l * 256, vbn1b + l * 256,
                vbn1m + l * 256, vbn1v + l * 256,
                nullptr, vthi, vtlo,
                nullptr, 0,
                256, 128, 1);
        }
        {
            float* outp = (l == LL - 1) ? (float*)d_out : h;
            int ny0 = 2, ny1 = 2;
            int gx1 = hasVN ? gxv : 0;
            int total = gridM * ny0 + gx1 * ny1;
            int grid = total < PERSIST ? total : PERSIST;
            gemm_uni_k<<<grid, 256, SM_TOT>>>(
                gridM, ny0, n,
                thi, tlo,
                Bhi + (size_t)(3 + l) * WSLOT, Blo + (size_t)(3 + l) * WSLOT,
                b2v + l * 128, bng + l * 128, bnb + l * 128,
                bnm + l * 128, bnv + l * 128,
                outp, nullptr, nullptr,
                gx1, ny1, hasVN ? GG : 0,
                nullptr, nullptr, vthi, vtlo,
                Bhi + (size_t)(8 + l) * WSLOT, Blo + (size_t)(8 + l) * WSLOT,
                vnb2 + l * 128, vbn2g + l * 128, vbn2b + l * 128,
                vbn2m + l * 128, vbn2v + l * 128,
                vn, nullptr, nullptr,
                (l == 0) ? (float4*)gsum : nullptr, GG * 32,
                128, 256, hasVN);
        }
    }
}

// round 12
// speedup vs baseline: 1.0977x; 1.0151x over previous
#include <cuda_runtime.h>
#include <cuda_bf16.h>
#include <cstdint>

#define MAXN 50000
#define MAXE 800000
#define GG   1024
#define DD   128
#define LL   3

// ---------------------------------------------------------------------------
// Static scratch
// ---------------------------------------------------------------------------
__device__ float g_h[MAXN * DD];
__device__ __nv_bfloat16 g_zhi[MAXN * DD];
__device__ __nv_bfloat16 g_zlo[MAXN * DD];
__device__ __nv_bfloat16 g_thi[MAXN * 2 * DD];
__device__ __nv_bfloat16 g_tlo[MAXN * 2 * DD];
__device__ float g_vn[GG * DD];
__device__ float g_gsum[GG * DD];
__device__ __nv_bfloat16 g_vthi[GG * 2 * DD];
__device__ __nv_bfloat16 g_vtlo[GG * 2 * DD];
__device__ float g_cb[LL * 1000 * DD];
__device__ int   g_cnt[MAXN];
__device__ int   g_off[MAXN + 1];
__device__ int   g_rank[MAXE];
__device__ int2  g_csr[MAXE];                  // packed {src, combo}
// Preconverted weights: B^T [N][K] bf16 hi/lo. 10 slots of 32768:
// W1 l0..2, W2 l0..2, vn1 l0..1, vn2 l0..1
__device__ __nv_bfloat16 g_Bhi[10 * 32768];
__device__ __nv_bfloat16 g_Blo[10 * 32768];

// ---------------------------------------------------------------------------
// PTX helpers
// ---------------------------------------------------------------------------
__device__ __forceinline__ uint32_t cvta_s(const void* p) {
    uint32_t a;
    asm("{ .reg .u64 t; cvta.to.shared.u64 t, %1; cvt.u32.u64 %0, t; }"
        : "=r"(a) : "l"(p));
    return a;
}
#define LDSM_X4(r0, r1, r2, r3, addr)                                          \
    asm volatile("ldmatrix.sync.aligned.m8n8.x4.shared.b16 {%0,%1,%2,%3}, [%4];"\
                 : "=r"(r0), "=r"(r1), "=r"(r2), "=r"(r3) : "r"(addr))
#define MMA_BF16(d0, d1, d2, d3, a0, a1, a2, a3, b0, b1)                       \
    asm volatile("mma.sync.aligned.m16n8k16.row.col.f32.bf16.bf16.f32 "        \
                 "{%0,%1,%2,%3}, {%4,%5,%6,%7}, {%8,%9}, {%0,%1,%2,%3};"       \
                 : "+f"(d0), "+f"(d1), "+f"(d2), "+f"(d3)                      \
                 : "r"(a0), "r"(a1), "r"(a2), "r"(a3), "r"(b0), "r"(b1))
#define CP_ASYNC16(dst, src, sz)                                               \
    asm volatile("cp.async.cg.shared.global [%0], [%1], 16, %2;"               \
                 :: "r"(dst), "l"(src), "r"(sz))
#define CP_COMMIT() asm volatile("cp.async.commit_group;" ::: "memory")
#define CP_WAIT1()  asm volatile("cp.async.wait_group 1;" ::: "memory")

__device__ __forceinline__ void split_bf16(float v, unsigned short& hi,
                                           unsigned short& lo) {
    __nv_bfloat16 h = __float2bfloat16_rn(v);
    hi = __bfloat16_as_ushort(h);
    lo = __bfloat16_as_ushort(__float2bfloat16_rn(v - __bfloat162float(h)));
}

// ---------------------------------------------------------------------------
// Mega-fused preprocessing (weights + combo table + zeros + atom + vn init)
// ---------------------------------------------------------------------------
__global__ void fused_pre_k(
    const float* __restrict__ W1, const float* __restrict__ W2,
    const float* __restrict__ vnW1, const float* __restrict__ vnW2,
    __nv_bfloat16* __restrict__ Bhi, __nv_bfloat16* __restrict__ Blo,
    const float* __restrict__ bond, float* __restrict__ cb,
    int* __restrict__ cnt, float* __restrict__ gsum,
    const int* __restrict__ xa, const float* __restrict__ emb,
    float* __restrict__ h,
    const float* __restrict__ v0, float* __restrict__ vn,
    int n, int c1, int c2, int c3, int c4b, int c5) {
    int blk = blockIdx.x;
    int tid = threadIdx.x;
    if (blk < c1) {
        int idx = blk * 256 + tid;
        if (idx < 10 * 32768) {
            int slot = idx >> 15;
            int r = idx & 32767;
            const float* W;
            int Nd;
            if (slot < 3)      { W = W1 + (size_t)slot * 32768;         Nd = 256; }
            else if (slot < 6) { W = W2 + (size_t)(slot - 3) * 32768;   Nd = 128; }
            else if (slot < 8) { W = vnW1 + (size_t)(slot - 6) * 32768; Nd = 256; }
            else               { W = vnW2 + (size_t)(slot - 8) * 32768; Nd = 128; }
            int Kd = 32768 / Nd;
            int k = r / Nd, nn = r % Nd;
            unsigned short hi, lo;
            split_bf16(W[r], hi, lo);
            size_t o = (size_t)slot * 32768 + (size_t)nn * Kd + k;
            Bhi[o] = __ushort_as_bfloat16(hi);
            Blo[o] = __ushort_as_bfloat16(lo);
        }
    } else if (blk < c2) {
        int idx = (blk - c1) * 256 + tid;
        if (idx < LL * 1000 * 32) {
            int cc4 = (idx & 31) << 2;
            int i = (idx >> 5) % 1000;
            int l = (idx >> 5) / 1000;
            int f0 = i / 100, f1 = (i / 10) % 10, f2 = i % 10;
            float4 a = *(const float4*)(bond + ((size_t)(l * 3 + 0) * 10 + f0) * DD + cc4);
            float4 b = *(const float4*)(bond + ((size_t)(l * 3 + 1) * 10 + f1) * DD + cc4);
            float4 c = *(const float4*)(bond + ((size_t)(l * 3 + 2) * 10 + f2) * DD + cc4);
            float4 o;
            o.x = a.x + b.x + c.x; o.y = a.y + b.y + c.y;
            o.z = a.z + b.z + c.z; o.w = a.w + b.w + c.w;
            *(float4*)(cb + ((size_t)(l * 1000 + i)) * DD + cc4) = o;
        }
    } else if (blk < c3) {
        int i = (blk - c2) * 256 + tid;
        if (i < n) cnt[i] = 0;
    } else if (blk < c4b) {
        int i = (blk - c3) * 256 + tid;
        if (i < GG * 32)
            *(float4*)(gsum + i * 4) = make_float4(0.f, 0.f, 0.f, 0.f);
    } else if (blk < c5) {
        int idx = (blk - c4b) * 256 + tid;
        if (idx < n * 32) {
            int node = idx >> 5;
            int cc4 = (idx & 31) << 2;
            float4 s = make_float4(0.f, 0.f, 0.f, 0.f);
#pragma unroll
            for (int f = 0; f < 9; f++) {
                int v = xa[node * 9 + f];
                float4 e = *(const float4*)(emb + (f * 100 + v) * DD + cc4);
                s.x += e.x; s.y += e.y; s.z += e.z; s.w += e.w;
            }
            *(float4*)(h + node * DD + cc4) = s;
        }
    } else {
        int idx = (blk - c5) * 256 + tid;
        if (idx < GG * 32) {
            int cc4 = (idx & 31) << 2;
            *(float4*)(vn + idx * 4) = *(const float4*)(v0 + cc4);
        }
    }
}

// ---------------------------------------------------------------------------
// CSR build: count also records each edge's rank within its dst bucket.
// ---------------------------------------------------------------------------
__global__ void count_k(const int* __restrict__ ei, int* __restrict__ cnt,
                        int* __restrict__ rank, int ecnt) {
    int j = (blockIdx.x * blockDim.x + threadIdx.x) * 4;
    if (j + 3 < ecnt) {
        int4 d = *(const int4*)(ei + ecnt + j);
        rank[j + 0] = atomicAdd(&cnt[d.x], 1);
        rank[j + 1] = atomicAdd(&cnt[d.y], 1);
        rank[j + 2] = atomicAdd(&cnt[d.z], 1);
        rank[j + 3] = atomicAdd(&cnt[d.w], 1);
    } else {
        for (int q = j; q < ecnt; q++)
            rank[q] = atomicAdd(&cnt[ei[ecnt + q]], 1);
    }
}
__global__ void scan_k(const int* __restrict__ cnt, int* __restrict__ off,
                       int n, int ecnt) {
    __shared__ int part[1024];
    int t = threadIdx.x;
    int chunk = (n + 1023) >> 10;
    int beg = t * chunk;
    int end = min(beg + chunk, n);
    int s = 0;
    for (int i = beg; i < end; i++) s += cnt[i];
    part[t] = s;
    __syncthreads();
    for (int d = 1; d < 1024; d <<= 1) {
        int v = (t >= d) ? part[t - d] : 0;
        __syncthreads();
        if (t >= d) part[t] += v;
        __syncthreads();
    }
    int run = (t == 0) ? 0 : part[t - 1];
    for (int i = beg; i < end; i++) {
        off[i] = run;
        run += cnt[i];
    }
    if (t == 0) off[n] = ecnt;
}
__global__ void scatter_k(const int* __restrict__ ei, const int* __restrict__ ea,
                          const int* __restrict__ off, const int* __restrict__ rank,
                          int2* __restrict__ csr, int ecnt) {
    int j = blockIdx.x * blockDim.x + threadIdx.x;
    if (j >= ecnt) return;
    int dst = ei[ecnt + j];
    int cm = ea[j * 3] * 100 + ea[j * 3 + 1] * 10 + ea[j * 3 + 2];
    csr[off[dst] + rank[j]] = make_int2(ei[j], cm);
}

// ---------------------------------------------------------------------------
// h += vn[batch]; optionally gsum[batch] += h (post-update)
// ---------------------------------------------------------------------------
__global__ void add_vn_k(float* __restrict__ h, const float* __restrict__ vn,
                         const int* __restrict__ batch,
                         float* __restrict__ gsum, int n, int dosum) {
    int idx = blockIdx.x * blockDim.x + threadIdx.x;
    if (idx >= n * 32) return;
    int node = idx >> 5;
    int c4 = (idx & 31) << 2;
    int g = batch[node];
    float4 hv = *(float4*)(h + idx * 4);
    float4 vv = *(const float4*)(vn + g * DD + c4);
    hv.x += vv.x; hv.y += vv.y; hv.z += vv.z; hv.w += vv.w;
    *(float4*)(h + idx * 4) = hv;
    if (dosum) {
        float* p = gsum + g * DD + c4;
        asm volatile("red.global.add.v4.f32 [%0], {%1,%2,%3,%4};"
                     :: "l"(p), "f"(hv.x), "f"(hv.y), "f"(hv.z), "f"(hv.w)
                     : "memory");
    }
}

// ---------------------------------------------------------------------------
// Edge gather (CSR, packed int2, combined cb table), 4x unrolled
// ---------------------------------------------------------------------------
__global__ void edge_csr_k(const int* __restrict__ off,
                           const int2* __restrict__ csr,
                           const float* __restrict__ cb,
                           const float* __restrict__ h,
                           const float* __restrict__ eps_p,
                           __nv_bfloat16* __restrict__ zhi,
                           __nv_bfloat16* __restrict__ zlo, int n) {
    int warp = (blockIdx.x * blockDim.x + threadIdx.x) >> 5;
    if (warp >= n) return;
    int lane = threadIdx.x & 31;
    int c4 = lane << 2;
    float4 acc = make_float4(0.f, 0.f, 0.f, 0.f);
    int beg = off[warp], end = off[warp + 1];
    const unsigned FULL = 0xffffffffu;
    for (int base = beg; base < end; base += 32) {
        int m = min(32, end - base);
        int s = 0, cm = 0;
        if (base + lane < end) {
            int2 e = csr[base + lane];
            s = e.x; cm = e.y;
        }
        int k = 0;
        for (; k + 4 <= m; k += 4) {
            int s0 = __shfl_sync(FULL, s, k),     c0 = __shfl_sync(FULL, cm, k);
            int s1 = __shfl_sync(FULL, s, k + 1), c1 = __shfl_sync(FULL, cm, k + 1);
            int s2 = __shfl_sync(FULL, s, k + 2), c2 = __shfl_sync(FULL, cm, k + 2);
            int s3 = __shfl_sync(FULL, s, k + 3), c3 = __shfl_sync(FULL, cm, k + 3);
            float4 h0 = *(const float4*)(h + (size_t)s0 * DD + c4);
            float4 e0 = *(const float4*)(cb + (size_t)c0 * DD + c4);
            float4 h1 = *(const float4*)(h + (size_t)s1 * DD + c4);
            float4 e1 = *(const float4*)(cb + (size_t)c1 * DD + c4);
            float4 h2 = *(const float4*)(h + (size_t)s2 * DD + c4);
            float4 e2 = *(const float4*)(cb + (size_t)c2 * DD + c4);
            float4 h3 = *(const float4*)(h + (size_t)s3 * DD + c4);
            float4 e3 = *(const float4*)(cb + (size_t)c3 * DD + c4);
            acc.x += fmaxf(h0.x + e0.x, 0.f) + fmaxf(h1.x + e1.x, 0.f)
                   + fmaxf(h2.x + e2.x, 0.f) + fmaxf(h3.x + e3.x, 0.f);
            acc.y += fmaxf(h0.y + e0.y, 0.f) + fmaxf(h1.y + e1.y, 0.f)
                   + fmaxf(h2.y + e2.y, 0.f) + fmaxf(h3.y + e3.y, 0.f);
            acc.z += fmaxf(h0.z + e0.z, 0.f) + fmaxf(h1.z + e1.z, 0.f)
                   + fmaxf(h2.z + e2.z, 0.f) + fmaxf(h3.z + e3.z, 0.f);
            acc.w += fmaxf(h0.w + e0.w, 0.f) + fmaxf(h1.w + e1.w, 0.f)
                   + fmaxf(h2.w + e2.w, 0.f) + fmaxf(h3.w + e3.w, 0.f);
        }
        for (; k < m; k++) {
            int ss = __shfl_sync(FULL, s, k);
            int cc = __shfl_sync(FULL, cm, k);
            float4 hv = *(const float4*)(h + (size_t)ss * DD + c4);
            float4 ev = *(const float4*)(cb + (size_t)cc * DD + c4);
            acc.x += fmaxf(hv.x + ev.x, 0.f);
            acc.y += fmaxf(hv.y + ev.y, 0.f);
            acc.z += fmaxf(hv.z + ev.z, 0.f);
            acc.w += fmaxf(hv.w + ev.w, 0.f);
        }
    }
    float al = 1.0f + *eps_p;
    float4 hv = *(const float4*)(h + (size_t)warp * DD + c4);
    unsigned short h0, h1, h2, h3, l0, l1, l2, l3;
    split_bf16(al * hv.x + acc.x, h0, l0);
    split_bf16(al * hv.y + acc.y, h1, l1);
    split_bf16(al * hv.z + acc.z, h2, l2);
    split_bf16(al * hv.w + acc.w, h3, l3);
    uint2 hp = make_uint2((uint32_t)h0 | ((uint32_t)h1 << 16),
                          (uint32_t)h2 | ((uint32_t)h3 << 16));
    uint2 lp = make_uint2((uint32_t)l0 | ((uint32_t)l1 << 16),
                          (uint32_t)l2 | ((uint32_t)l3 << 16));
    *(uint2*)(zhi + (size_t)warp * DD + c4) = hp;
    *(uint2*)(zlo + (size_t)warp * DD + c4) = lp;
}

// ---------------------------------------------------------------------------
// Persistent unified GEMM with vn rider tiles, cp.async 2-stage, BK=32.
// ---------------------------------------------------------------------------
#define ASTR 40
#define STG_A_HI 0
#define STG_A_LO 10240
#define STG_B_HI 20480
#define STG_B_LO 25600
#define STG_SZ   30720
#define SM_TOT   61440

__global__ void __launch_bounds__(256, 2)
gemm_uni_k(int gx0, int ny0, int M0,
           const __nv_bfloat16* __restrict__ A0hi,
           const __nv_bfloat16* __restrict__ A0lo,
           const __nv_bfloat16* __restrict__ B0hi,
           const __nv_bfloat16* __restrict__ B0lo,
           const float* __restrict__ lb0, const float* __restrict__ g0,
           const float* __restrict__ be0, const float* __restrict__ m0,
           const float* __restrict__ vv0,
           float* __restrict__ C0f,
           __nv_bfloat16* __restrict__ C0hi, __nv_bfloat16* __restrict__ C0lo,
           int gx1, int ny1, int M1,
           const float* __restrict__ A1f, const float* __restrict__ A1f2,
           const __nv_bfloat16* __restrict__ A1hi,
           const __nv_bfloat16* __restrict__ A1lo,
           const __nv_bfloat16* __restrict__ B1hi,
           const __nv_bfloat16* __restrict__ B1lo,
           const float* __restrict__ lb1, const float* __restrict__ g1,
           const float* __restrict__ be1, const float* __restrict__ m1,
           const float* __restrict__ vv1,
           float* __restrict__ C1f,
           __nv_bfloat16* __restrict__ C1hi, __nv_bfloat16* __restrict__ C1lo,
           float4* __restrict__ zbuf, int zcnt4,
           int N, int K, int do_relu) {
    extern __shared__ char dsm[];
    __shared__ float s_sc[64], s_sb[64];

    int tid = threadIdx.x;
    int lane = tid & 31, wid = tid >> 5;
    uint32_t smbase = cvta_s(dsm);

    if (zbuf) {
        for (int i = blockIdx.x * 256 + tid; i < zcnt4; i += gridDim.x * 256)
            zbuf[i] = make_float4(0.f, 0.f, 0.f, 0.f);
    }

    int ntile0 = gx0 * ny0;
    int total = ntile0 + gx1 * ny1;

    int wm = (wid >> 1) * 32;
    int wn = (wid & 1) * 32;
    int r8 = lane & 7, g = lane >> 3;
    int acolg = (g >> 1) << 3;
    int bcolg = (g & 1) << 3;
    int nch = K >> 5;

    for (int tile = blockIdx.x; tile < total; tile += gridDim.x) {
        int part = 0, bx, by;
        int q = tile;
        if (q < ntile0) { bx = q / ny0; by = q % ny0; }
        else { part = 1; q -= ntile0; bx = q / ny1; by = q % ny1; }

        int M = part ? M1 : M0;
        const __nv_bfloat16* Ahi = part ? A1hi : A0hi;
        const __nv_bfloat16* Alo = part ? A1lo : A0lo;
        const __nv_bfloat16* Bh  = part ? B1hi : B0hi;
        const __nv_bfloat16* Bl  = part ? B1lo : B0lo;
        const float* lb = part ? lb1 : lb0;
        const float* gg = part ? g1 : g0;
        const float* bbp = part ? be1 : be0;
        const float* mmp = part ? m1 : m0;
        const float* vvp = part ? vv1 : vv0;
        float* Cf = part ? C1f : C0f;
        __nv_bfloat16* Chi = part ? C1hi : C0hi;
        __nv_bfloat16* Clo = part ? C1lo : C0lo;
        const float* Af  = part ? A1f  : (const float*)0;
        const float* Af2 = part ? A1f2 : (const float*)0;
        bool fp32A = (part && Af);

        int bm = bx * 128;
        int bn = by * 64;

        __syncthreads();   // guard s_sc reuse vs previous tile's epilogue
        if (tid < 64) {
            int col = bn + tid;
            float s = gg[col] * rsqrtf(vvp[col] + 1e-5f);
            s_sc[tid] = s;
            s_sb[tid] = (lb[col] - mmp[col]) * s + bbp[col];
        }

        float acc[2][4][4];
#pragma unroll
        for (int a = 0; a < 2; a++)
#pragma unroll
            for (int b = 0; b < 4; b++)
#pragma unroll
                for (int qq = 0; qq < 4; qq++) acc[a][b][qq] = 0.f;

        int arow = wm + ((g & 1) << 3) + r8;
        int brow = wn + ((g >> 1) << 3) + r8;

        auto issue_async = [&](int ch, int stg) {
            int cc = ch << 5;
            uint32_t sb = smbase + stg * STG_SZ;
#pragma unroll
            for (int it = 0; it < 2; it++) {
                int i = tid + it * 256;
                int row = i >> 2, c8 = (i & 3) << 3;
                int sz = (bm + row < M) ? 16 : 0;
                const __nv_bfloat16* sh = Ahi + (size_t)(bm + row) * K + cc + c8;
                const __nv_bfloat16* sl = Alo + (size_t)(bm + row) * K + cc + c8;
                uint32_t doff = (uint32_t)(row * ASTR + c8) * 2;
                CP_ASYNC16(sb + STG_A_HI + doff, sh, sz);
                CP_ASYNC16(sb + STG_A_LO + doff, sl, sz);
            }
            {
                int row = tid >> 2, c8 = (tid & 3) << 3;
                const __nv_bfloat16* sh = Bh + (size_t)(bn + row) * K + cc + c8;
                const __nv_bfloat16* sl = Bl + (size_t)(bn + row) * K + cc + c8;
                uint32_t doff = (uint32_t)(row * ASTR + c8) * 2;
                CP_ASYNC16(sb + STG_B_HI + doff, sh, 16);
                CP_ASYNC16(sb + STG_B_LO + doff, sl, 16);
            }
        };
        auto issue_sync = [&](int ch, int stg) {
            int cc = ch << 5;
            char* sb = dsm + stg * STG_SZ;
#pragma unroll
            for (int it = 0; it < 4; it++) {
                int i = tid + it * 256;
                int row = i >> 3, c4 = (i & 7) << 2;
                float4 v = make_float4(0.f, 0.f, 0.f, 0.f);
                if (bm + row < M) {
                    v = *(const float4*)(Af + (size_t)(bm + row) * K + cc + c4);
                    float4 w = *(const float4*)(Af2 + (size_t)(bm + row) * K + cc + c4);
                    v.x += w.x; v.y += w.y; v.z += w.z; v.w += w.w;
                }
                unsigned short h0, h1, h2, h3, l0, l1, l2, l3;
                split_bf16(v.x, h0, l0); split_bf16(v.y, h1, l1);
                split_bf16(v.z, h2, l2); split_bf16(v.w, h3, l3);
                int off = (row * ASTR + c4) * 2;
                *(uint2*)(sb + STG_A_HI + off) = make_uint2(
                    (uint32_t)h0 | ((uint32_t)h1 << 16),
                    (uint32_t)h2 | ((uint32_t)h3 << 16));
                *(uint2*)(sb + STG_A_LO + off) = make_uint2(
                    (uint32_t)l0 | ((uint32_t)l1 << 16),
                    (uint32_t)l2 | ((uint32_t)l3 << 16));
            }
            {
                int row = tid >> 2, c8 = (tid & 3) << 3;
                uint4 vh = *(const uint4*)(Bh + (size_t)(bn + row) * K + cc + c8);
                uint4 vl = *(const uint4*)(Bl + (size_t)(bn + row) * K + cc + c8);
                int off = (row * ASTR + c8) * 2;
                *(uint4*)(sb + STG_B_HI + off) = vh;
                *(uint4*)(sb + STG_B_LO + off) = vl;
            }
        };

        if (fp32A) issue_sync(0, 0);
        else       issue_async(0, 0);
        CP_COMMIT();

        for (int ch = 0; ch < nch; ch++) {
            if (ch + 1 < nch) {
                if (fp32A) issue_sync(ch + 1, (ch + 1) & 1);
                else       issue_async(ch + 1, (ch + 1) & 1);
            }
            CP_COMMIT();
            CP_WAIT1();
            __syncthreads();

            uint32_t sb = smbase + (ch & 1) * STG_SZ;
#pragma unroll
            for (int ks = 0; ks < 2; ks++) {
                int kk = ks << 4;
                uint32_t ah0, ah1, ah2, ah3, ah4, ah5, ah6, ah7;
                uint32_t am0, am1, am2, am3, am4, am5, am6, am7;
                uint32_t bh0, bh1, bh2, bh3, bh4, bh5, bh6, bh7;
                uint32_t bm0, bm1, bm2, bm3, bm4, bm5, bm6, bm7;
                {
                    uint32_t ad0 = sb + STG_A_HI + ((arow) * ASTR + kk + acolg) * 2;
                    uint32_t ad1 = sb + STG_A_HI + ((arow + 16) * ASTR + kk + acolg) * 2;
                    LDSM_X4(ah0, ah1, ah2, ah3, ad0);
                    LDSM_X4(ah4, ah5, ah6, ah7, ad1);
                    LDSM_X4(am0, am1, am2, am3, ad0 + (STG_A_LO - STG_A_HI));
                    LDSM_X4(am4, am5, am6, am7, ad1 + (STG_A_LO - STG_A_HI));
                    uint32_t bd0 = sb + STG_B_HI + ((brow) * ASTR + kk + bcolg) * 2;
                    uint32_t bd1 = sb + STG_B_HI + ((brow + 16) * ASTR + kk + bcolg) * 2;
                    LDSM_X4(bh0, bh1, bh2, bh3, bd0);
                    LDSM_X4(bh4, bh5, bh6, bh7, bd1);
                    LDSM_X4(bm0, bm1, bm2, bm3, bd0 + (STG_B_LO - STG_B_HI));
                    LDSM_X4(bm4, bm5, bm6, bm7, bd1 + (STG_B_LO - STG_B_HI));
                }
#define DO_NT(mt, nt, B0, B1, BL0, BL1, A0, A1, A2_, A3, AL0, AL1, AL2, AL3)    \
                MMA_BF16(acc[mt][nt][0], acc[mt][nt][1], acc[mt][nt][2],        \
                         acc[mt][nt][3], A0, A1, A2_, A3, B0, B1);              \
                MMA_BF16(acc[mt][nt][0], acc[mt][nt][1], acc[mt][nt][2],        \
                         acc[mt][nt][3], A0, A1, A2_, A3, BL0, BL1);            \
                MMA_BF16(acc[mt][nt][0], acc[mt][nt][1], acc[mt][nt][2],        \
                         acc[mt][nt][3], AL0, AL1, AL2, AL3, B0, B1);
                DO_NT(0, 0, bh0, bh1, bm0, bm1, ah0, ah1, ah2, ah3, am0, am1, am2, am3)
                DO_NT(0, 1, bh2, bh3, bm2, bm3, ah0, ah1, ah2, ah3, am0, am1, am2, am3)
                DO_NT(0, 2, bh4, bh5, bm4, bm5, ah0, ah1, ah2, ah3, am0, am1, am2, am3)
                DO_NT(0, 3, bh6, bh7, bm6, bm7, ah0, ah1, ah2, ah3, am0, am1, am2, am3)
                DO_NT(1, 0, bh0, bh1, bm0, bm1, ah4, ah5, ah6, ah7, am4, am5, am6, am7)
                DO_NT(1, 1, bh2, bh3, bm2, bm3, ah4, ah5, ah6, ah7, am4, am5, am6, am7)
                DO_NT(1, 2, bh4, bh5, bm4, bm5, ah4, ah5, ah6, ah7, am4, am5, am6, am7)
                DO_NT(1, 3, bh6, bh7, bm6, bm7, ah4, ah5, ah6, ah7, am4, am5, am6, am7)
#undef DO_NT
            }
            __syncthreads();
        }

        // ---- epilogue
        int rq = lane >> 2, cq = (lane & 3) * 2;
        bool outBF = (Chi != (__nv_bfloat16*)0);
#pragma unroll
        for (int mt = 0; mt < 2; mt++) {
            int r0 = bm + wm + mt * 16 + rq;
#pragma unroll
            for (int nt = 0; nt < 4; nt++) {
                int c0 = wn + nt * 8 + cq;
                float s0 = s_sc[c0], s1 = s_sc[c0 + 1];
                float t0 = s_sb[c0], t1 = s_sb[c0 + 1];
                float v0 = acc[mt][nt][0] * s0 + t0;
                float v1 = acc[mt][nt][1] * s1 + t1;
                float v2 = acc[mt][nt][2] * s0 + t0;
                float v3 = acc[mt][nt][3] * s1 + t1;
                if (do_relu) {
                    v0 = fmaxf(v0, 0.f); v1 = fmaxf(v1, 0.f);
                    v2 = fmaxf(v2, 0.f); v3 = fmaxf(v3, 0.f);
                }
                if (outBF) {
                    unsigned short h0, h1, h2, h3, l0, l1, l2, l3;
                    split_bf16(v0, h0, l0); split_bf16(v1, h1, l1);
                    split_bf16(v2, h2, l2); split_bf16(v3, h3, l3);
                    if (r0 < M) {
                        *(uint32_t*)(Chi + (size_t)r0 * N + bn + c0) =
                            (uint32_t)h0 | ((uint32_t)h1 << 16);
                        *(uint32_t*)(Clo + (size_t)r0 * N + bn + c0) =
                            (uint32_t)l0 | ((uint32_t)l1 << 16);
                    }
                    if (r0 + 8 < M) {
                        *(uint32_t*)(Chi + (size_t)(r0 + 8) * N + bn + c0) =
                            (uint32_t)h2 | ((uint32_t)h3 << 16);
                        *(uint32_t*)(Clo + (size_t)(r0 + 8) * N + bn + c0) =
                            (uint32_t)l2 | ((uint32_t)l3 << 16);
                    }
                } else {
                    if (r0 < M)
                        *(float2*)(Cf + (size_t)r0 * N + bn + c0) = make_float2(v0, v1);
                    if (r0 + 8 < M)
                        *(float2*)(Cf + (size_t)(r0 + 8) * N + bn + c0) = make_float2(v2, v3);
                }
            }
        }
    }
}

// ---------------------------------------------------------------------------
// Host driver
// ---------------------------------------------------------------------------
extern "C" void kernel_launch(void* const* d_in, const int* in_sizes, int n_in,
                              void* d_out, int out_size) {
    const int*   x_atom  = (const int*)d_in[0];
    const int*   ei      = (const int*)d_in[1];
    const int*   ea      = (const int*)d_in[2];
    const int*   batch   = (const int*)d_in[3];
    const float* atomemb = (const float*)d_in[4];
    const float* vn0     = (const float*)d_in[5];
    const float* bond    = (const float*)d_in[6];
    const float* eps     = (const float*)d_in[7];
    const float* W1      = (const float*)d_in[8];
    const float* b1v     = (const float*)d_in[9];
    const float* bn1g    = (const float*)d_in[10];
    const float* bn1b    = (const float*)d_in[11];
    const float* bn1m    = (const float*)d_in[12];
    const float* bn1v    = (const float*)d_in[13];
    const float* W2      = (const float*)d_in[14];
    const float* b2v     = (const float*)d_in[15];
    const float* bng     = (const float*)d_in[16];
    const float* bnb     = (const float*)d_in[17];
    const float* bnm     = (const float*)d_in[18];
    const float* bnv     = (const float*)d_in[19];
    const float* vnW1    = (const float*)d_in[20];
    const float* vnb1    = (const float*)d_in[21];
    const float* vbn1g   = (const float*)d_in[22];
    const float* vbn1b   = (const float*)d_in[23];
    const float* vbn1m   = (const float*)d_in[24];
    const float* vbn1v   = (const float*)d_in[25];
    const float* vnW2    = (const float*)d_in[26];
    const float* vnb2    = (const float*)d_in[27];
    const float* vbn2g   = (const float*)d_in[28];
    const float* vbn2b   = (const float*)d_in[29];
    const float* vbn2m   = (const float*)d_in[30];
    const float* vbn2v   = (const float*)d_in[31];

    int n = in_sizes[3];
    int ecnt = in_sizes[1] / 2;

    float *h, *vn, *gsum, *cb;
    __nv_bfloat16 *zhi, *zlo, *thi, *tlo, *vthi, *vtlo, *Bhi, *Blo;
    int *cnt, *off, *rank;
    int2* csr;
    cudaGetSymbolAddress((void**)&h, g_h);
    cudaGetSymbolAddress((void**)&zhi, g_zhi);
    cudaGetSymbolAddress((void**)&zlo, g_zlo);
    cudaGetSymbolAddress((void**)&thi, g_thi);
    cudaGetSymbolAddress((void**)&tlo, g_tlo);
    cudaGetSymbolAddress((void**)&vn, g_vn);
    cudaGetSymbolAddress((void**)&gsum, g_gsum);
    cudaGetSymbolAddress((void**)&vthi, g_vthi);
    cudaGetSymbolAddress((void**)&vtlo, g_vtlo);
    cudaGetSymbolAddress((void**)&cb, g_cb);
    cudaGetSymbolAddress((void**)&cnt, g_cnt);
    cudaGetSymbolAddress((void**)&off, g_off);
    cudaGetSymbolAddress((void**)&rank, g_rank);
    cudaGetSymbolAddress((void**)&csr, g_csr);
    cudaGetSymbolAddress((void**)&Bhi, g_Bhi);
    cudaGetSymbolAddress((void**)&Blo, g_Blo);

    cudaFuncSetAttribute(gemm_uni_k, cudaFuncAttributeMaxDynamicSharedMemorySize,
                         SM_TOT);

    const int WSLOT = 32768;
    int gridND = (n * 32 + 255) / 256;

    int c1 = (10 * 32768 + 255) / 256;
    int c2 = c1 + (LL * 1000 * 32 + 255) / 256;
    int c3 = c2 + (n + 255) / 256;
    int c4b = c3 + (GG * 32 + 255) / 256;
    int c5 = c4b + gridND;
    int c6 = c5 + (GG * 32 + 255) / 256;
    fused_pre_k<<<c6, 256>>>(W1, W2, vnW1, vnW2, Bhi, Blo, bond, cb,
                             cnt, gsum, x_atom, atomemb, h, vn0, vn,
                             n, c1, c2, c3, c4b, c5);
    count_k<<<(ecnt / 4 + 255) / 256, 256>>>(ei, cnt, rank, ecnt);
    scan_k<<<1, 1024>>>(cnt, off, n, ecnt);
    scatter_k<<<(ecnt + 255) / 256, 256>>>(ei, ea, off, rank, csr, ecnt);

    int gridM = (n + 127) / 128;
    int gxv = GG / 128;
    const int PERSIST = 296;   // 148 SMs x 2 CTAs
    for (int l = 0; l < LL; l++) {
        int hasVN = (l < LL - 1) ? 1 : 0;
        add_vn_k<<<gridND, 256>>>(h, vn, batch, gsum, n, hasVN);
        edge_csr_k<<<gridND, 256>>>(off, csr, cb + (size_t)l * 1000 * DD, h,
                                    eps + l, zhi, zlo, n);
        {
            int ny0 = 4, ny1 = 4;
            int gx1 = hasVN ? gxv : 0;
            int total = gridM * ny0 + gx1 * ny1;
            int grid = total < PERSIST ? total : PERSIST;
            gemm_uni_k<<<grid, 256, SM_TOT>>>(
                gridM, ny0, n,
                zhi, zlo,
                Bhi + (size_t)l * WSLOT, Blo + (size_t)l * WSLOT,
                b1v + l * 256, bn1g + l * 256, bn1b + l * 256,
                bn1m + l * 256, bn1v + l * 256,
                nullptr, thi, tlo,
                gx1, ny1, hasVN ? GG : 0,
                vn, gsum, nullptr, nullptr,
                Bhi + (size_t)(6 + l) * WSLOT, Blo + (size_t)(6 + l) * WSLOT,
                vnb1 + l * 256, vbn1g + l * 256, vbn1b + l * 256,
                vbn1m + l * 256, vbn1v + l * 256,
                nullptr, vthi, vtlo,
                nullptr, 0,
                256, 128, 1);
        }
        {
            float* outp = (l == LL - 1) ? (float*)d_out : h;
            int ny0 = 2, ny1 = 2;
            int gx1 = hasVN ? gxv : 0;
            int total = gridM * ny0 + gx1 * ny1;
            int grid = total < PERSIST ? total : PERSIST;
            gemm_uni_k<<<grid, 256, SM_TOT>>>(
                gridM, ny0, n,
                thi, tlo,
                Bhi + (size_t)(3 + l) * WSLOT, Blo + (size_t)(3 + l) * WSLOT,
                b2v + l * 128, bng + l * 128, bnb + l * 128,
                bnm + l * 128, bnv + l * 128,
                outp, nullptr, nullptr,
                gx1, ny1, hasVN ? GG : 0,
                nullptr, nullptr, vthi, vtlo,
                Bhi + (size_t)(8 + l) * WSLOT, Blo + (size_t)(8 + l) * WSLOT,
                vnb2 + l * 128, vbn2g + l * 128, vbn2b + l * 128,
                vbn2m + l * 128, vbn2v + l * 128,
                vn, nullptr, nullptr,
                (l == 0) ? (float4*)gsum : nullptr, GG * 32,
                128, 256, hasVN);
        }
    }
}

// round 14
// speedup vs baseline: 1.3319x; 1.2134x over previous
#include <cuda_runtime.h>
#include <cuda_fp16.h>
#include <cstdint>

#define MAXN 50000
#define MAXE 800000
#define GG   1024
#define DD   128
#define LL   3

// ---------------------------------------------------------------------------
// Static scratch
// ---------------------------------------------------------------------------
__device__ float g_h[MAXN * DD];
__device__ __half g_zh[MAXN * DD];            // GIN input z, fp16
__device__ __half g_th[MAXN * 2 * DD];        // MLP hidden t, fp16
__device__ float g_vn[GG * DD];
__device__ float g_gsum[GG * DD];
__device__ __half g_vth[GG * 2 * DD];         // vn hidden, fp16
__device__ float g_cb[LL * 1000 * DD];
__device__ int   g_cnt[MAXN];
__device__ int   g_off[MAXN + 1];
__device__ int   g_rank[MAXE];
__device__ int2  g_csr[MAXE];                  // packed {src, combo}
// Preconverted weights: B^T [N][K] fp16 hi/lo limbs. 10 slots of 32768:
// W1 l0..2, W2 l0..2, vn1 l0..1, vn2 l0..1
__device__ __half g_Bhi[10 * 32768];
__device__ __half g_Blo[10 * 32768];

// ---------------------------------------------------------------------------
// PTX helpers
// ---------------------------------------------------------------------------
__device__ __forceinline__ uint32_t cvta_s(const void* p) {
    uint32_t a;
    asm("{ .reg .u64 t; cvta.to.shared.u64 t, %1; cvt.u32.u64 %0, t; }"
        : "=r"(a) : "l"(p));
    return a;
}
#define LDSM_X4(r0, r1, r2, r3, addr)                                          \
    asm volatile("ldmatrix.sync.aligned.m8n8.x4.shared.b16 {%0,%1,%2,%3}, [%4];"\
                 : "=r"(r0), "=r"(r1), "=r"(r2), "=r"(r3) : "r"(addr))
#define MMA_F16(d0, d1, d2, d3, a0, a1, a2, a3, b0, b1)                        \
    asm volatile("mma.sync.aligned.m16n8k16.row.col.f32.f16.f16.f32 "          \
                 "{%0,%1,%2,%3}, {%4,%5,%6,%7}, {%8,%9}, {%0,%1,%2,%3};"       \
                 : "+f"(d0), "+f"(d1), "+f"(d2), "+f"(d3)                      \
                 : "r"(a0), "r"(a1), "r"(a2), "r"(a3), "r"(b0), "r"(b1))
#define CP_ASYNC16(dst, src, sz)                                               \
    asm volatile("cp.async.cg.shared.global [%0], [%1], 16, %2;"               \
                 :: "r"(dst), "l"(src), "r"(sz))
#define CP_COMMIT() asm volatile("cp.async.commit_group;" ::: "memory")
#define CP_WAIT1()  asm volatile("cp.async.wait_group 1;" ::: "memory")

__device__ __forceinline__ void split_f16(float v, unsigned short& hi,
                                          unsigned short& lo) {
    __half h = __float2half_rn(v);
    hi = __half_as_ushort(h);
    lo = __half_as_ushort(__float2half_rn(v - __half2float(h)));
}
__device__ __forceinline__ unsigned short f16u(float v) {
    return __half_as_ushort(__float2half_rn(v));
}

// ---------------------------------------------------------------------------
// Mega-fused preprocessing (weights + combo table + zeros + atom + vn init)
// ---------------------------------------------------------------------------
__global__ void fused_pre_k(
    const float* __restrict__ W1, const float* __restrict__ W2,
    const float* __restrict__ vnW1, const float* __restrict__ vnW2,
    __half* __restrict__ Bhi, __half* __restrict__ Blo,
    const float* __restrict__ bond, float* __restrict__ cb,
    int* __restrict__ cnt, float* __restrict__ gsum,
    const int* __restrict__ xa, const float* __restrict__ emb,
    float* __restrict__ h,
    const float* __restrict__ v0, float* __restrict__ vn,
    int n, int c1, int c2, int c3, int c4b, int c5) {
    int blk = blockIdx.x;
    int tid = threadIdx.x;
    if (blk < c1) {
        int idx = blk * 256 + tid;
        if (idx < 10 * 32768) {
            int slot = idx >> 15;
            int r = idx & 32767;
            const float* W;
            int Nd;
            if (slot < 3)      { W = W1 + (size_t)slot * 32768;         Nd = 256; }
            else if (slot < 6) { W = W2 + (size_t)(slot - 3) * 32768;   Nd = 128; }
            else if (slot < 8) { W = vnW1 + (size_t)(slot - 6) * 32768; Nd = 256; }
            else               { W = vnW2 + (size_t)(slot - 8) * 32768; Nd = 128; }
            int Kd = 32768 / Nd;
            int k = r / Nd, nn = r % Nd;
            unsigned short hi, lo;
            split_f16(W[r], hi, lo);
            size_t o = (size_t)slot * 32768 + (size_t)nn * Kd + k;
            Bhi[o] = __ushort_as_half(hi);
            Blo[o] = __ushort_as_half(lo);
        }
    } else if (blk < c2) {
        int idx = (blk - c1) * 256 + tid;
        if (idx < LL * 1000 * 32) {
            int cc4 = (idx & 31) << 2;
            int i = (idx >> 5) % 1000;
            int l = (idx >> 5) / 1000;
            int f0 = i / 100, f1 = (i / 10) % 10, f2 = i % 10;
            float4 a = *(const float4*)(bond + ((size_t)(l * 3 + 0) * 10 + f0) * DD + cc4);
            float4 b = *(const float4*)(bond + ((size_t)(l * 3 + 1) * 10 + f1) * DD + cc4);
            float4 c = *(const float4*)(bond + ((size_t)(l * 3 + 2) * 10 + f2) * DD + cc4);
            float4 o;
            o.x = a.x + b.x + c.x; o.y = a.y + b.y + c.y;
            o.z = a.z + b.z + c.z; o.w = a.w + b.w + c.w;
            *(float4*)(cb + ((size_t)(l * 1000 + i)) * DD + cc4) = o;
        }
    } else if (blk < c3) {
        int i = (blk - c2) * 256 + tid;
        if (i < n) cnt[i] = 0;
    } else if (blk < c4b) {
        int i = (blk - c3) * 256 + tid;
        if (i < GG * 32)
            *(float4*)(gsum + i * 4) = make_float4(0.f, 0.f, 0.f, 0.f);
    } else if (blk < c5) {
        int idx = (blk - c4b) * 256 + tid;
        if (idx < n * 32) {
            int node = idx >> 5;
            int cc4 = (idx & 31) << 2;
            float4 s = make_float4(0.f, 0.f, 0.f, 0.f);
#pragma unroll
            for (int f = 0; f < 9; f++) {
                int v = xa[node * 9 + f];
                float4 e = *(const float4*)(emb + (f * 100 + v) * DD + cc4);
                s.x += e.x; s.y += e.y; s.z += e.z; s.w += e.w;
            }
            *(float4*)(h + node * DD + cc4) = s;
        }
    } else {
        int idx = (blk - c5) * 256 + tid;
        if (idx < GG * 32) {
            int cc4 = (idx & 31) << 2;
            *(float4*)(vn + idx * 4) = *(const float4*)(v0 + cc4);
        }
    }
}

// ---------------------------------------------------------------------------
// CSR build
// ---------------------------------------------------------------------------
__global__ void count_k(const int* __restrict__ ei, int* __restrict__ cnt,
                        int* __restrict__ rank, int ecnt) {
    int j = (blockIdx.x * blockDim.x + threadIdx.x) * 4;
    if (j + 3 < ecnt) {
        int4 d = *(const int4*)(ei + ecnt + j);
        rank[j + 0] = atomicAdd(&cnt[d.x], 1);
        rank[j + 1] = atomicAdd(&cnt[d.y], 1);
        rank[j + 2] = atomicAdd(&cnt[d.z], 1);
        rank[j + 3] = atomicAdd(&cnt[d.w], 1);
    } else {
        for (int q = j; q < ecnt; q++)
            rank[q] = atomicAdd(&cnt[ei[ecnt + q]], 1);
    }
}
__global__ void scan_k(const int* __restrict__ cnt, int* __restrict__ off,
                       int n, int ecnt) {
    __shared__ int part[1024];
    int t = threadIdx.x;
    int chunk = (n + 1023) >> 10;
    int beg = t * chunk;
    int end = min(beg + chunk, n);
    int s = 0;
    for (int i = beg; i < end; i++) s += cnt[i];
    part[t] = s;
    __syncthreads();
    for (int d = 1; d < 1024; d <<= 1) {
        int v = (t >= d) ? part[t - d] : 0;
        __syncthreads();
        if (t >= d) part[t] += v;
        __syncthreads();
    }
    int run = (t == 0) ? 0 : part[t - 1];
    for (int i = beg; i < end; i++) {
        off[i] = run;
        run += cnt[i];
    }
    if (t == 0) off[n] = ecnt;
}
__global__ void scatter_k(const int* __restrict__ ei, const int* __restrict__ ea,
                          const int* __restrict__ off, const int* __restrict__ rank,
                          int2* __restrict__ csr, int ecnt) {
    int j = blockIdx.x * blockDim.x + threadIdx.x;
    if (j >= ecnt) return;
    int dst = ei[ecnt + j];
    int cm = ea[j * 3] * 100 + ea[j * 3 + 1] * 10 + ea[j * 3 + 2];
    csr[off[dst] + rank[j]] = make_int2(ei[j], cm);
}

// ---------------------------------------------------------------------------
// h += vn[batch]; optionally gsum[batch] += h (post-update)
// ---------------------------------------------------------------------------
__global__ void add_vn_k(float* __restrict__ h, const float* __restrict__ vn,
                         const int* __restrict__ batch,
                         float* __restrict__ gsum, int n, int dosum) {
    int idx = blockIdx.x * blockDim.x + threadIdx.x;
    if (idx >= n * 32) return;
    int node = idx >> 5;
    int c4 = (idx & 31) << 2;
    int g = batch[node];
    float4 hv = *(float4*)(h + idx * 4);
    float4 vv = *(const float4*)(vn + g * DD + c4);
    hv.x += vv.x; hv.y += vv.y; hv.z += vv.z; hv.w += vv.w;
    *(float4*)(h + idx * 4) = hv;
    if (dosum) {
        float* p = gsum + g * DD + c4;
        asm volatile("red.global.add.v4.f32 [%0], {%1,%2,%3,%4};"
                     :: "l"(p), "f"(hv.x), "f"(hv.y), "f"(hv.z), "f"(hv.w)
                     : "memory");
    }
}

// ---------------------------------------------------------------------------
// Edge gather (CSR, packed int2, combined cb table), 4x unrolled.
// Output z as single fp16.
// ---------------------------------------------------------------------------
__global__ void edge_csr_k(const int* __restrict__ off,
                           const int2* __restrict__ csr,
                           const float* __restrict__ cb,
                           const float* __restrict__ h,
                           const float* __restrict__ eps_p,
                           __half* __restrict__ zh, int n) {
    int warp = (blockIdx.x * blockDim.x + threadIdx.x) >> 5;
    if (warp >= n) return;
    int lane = threadIdx.x & 31;
    int c4 = lane << 2;
    float4 acc = make_float4(0.f, 0.f, 0.f, 0.f);
    int beg = off[warp], end = off[warp + 1];
    const unsigned FULL = 0xffffffffu;
    for (int base = beg; base < end; base += 32) {
        int m = min(32, end - base);
        int s = 0, cm = 0;
        if (base + lane < end) {
            int2 e = csr[base + lane];
            s = e.x; cm = e.y;
        }
        int k = 0;
        for (; k + 4 <= m; k += 4) {
            int s0 = __shfl_sync(FULL, s, k),     c0 = __shfl_sync(FULL, cm, k);
            int s1 = __shfl_sync(FULL, s, k + 1), c1 = __shfl_sync(FULL, cm, k + 1);
            int s2 = __shfl_sync(FULL, s, k + 2), c2 = __shfl_sync(FULL, cm, k + 2);
            int s3 = __shfl_sync(FULL, s, k + 3), c3 = __shfl_sync(FULL, cm, k + 3);
            float4 h0 = *(const float4*)(h + (size_t)s0 * DD + c4);
            float4 e0 = *(const float4*)(cb + (size_t)c0 * DD + c4);
            float4 h1 = *(const float4*)(h + (size_t)s1 * DD + c4);
            float4 e1 = *(const float4*)(cb + (size_t)c1 * DD + c4);
            float4 h2 = *(const float4*)(h + (size_t)s2 * DD + c4);
            float4 e2 = *(const float4*)(cb + (size_t)c2 * DD + c4);
            float4 h3 = *(const float4*)(h + (size_t)s3 * DD + c4);
            float4 e3 = *(const float4*)(cb + (size_t)c3 * DD + c4);
            acc.x += fmaxf(h0.x + e0.x, 0.f) + fmaxf(h1.x + e1.x, 0.f)
                   + fmaxf(h2.x + e2.x, 0.f) + fmaxf(h3.x + e3.x, 0.f);
            acc.y += fmaxf(h0.y + e0.y, 0.f) + fmaxf(h1.y + e1.y, 0.f)
                   + fmaxf(h2.y + e2.y, 0.f) + fmaxf(h3.y + e3.y, 0.f);
            acc.z += fmaxf(h0.z + e0.z, 0.f) + fmaxf(h1.z + e1.z, 0.f)
                   + fmaxf(h2.z + e2.z, 0.f) + fmaxf(h3.z + e3.z, 0.f);
            acc.w += fmaxf(h0.w + e0.w, 0.f) + fmaxf(h1.w + e1.w, 0.f)
                   + fmaxf(h2.w + e2.w, 0.f) + fmaxf(h3.w + e3.w, 0.f);
        }
        for (; k < m; k++) {
            int ss = __shfl_sync(FULL, s, k);
            int cc = __shfl_sync(FULL, cm, k);
            float4 hv = *(const float4*)(h + (size_t)ss * DD + c4);
            float4 ev = *(const float4*)(cb + (size_t)cc * DD + c4);
            acc.x += fmaxf(hv.x + ev.x, 0.f);
            acc.y += fmaxf(hv.y + ev.y, 0.f);
            acc.z += fmaxf(hv.z + ev.z, 0.f);
            acc.w += fmaxf(hv.w + ev.w, 0.f);
        }
    }
    float al = 1.0f + *eps_p;
    float4 hv = *(const float4*)(h + (size_t)warp * DD + c4);
    uint2 zp;
    zp.x = (uint32_t)f16u(al * hv.x + acc.x) |
           ((uint32_t)f16u(al * hv.y + acc.y) << 16);
    zp.y = (uint32_t)f16u(al * hv.z + acc.z) |
           ((uint32_t)f16u(al * hv.w + acc.w) << 16);
    *(uint2*)(zh + (size_t)warp * DD + c4) = zp;
}

// ---------------------------------------------------------------------------
// Persistent unified GEMM, fp16 2-product split (A single limb, B hi/lo):
//   D = A @ Bhi + A @ Blo
// cp.async 2-stage, BK=32, vn rider tiles. Stage = 20 KB.
// ---------------------------------------------------------------------------
#define ASTR 40
#define STG_A    0
#define STG_B_HI 10240
#define STG_B_LO 15360
#define STG_SZ   20480
#define SM_TOT   40960

__global__ void __launch_bounds__(256, 2)
gemm_uni_k(int gx0, int ny0, int M0,
           const __half* __restrict__ A0h,
           const __half* __restrict__ B0hi, const __half* __restrict__ B0lo,
           const float* __restrict__ lb0, const float* __restrict__ g0,
           const float* __restrict__ be0, const float* __restrict__ m0,
           const float* __restrict__ vv0,
           float* __restrict__ C0f, __half* __restrict__ C0h,
           int gx1, int ny1, int M1,
           const float* __restrict__ A1f, const float* __restrict__ A1f2,
           const __half* __restrict__ A1h,
           const __half* __restrict__ B1hi, const __half* __restrict__ B1lo,
           const float* __restrict__ lb1, const float* __restrict__ g1,
           const float* __restrict__ be1, const float* __restrict__ m1,
           const float* __restrict__ vv1,
           float* __restrict__ C1f, __half* __restrict__ C1h,
           float4* __restrict__ zbuf, int zcnt4,
           int N, int K, int do_relu) {
    extern __shared__ char dsm[];
    __shared__ float s_sc[64], s_sb[64];

    int tid = threadIdx.x;
    int lane = tid & 31, wid = tid >> 5;
    uint32_t smbase = cvta_s(dsm);

    if (zbuf) {
        for (int i = blockIdx.x * 256 + tid; i < zcnt4; i += gridDim.x * 256)
            zbuf[i] = make_float4(0.f, 0.f, 0.f, 0.f);
    }

    int ntile0 = gx0 * ny0;
    int total = ntile0 + gx1 * ny1;

    int wm = (wid >> 1) * 32;
    int wn = (wid & 1) * 32;
    int r8 = lane & 7, g = lane >> 3;
    int acolg = (g >> 1) << 3;
    int bcolg = (g & 1) << 3;
    int nch = K >> 5;

    for (int tile = blockIdx.x; tile < total; tile += gridDim.x) {
        int part = 0, bx, by;
        int q = tile;
        if (q < ntile0) { bx = q / ny0; by = q % ny0; }
        else { part = 1; q -= ntile0; bx = q / ny1; by = q % ny1; }

        int M = part ? M1 : M0;
        const __half* Ah = part ? A1h : A0h;
        const __half* Bh = part ? B1hi : B0hi;
        const __half* Bl = part ? B1lo : B0lo;
        const float* lb = part ? lb1 : lb0;
        const float* gg = part ? g1 : g0;
        const float* bbp = part ? be1 : be0;
        const float* mmp = part ? m1 : m0;
        const float* vvp = part ? vv1 : vv0;
        float* Cf = part ? C1f : C0f;
        __half* Ch = part ? C1h : C0h;
        const float* Af  = part ? A1f  : (const float*)0;
        const float* Af2 = part ? A1f2 : (const float*)0;
        bool fp32A = (part && Af);

        int bm = bx * 128;
        int bn = by * 64;

        __syncthreads();   // guard s_sc reuse vs previous tile's epilogue
        if (tid < 64) {
            int col = bn + tid;
            float s = gg[col] * rsqrtf(vvp[col] + 1e-5f);
            s_sc[tid] = s;
            s_sb[tid] = (lb[col] - mmp[col]) * s + bbp[col];
        }

        float acc[2][4][4];
#pragma unroll
        for (int a = 0; a < 2; a++)
#pragma unroll
            for (int b = 0; b < 4; b++)
#pragma unroll
                for (int qq = 0; qq < 4; qq++) acc[a][b][qq] = 0.f;

        int arow = wm + ((g & 1) << 3) + r8;
        int brow = wn + ((g >> 1) << 3) + r8;

        auto issue_async = [&](int ch, int stg) {
            int cc = ch << 5;
            uint32_t sb = smbase + stg * STG_SZ;
#pragma unroll
            for (int it = 0; it < 2; it++) {
                int i = tid + it * 256;
                int row = i >> 2, c8 = (i & 3) << 3;
                int sz = (bm + row < M) ? 16 : 0;
                const __half* sa = Ah + (size_t)(bm + row) * K + cc + c8;
                uint32_t doff = (uint32_t)(row * ASTR + c8) * 2;
                CP_ASYNC16(sb + STG_A + doff, sa, sz);
            }
            {
                int row = tid >> 2, c8 = (tid & 3) << 3;
                const __half* sh = Bh + (size_t)(bn + row) * K + cc + c8;
                const __half* sl = Bl + (size_t)(bn + row) * K + cc + c8;
                uint32_t doff = (uint32_t)(row * ASTR + c8) * 2;
                CP_ASYNC16(sb + STG_B_HI + doff, sh, 16);
                CP_ASYNC16(sb + STG_B_LO + doff, sl, 16);
            }
        };
        auto issue_sync = [&](int ch, int stg) {
            int cc = ch << 5;
            char* sb = dsm + stg * STG_SZ;
#pragma unroll
            for (int it = 0; it < 4; it++) {
                int i = tid + it * 256;
                int row = i >> 3, c4 = (i & 7) << 2;
                float4 v = make_float4(0.f, 0.f, 0.f, 0.f);
                if (bm + row < M) {
                    v = *(const float4*)(Af + (size_t)(bm + row) * K + cc + c4);
                    float4 w = *(const float4*)(Af2 + (size_t)(bm + row) * K + cc + c4);
                    v.x += w.x; v.y += w.y; v.z += w.z; v.w += w.w;
                }
                uint2 p;
                p.x = (uint32_t)f16u(v.x) | ((uint32_t)f16u(v.y) << 16);
                p.y = (uint32_t)f16u(v.z) | ((uint32_t)f16u(v.w) << 16);
                *(uint2*)(sb + STG_A + (row * ASTR + c4) * 2) = p;
            }
            {
                int row = tid >> 2, c8 = (tid & 3) << 3;
                uint4 vh = *(const uint4*)(Bh + (size_t)(bn + row) * K + cc + c8);
                uint4 vl = *(const uint4*)(Bl + (size_t)(bn + row) * K + cc + c8);
                int off = (row * ASTR + c8) * 2;
                *(uint4*)(sb + STG_B_HI + off) = vh;
                *(uint4*)(sb + STG_B_LO + off) = vl;
            }
        };

        if (fp32A) issue_sync(0, 0);
        else       issue_async(0, 0);
        CP_COMMIT();

        for (int ch = 0; ch < nch; ch++) {
            if (ch + 1 < nch) {
                if (fp32A) issue_sync(ch + 1, (ch + 1) & 1);
                else       issue_async(ch + 1, (ch + 1) & 1);
            }
            CP_COMMIT();
            CP_WAIT1();
            __syncthreads();

            uint32_t sb = smbase + (ch & 1) * STG_SZ;
#pragma unroll
            for (int ks = 0; ks < 2; ks++) {
                int kk = ks << 4;
                uint32_t a0, a1, a2, a3, a4, a5, a6, a7;
                uint32_t bh0, bh1, bh2, bh3, bh4, bh5, bh6, bh7;
                uint32_t bl0, bl1, bl2, bl3, bl4, bl5, bl6, bl7;
                {
                    uint32_t ad0 = sb + STG_A + ((arow) * ASTR + kk + acolg) * 2;
                    uint32_t ad1 = sb + STG_A + ((arow + 16) * ASTR + kk + acolg) * 2;
                    LDSM_X4(a0, a1, a2, a3, ad0);
                    LDSM_X4(a4, a5, a6, a7, ad1);
                    uint32_t bd0 = sb + STG_B_HI + ((brow) * ASTR + kk + bcolg) * 2;
                    uint32_t bd1 = sb + STG_B_HI + ((brow + 16) * ASTR + kk + bcolg) * 2;
                    LDSM_X4(bh0, bh1, bh2, bh3, bd0);
                    LDSM_X4(bh4, bh5, bh6, bh7, bd1);
                    LDSM_X4(bl0, bl1, bl2, bl3, bd0 + (STG_B_LO - STG_B_HI));
                    LDSM_X4(bl4, bl5, bl6, bl7, bd1 + (STG_B_LO - STG_B_HI));
                }
#define DO_NT(mt, nt, BH0, BH1, BL0, BL1, A0, A1, A2_, A3)                      \
                MMA_F16(acc[mt][nt][0], acc[mt][nt][1], acc[mt][nt][2],         \
                        acc[mt][nt][3], A0, A1, A2_, A3, BH0, BH1);             \
                MMA_F16(acc[mt][nt][0], acc[mt][nt][1], acc[mt][nt][2],         \
                        acc[mt][nt][3], A0, A1, A2_, A3, BL0, BL1);
                DO_NT(0, 0, bh0, bh1, bl0, bl1, a0, a1, a2, a3)
                DO_NT(0, 1, bh2, bh3, bl2, bl3, a0, a1, a2, a3)
                DO_NT(0, 2, bh4, bh5, bl4, bl5, a0, a1, a2, a3)
                DO_NT(0, 3, bh6, bh7, bl6, bl7, a0, a1, a2, a3)
                DO_NT(1, 0, bh0, bh1, bl0, bl1, a4, a5, a6, a7)
                DO_NT(1, 1, bh2, bh3, bl2, bl3, a4, a5, a6, a7)
                DO_NT(1, 2, bh4, bh5, bl4, bl5, a4, a5, a6, a7)
                DO_NT(1, 3, bh6, bh7, bl6, bl7, a4, a5, a6, a7)
#undef DO_NT
            }
            __syncthreads();
        }

        // ---- epilogue
        int rq = lane >> 2, cq = (lane & 3) * 2;
        bool outF16 = (Ch != (__half*)0);
#pragma unroll
        for (int mt = 0; mt < 2; mt++) {
            int r0 = bm + wm + mt * 16 + rq;
#pragma unroll
            for (int nt = 0; nt < 4; nt++) {
                int c0 = wn + nt * 8 + cq;
                float s0 = s_sc[c0], s1 = s_sc[c0 + 1];
                float t0 = s_sb[c0], t1 = s_sb[c0 + 1];
                float v0 = acc[mt][nt][0] * s0 + t0;
                float v1 = acc[mt][nt][1] * s1 + t1;
                float v2 = acc[mt][nt][2] * s0 + t0;
                float v3 = acc[mt][nt][3] * s1 + t1;
                if (do_relu) {
                    v0 = fmaxf(v0, 0.f); v1 = fmaxf(v1, 0.f);
                    v2 = fmaxf(v2, 0.f); v3 = fmaxf(v3, 0.f);
                }
                if (outF16) {
                    if (r0 < M)
                        *(uint32_t*)(Ch + (size_t)r0 * N + bn + c0) =
                            (uint32_t)f16u(v0) | ((uint32_t)f16u(v1) << 16);
                    if (r0 + 8 < M)
                        *(uint32_t*)(Ch + (size_t)(r0 + 8) * N + bn + c0) =
                            (uint32_t)f16u(v2) | ((uint32_t)f16u(v3) << 16);
                } else {
                    if (r0 < M)
                        *(float2*)(Cf + (size_t)r0 * N + bn + c0) = make_float2(v0, v1);
                    if (r0 + 8 < M)
                        *(float2*)(Cf + (size_t)(r0 + 8) * N + bn + c0) = make_float2(v2, v3);
                }
            }
        }
    }
}

// ---------------------------------------------------------------------------
// Host driver
// ---------------------------------------------------------------------------
extern "C" void kernel_launch(void* const* d_in, const int* in_sizes, int n_in,
                              void* d_out, int out_size) {
    const int*   x_atom  = (const int*)d_in[0];
    const int*   ei      = (const int*)d_in[1];
    const int*   ea      = (const int*)d_in[2];
    const int*   batch   = (const int*)d_in[3];
    const float* atomemb = (const float*)d_in[4];
    const float* vn0     = (const float*)d_in[5];
    const float* bond    = (const float*)d_in[6];
    const float* eps     = (const float*)d_in[7];
    const float* W1      = (const float*)d_in[8];
    const float* b1v     = (const float*)d_in[9];
    const float* bn1g    = (const float*)d_in[10];
    const float* bn1b    = (const float*)d_in[11];
    const float* bn1m    = (const float*)d_in[12];
    const float* bn1v    = (const float*)d_in[13];
    const float* W2      = (const float*)d_in[14];
    const float* b2v     = (const float*)d_in[15];
    const float* bng     = (const float*)d_in[16];
    const float* bnb     = (const float*)d_in[17];
    const float* bnm     = (const float*)d_in[18];
    const float* bnv     = (const float*)d_in[19];
    const float* vnW1    = (const float*)d_in[20];
    const float* vnb1    = (const float*)d_in[21];
    const float* vbn1g   = (const float*)d_in[22];
    const float* vbn1b   = (const float*)d_in[23];
    const float* vbn1m   = (const float*)d_in[24];
    const float* vbn1v   = (const float*)d_in[25];
    const float* vnW2    = (const float*)d_in[26];
    const float* vnb2    = (const float*)d_in[27];
    const float* vbn2g   = (const float*)d_in[28];
    const float* vbn2b   = (const float*)d_in[29];
    const float* vbn2m   = (const float*)d_in[30];
    const float* vbn2v   = (const float*)d_in[31];

    int n = in_sizes[3];
    int ecnt = in_sizes[1] / 2;

    float *h, *vn, *gsum, *cb;
    __half *zh, *th, *vth, *Bhi, *Blo;
    int *cnt, *off, *rank;
    int2* csr;
    cudaGetSymbolAddress((void**)&h, g_h);
    cudaGetSymbolAddress((void**)&zh, g_zh);
    cudaGetSymbolAddress((void**)&th, g_th);
    cudaGetSymbolAddress((void**)&vn, g_vn);
    cudaGetSymbolAddress((void**)&gsum, g_gsum);
    cudaGetSymbolAddress((void**)&vth, g_vth);
    cudaGetSymbolAddress((void**)&cb, g_cb);
    cudaGetSymbolAddress((void**)&cnt, g_cnt);
    cudaGetSymbolAddress((void**)&off, g_off);
    cudaGetSymbolAddress((void**)&rank, g_rank);
    cudaGetSymbolAddress((void**)&csr, g_csr);
    cudaGetSymbolAddress((void**)&Bhi, g_Bhi);
    cudaGetSymbolAddress((void**)&Blo, g_Blo);

    cudaFuncSetAttribute(gemm_uni_k, cudaFuncAttributeMaxDynamicSharedMemorySize,
                         SM_TOT);

    const int WSLOT = 32768;
    int gridND = (n * 32 + 255) / 256;

    int c1 = (10 * 32768 + 255) / 256;
    int c2 = c1 + (LL * 1000 * 32 + 255) / 256;
    int c3 = c2 + (n + 255) / 256;
    int c4b = c3 + (GG * 32 + 255) / 256;
    int c5 = c4b + gridND;
    int c6 = c5 + (GG * 32 + 255) / 256;
    fused_pre_k<<<c6, 256>>>(W1, W2, vnW1, vnW2, Bhi, Blo, bond, cb,
                             cnt, gsum, x_atom, atomemb, h, vn0, vn,
                             n, c1, c2, c3, c4b, c5);
    count_k<<<(ecnt / 4 + 255) / 256, 256>>>(ei, cnt, rank, ecnt);
    scan_k<<<1, 1024>>>(cnt, off, n, ecnt);
    scatter_k<<<(ecnt + 255) / 256, 256>>>(ei, ea, off, rank, csr, ecnt);

    int gridM = (n + 127) / 128;
    int gxv = GG / 128;
    const int PERSIST = 296;   // 148 SMs x 2 CTAs
    for (int l = 0; l < LL; l++) {
        int hasVN = (l < LL - 1) ? 1 : 0;
        add_vn_k<<<gridND, 256>>>(h, vn, batch, gsum, n, hasVN);
        edge_csr_k<<<gridND, 256>>>(off, csr, cb + (size_t)l * 1000 * DD, h,
                                    eps + l, zh, n);
        {
            int ny0 = 4, ny1 = 4;
            int gx1 = hasVN ? gxv : 0;
            int total = gridM * ny0 + gx1 * ny1;
            int grid = total < PERSIST ? total : PERSIST;
            gemm_uni_k<<<grid, 256, SM_TOT>>>(
                gridM, ny0, n,
                zh,
                Bhi + (size_t)l * WSLOT, Blo + (size_t)l * WSLOT,
                b1v + l * 256, bn1g + l * 256, bn1b + l * 256,
                bn1m + l * 256, bn1v + l * 256,
                nullptr, th,
                gx1, ny1, hasVN ? GG : 0,
                vn, gsum, nullptr,
                Bhi + (size_t)(6 + l) * WSLOT, Blo + (size_t)(6 + l) * WSLOT,
                vnb1 + l * 256, vbn1g + l * 256, vbn1b + l * 256,
                vbn1m + l * 256, vbn1v + l * 256,
                nullptr, vth,
                nullptr, 0,
                256, 128, 1);
        }
        {
            float* outp = (l == LL - 1) ? (float*)d_out : h;
            int ny0 = 2, ny1 = 2;
            int gx1 = hasVN ? gxv : 0;
            int total = gridM * ny0 + gx1 * ny1;
            int grid = total < PERSIST ? total : PERSIST;
            gemm_uni_k<<<grid, 256, SM_TOT>>>(
                gridM, ny0, n,
                th,
                Bhi + (size_t)(3 + l) * WSLOT, Blo + (size_t)(3 + l) * WSLOT,
                b2v + l * 128, bng + l * 128, bnb + l * 128,
                bnm + l * 128, bnv + l * 128,
                outp, nullptr,
                gx1, ny1, hasVN ? GG : 0,
                nullptr, nullptr, vth,
                Bhi + (size_t)(8 + l) * WSLOT, Blo + (size_t)(8 + l) * WSLOT,
                vnb2 + l * 128, vbn2g + l * 128, vbn2b + l * 128,
                vbn2m + l * 128, vbn2v + l * 128,
                vn, nullptr,
                (l == 0) ? (float4*)gsum : nullptr, GG * 32,
                128, 256, hasVN);
        }
    }
}

// round 15
// speedup vs baseline: 1.4057x; 1.0554x over previous
#include <cuda_runtime.h>
#include <cuda_fp16.h>
#include <cstdint>

#define MAXN 50000
#define MAXE 800000
#define GG   1024
#define DD   128
#define LL   3

// ---------------------------------------------------------------------------
// Static scratch
// ---------------------------------------------------------------------------
__device__ float g_h[MAXN * DD];
__device__ __half g_h16[MAXN * DD];           // fp16 mirror of h (edge gather)
__device__ __half g_zh[MAXN * DD];            // GIN input z, fp16
__device__ __half g_th[MAXN * 2 * DD];        // MLP hidden t, fp16
__device__ float g_vn[GG * DD];
__device__ float g_gsum[GG * DD];
__device__ __half g_vth[GG * 2 * DD];         // vn hidden, fp16
__device__ __half g_cb16[LL * 1000 * DD];     // combined bond table, fp16
__device__ int   g_cnt[MAXN];
__device__ int   g_off[MAXN + 1];
__device__ int   g_rank[MAXE];
__device__ int2  g_csr[MAXE];                  // packed {src, combo}
// Preconverted weights: B^T [N][K] fp16 hi/lo limbs. 10 slots of 32768:
// W1 l0..2, W2 l0..2, vn1 l0..1, vn2 l0..1
__device__ __half g_Bhi[10 * 32768];
__device__ __half g_Blo[10 * 32768];

// ---------------------------------------------------------------------------
// PTX helpers
// ---------------------------------------------------------------------------
__device__ __forceinline__ uint32_t cvta_s(const void* p) {
    uint32_t a;
    asm("{ .reg .u64 t; cvta.to.shared.u64 t, %1; cvt.u32.u64 %0, t; }"
        : "=r"(a) : "l"(p));
    return a;
}
#define LDSM_X4(r0, r1, r2, r3, addr)                                          \
    asm volatile("ldmatrix.sync.aligned.m8n8.x4.shared.b16 {%0,%1,%2,%3}, [%4];"\
                 : "=r"(r0), "=r"(r1), "=r"(r2), "=r"(r3) : "r"(addr))
#define MMA_F16(d0, d1, d2, d3, a0, a1, a2, a3, b0, b1)                        \
    asm volatile("mma.sync.aligned.m16n8k16.row.col.f32.f16.f16.f32 "          \
                 "{%0,%1,%2,%3}, {%4,%5,%6,%7}, {%8,%9}, {%0,%1,%2,%3};"       \
                 : "+f"(d0), "+f"(d1), "+f"(d2), "+f"(d3)                      \
                 : "r"(a0), "r"(a1), "r"(a2), "r"(a3), "r"(b0), "r"(b1))
#define CP_ASYNC16(dst, src, sz)                                               \
    asm volatile("cp.async.cg.shared.global [%0], [%1], 16, %2;"               \
                 :: "r"(dst), "l"(src), "r"(sz))
#define CP_COMMIT() asm volatile("cp.async.commit_group;" ::: "memory")
#define CP_WAIT1()  asm volatile("cp.async.wait_group 1;" ::: "memory")

__device__ __forceinline__ void split_f16(float v, unsigned short& hi,
                                          unsigned short& lo) {
    __half h = __float2half_rn(v);
    hi = __half_as_ushort(h);
    lo = __half_as_ushort(__float2half_rn(v - __half2float(h)));
}
__device__ __forceinline__ unsigned short f16u(float v) {
    return __half_as_ushort(__float2half_rn(v));
}
__device__ __forceinline__ float4 unp4(uint2 p) {
    __half2 a = *(__half2*)&p.x, b = *(__half2*)&p.y;
    float2 fa = __half22float2(a), fb = __half22float2(b);
    return make_float4(fa.x, fa.y, fb.x, fb.y);
}

// ---------------------------------------------------------------------------
// Mega-fused preprocessing (weights + combo table + zeros + atom + vn init)
// ---------------------------------------------------------------------------
__global__ void fused_pre_k(
    const float* __restrict__ W1, const float* __restrict__ W2,
    const float* __restrict__ vnW1, const float* __restrict__ vnW2,
    __half* __restrict__ Bhi, __half* __restrict__ Blo,
    const float* __restrict__ bond, __half* __restrict__ cb16,
    int* __restrict__ cnt, float* __restrict__ gsum,
    const int* __restrict__ xa, const float* __restrict__ emb,
    float* __restrict__ h,
    const float* __restrict__ v0, float* __restrict__ vn,
    int n, int c1, int c2, int c3, int c4b, int c5) {
    int blk = blockIdx.x;
    int tid = threadIdx.x;
    if (blk < c1) {
        int idx = blk * 256 + tid;
        if (idx < 10 * 32768) {
            int slot = idx >> 15;
            int r = idx & 32767;
            const float* W;
            int Nd;
            if (slot < 3)      { W = W1 + (size_t)slot * 32768;         Nd = 256; }
            else if (slot < 6) { W = W2 + (size_t)(slot - 3) * 32768;   Nd = 128; }
            else if (slot < 8) { W = vnW1 + (size_t)(slot - 6) * 32768; Nd = 256; }
            else               { W = vnW2 + (size_t)(slot - 8) * 32768; Nd = 128; }
            int Kd = 32768 / Nd;
            int k = r / Nd, nn = r % Nd;
            unsigned short hi, lo;
            split_f16(W[r], hi, lo);
            size_t o = (size_t)slot * 32768 + (size_t)nn * Kd + k;
            Bhi[o] = __ushort_as_half(hi);
            Blo[o] = __ushort_as_half(lo);
        }
    } else if (blk < c2) {
        int idx = (blk - c1) * 256 + tid;
        if (idx < LL * 1000 * 32) {
            int cc4 = (idx & 31) << 2;
            int i = (idx >> 5) % 1000;
            int l = (idx >> 5) / 1000;
            int f0 = i / 100, f1 = (i / 10) % 10, f2 = i % 10;
            float4 a = *(const float4*)(bond + ((size_t)(l * 3 + 0) * 10 + f0) * DD + cc4);
            float4 b = *(const float4*)(bond + ((size_t)(l * 3 + 1) * 10 + f1) * DD + cc4);
            float4 c = *(const float4*)(bond + ((size_t)(l * 3 + 2) * 10 + f2) * DD + cc4);
            float4 o;
            o.x = a.x + b.x + c.x; o.y = a.y + b.y + c.y;
            o.z = a.z + b.z + c.z; o.w = a.w + b.w + c.w;
            uint2 p;
            p.x = (uint32_t)f16u(o.x) | ((uint32_t)f16u(o.y) << 16);
            p.y = (uint32_t)f16u(o.z) | ((uint32_t)f16u(o.w) << 16);
            *(uint2*)(cb16 + ((size_t)(l * 1000 + i)) * DD + cc4) = p;
        }
    } else if (blk < c3) {
        int i = (blk - c2) * 256 + tid;
        if (i < n) cnt[i] = 0;
    } else if (blk < c4b) {
        int i = (blk - c3) * 256 + tid;
        if (i < GG * 32)
            *(float4*)(gsum + i * 4) = make_float4(0.f, 0.f, 0.f, 0.f);
    } else if (blk < c5) {
        int idx = (blk - c4b) * 256 + tid;
        if (idx < n * 32) {
            int node = idx >> 5;
            int cc4 = (idx & 31) << 2;
            float4 s = make_float4(0.f, 0.f, 0.f, 0.f);
#pragma unroll
            for (int f = 0; f < 9; f++) {
                int v = xa[node * 9 + f];
                float4 e = *(const float4*)(emb + (f * 100 + v) * DD + cc4);
                s.x += e.x; s.y += e.y; s.z += e.z; s.w += e.w;
            }
            *(float4*)(h + node * DD + cc4) = s;
        }
    } else {
        int idx = (blk - c5) * 256 + tid;
        if (idx < GG * 32) {
            int cc4 = (idx & 31) << 2;
            *(float4*)(vn + idx * 4) = *(const float4*)(v0 + cc4);
        }
    }
}

// ---------------------------------------------------------------------------
// CSR build
// ---------------------------------------------------------------------------
__global__ void count_k(const int* __restrict__ ei, int* __restrict__ cnt,
                        int* __restrict__ rank, int ecnt) {
    int j = (blockIdx.x * blockDim.x + threadIdx.x) * 4;
    if (j + 3 < ecnt) {
        int4 d = *(const int4*)(ei + ecnt + j);
        rank[j + 0] = atomicAdd(&cnt[d.x], 1);
        rank[j + 1] = atomicAdd(&cnt[d.y], 1);
        rank[j + 2] = atomicAdd(&cnt[d.z], 1);
        rank[j + 3] = atomicAdd(&cnt[d.w], 1);
    } else {
        for (int q = j; q < ecnt; q++)
            rank[q] = atomicAdd(&cnt[ei[ecnt + q]], 1);
    }
}
__global__ void scan_k(const int* __restrict__ cnt, int* __restrict__ off,
                       int n, int ecnt) {
    __shared__ int part[1024];
    int t = threadIdx.x;
    int chunk = (n + 1023) >> 10;
    int beg = t * chunk;
    int end = min(beg + chunk, n);
    int s = 0;
    for (int i = beg; i < end; i++) s += cnt[i];
    part[t] = s;
    __syncthreads();
    for (int d = 1; d < 1024; d <<= 1) {
        int v = (t >= d) ? part[t - d] : 0;
        __syncthreads();
        if (t >= d) part[t] += v;
        __syncthreads();
    }
    int run = (t == 0) ? 0 : part[t - 1];
    for (int i = beg; i < end; i++) {
        off[i] = run;
        run += cnt[i];
    }
    if (t == 0) off[n] = ecnt;
}
__global__ void scatter_k(const int* __restrict__ ei, const int* __restrict__ ea,
                          const int* __restrict__ off, const int* __restrict__ rank,
                          int2* __restrict__ csr, int ecnt) {
    int j = blockIdx.x * blockDim.x + threadIdx.x;
    if (j >= ecnt) return;
    int dst = ei[ecnt + j];
    int cm = ea[j * 3] * 100 + ea[j * 3 + 1] * 10 + ea[j * 3 + 2];
    csr[off[dst] + rank[j]] = make_int2(ei[j], cm);
}

// ---------------------------------------------------------------------------
// h += vn[batch]; write fp16 mirror; optionally gsum[batch] += h (post-update)
// ---------------------------------------------------------------------------
__global__ void add_vn_k(float* __restrict__ h, __half* __restrict__ h16,
                         const float* __restrict__ vn,
                         const int* __restrict__ batch,
                         float* __restrict__ gsum, int n, int dosum) {
    int idx = blockIdx.x * blockDim.x + threadIdx.x;
    if (idx >= n * 32) return;
    int node = idx >> 5;
    int c4 = (idx & 31) << 2;
    int g = batch[node];
    float4 hv = *(float4*)(h + idx * 4);
    float4 vv = *(const float4*)(vn + g * DD + c4);
    hv.x += vv.x; hv.y += vv.y; hv.z += vv.z; hv.w += vv.w;
    *(float4*)(h + idx * 4) = hv;
    uint2 p;
    p.x = (uint32_t)f16u(hv.x) | ((uint32_t)f16u(hv.y) << 16);
    p.y = (uint32_t)f16u(hv.z) | ((uint32_t)f16u(hv.w) << 16);
    *(uint2*)(h16 + idx * 4) = p;
    if (dosum) {
        float* p2 = gsum + g * DD + c4;
        asm volatile("red.global.add.v4.f32 [%0], {%1,%2,%3,%4};"
                     :: "l"(p2), "f"(hv.x), "f"(hv.y), "f"(hv.z), "f"(hv.w)
                     : "memory");
    }
}

// ---------------------------------------------------------------------------
// Edge gather (CSR, fp16 h16/cb16 -> half traffic), 4x unrolled.
// z = fp16( (1+eps)*h + sum relu(h16[src] + cb16[combo]) )
// ---------------------------------------------------------------------------
__global__ void edge_csr_k(const int* __restrict__ off,
                           const int2* __restrict__ csr,
                           const __half* __restrict__ cb16,
                           const float* __restrict__ h,
                           const __half* __restrict__ h16,
                           const float* __restrict__ eps_p,
                           __half* __restrict__ zh, int n) {
    int warp = (blockIdx.x * blockDim.x + threadIdx.x) >> 5;
    if (warp >= n) return;
    int lane = threadIdx.x & 31;
    int c4 = lane << 2;
    float4 acc = make_float4(0.f, 0.f, 0.f, 0.f);
    int beg = off[warp], end = off[warp + 1];
    const unsigned FULL = 0xffffffffu;
    for (int base = beg; base < end; base += 32) {
        int m = min(32, end - base);
        int s = 0, cm = 0;
        if (base + lane < end) {
            int2 e = csr[base + lane];
            s = e.x; cm = e.y;
        }
        int k = 0;
        for (; k + 4 <= m; k += 4) {
            int s0 = __shfl_sync(FULL, s, k),     c0 = __shfl_sync(FULL, cm, k);
            int s1 = __shfl_sync(FULL, s, k + 1), c1 = __shfl_sync(FULL, cm, k + 1);
            int s2 = __shfl_sync(FULL, s, k + 2), c2 = __shfl_sync(FULL, cm, k + 2);
            int s3 = __shfl_sync(FULL, s, k + 3), c3 = __shfl_sync(FULL, cm, k + 3);
            uint2 hp0 = *(const uint2*)(h16 + (size_t)s0 * DD + c4);
            uint2 ep0 = *(const uint2*)(cb16 + (size_t)c0 * DD + c4);
            uint2 hp1 = *(const uint2*)(h16 + (size_t)s1 * DD + c4);
            uint2 ep1 = *(const uint2*)(cb16 + (size_t)c1 * DD + c4);
            uint2 hp2 = *(const uint2*)(h16 + (size_t)s2 * DD + c4);
            uint2 ep2 = *(const uint2*)(cb16 + (size_t)c2 * DD + c4);
            uint2 hp3 = *(const uint2*)(h16 + (size_t)s3 * DD + c4);
            uint2 ep3 = *(const uint2*)(cb16 + (size_t)c3 * DD + c4);
            float4 h0 = unp4(hp0), e0 = unp4(ep0);
            float4 h1 = unp4(hp1), e1 = unp4(ep1);
            float4 h2 = unp4(hp2), e2 = unp4(ep2);
            float4 h3 = unp4(hp3), e3 = unp4(ep3);
            acc.x += fmaxf(h0.x + e0.x, 0.f) + fmaxf(h1.x + e1.x, 0.f)
                   + fmaxf(h2.x + e2.x, 0.f) + fmaxf(h3.x + e3.x, 0.f);
            acc.y += fmaxf(h0.y + e0.y, 0.f) + fmaxf(h1.y + e1.y, 0.f)
                   + fmaxf(h2.y + e2.y, 0.f) + fmaxf(h3.y + e3.y, 0.f);
            acc.z += fmaxf(h0.z + e0.z, 0.f) + fmaxf(h1.z + e1.z, 0.f)
                   + fmaxf(h2.z + e2.z, 0.f) + fmaxf(h3.z + e3.z, 0.f);
            acc.w += fmaxf(h0.w + e0.w, 0.f) + fmaxf(h1.w + e1.w, 0.f)
                   + fmaxf(h2.w + e2.w, 0.f) + fmaxf(h3.w + e3.w, 0.f);
        }
        for (; k < m; k++) {
            int ss = __shfl_sync(FULL, s, k);
            int cc = __shfl_sync(FULL, cm, k);
            float4 hv = unp4(*(const uint2*)(h16 + (size_t)ss * DD + c4));
            float4 ev = unp4(*(const uint2*)(cb16 + (size_t)cc * DD + c4));
            acc.x += fmaxf(hv.x + ev.x, 0.f);
            acc.y += fmaxf(hv.y + ev.y, 0.f);
            acc.z += fmaxf(hv.z + ev.z, 0.f);
            acc.w += fmaxf(hv.w + ev.w, 0.f);
        }
    }
    float al = 1.0f + *eps_p;
    float4 hv = *(const float4*)(h + (size_t)warp * DD + c4);
    uint2 zp;
    zp.x = (uint32_t)f16u(al * hv.x + acc.x) |
           ((uint32_t)f16u(al * hv.y + acc.y) << 16);
    zp.y = (uint32_t)f16u(al * hv.z + acc.z) |
           ((uint32_t)f16u(al * hv.w + acc.w) << 16);
    *(uint2*)(zh + (size_t)warp * DD + c4) = zp;
}

// ---------------------------------------------------------------------------
// Persistent unified GEMM, fp16 2-product split (A single limb, B hi/lo):
//   D = A @ Bhi + A @ Blo
// cp.async 2-stage, BK=32, vn rider tiles. Stage = 20 KB.
// ---------------------------------------------------------------------------
#define ASTR 40
#define STG_A    0
#define STG_B_HI 10240
#define STG_B_LO 15360
#define STG_SZ   20480
#define SM_TOT   40960

__global__ void __launch_bounds__(256, 2)
gemm_uni_k(int gx0, int ny0, int M0,
           const __half* __restrict__ A0h,
           const __half* __restrict__ B0hi, const __half* __restrict__ B0lo,
           const float* __restrict__ lb0, const float* __restrict__ g0,
           const float* __restrict__ be0, const float* __restrict__ m0,
           const float* __restrict__ vv0,
           float* __restrict__ C0f, __half* __restrict__ C0h,
           int gx1, int ny1, int M1,
           const float* __restrict__ A1f, const float* __restrict__ A1f2,
           const __half* __restrict__ A1h,
           const __half* __restrict__ B1hi, const __half* __restrict__ B1lo,
           const float* __restrict__ lb1, const float* __restrict__ g1,
           const float* __restrict__ be1, const float* __restrict__ m1,
           const float* __restrict__ vv1,
           float* __restrict__ C1f, __half* __restrict__ C1h,
           float4* __restrict__ zbuf, int zcnt4,
           int N, int K, int do_relu) {
    extern __shared__ char dsm[];
    __shared__ float s_sc[64], s_sb[64];

    int tid = threadIdx.x;
    int lane = tid & 31, wid = tid >> 5;
    uint32_t smbase = cvta_s(dsm);

    if (zbuf) {
        for (int i = blockIdx.x * 256 + tid; i < zcnt4; i += gridDim.x * 256)
            zbuf[i] = make_float4(0.f, 0.f, 0.f, 0.f);
    }

    int ntile0 = gx0 * ny0;
    int total = ntile0 + gx1 * ny1;

    int wm = (wid >> 1) * 32;
    int wn = (wid & 1) * 32;
    int r8 = lane & 7, g = lane >> 3;
    int acolg = (g >> 1) << 3;
    int bcolg = (g & 1) << 3;
    int nch = K >> 5;

    for (int tile = blockIdx.x; tile < total; tile += gridDim.x) {
        int part = 0, bx, by;
        int q = tile;
        if (q < ntile0) { bx = q / ny0; by = q % ny0; }
        else { part = 1; q -= ntile0; bx = q / ny1; by = q % ny1; }

        int M = part ? M1 : M0;
        const __half* Ah = part ? A1h : A0h;
        const __half* Bh = part ? B1hi : B0hi;
        const __half* Bl = part ? B1lo : B0lo;
        const float* lb = part ? lb1 : lb0;
        const float* gg = part ? g1 : g0;
        const float* bbp = part ? be1 : be0;
        const float* mmp = part ? m1 : m0;
        const float* vvp = part ? vv1 : vv0;
        float* Cf = part ? C1f : C0f;
        __half* Ch = part ? C1h : C0h;
        const float* Af  = part ? A1f  : (const float*)0;
        const float* Af2 = part ? A1f2 : (const float*)0;
        bool fp32A = (part && Af);

        int bm = bx * 128;
        int bn = by * 64;

        __syncthreads();   // guard s_sc reuse vs previous tile's epilogue
        if (tid < 64) {
            int col = bn + tid;
            float s = gg[col] * rsqrtf(vvp[col] + 1e-5f);
            s_sc[tid] = s;
            s_sb[tid] = (lb[col] - mmp[col]) * s + bbp[col];
        }

        float acc[2][4][4];
#pragma unroll
        for (int a = 0; a < 2; a++)
#pragma unroll
            for (int b = 0; b < 4; b++)
#pragma unroll
                for (int qq = 0; qq < 4; qq++) acc[a][b][qq] = 0.f;

        int arow = wm + ((g & 1) << 3) + r8;
        int brow = wn + ((g >> 1) << 3) + r8;

        auto issue_async = [&](int ch, int stg) {
            int cc = ch << 5;
            uint32_t sb = smbase + stg * STG_SZ;
#pragma unroll
            for (int it = 0; it < 2; it++) {
                int i = tid + it * 256;
                int row = i >> 2, c8 = (i & 3) << 3;
                int sz = (bm + row < M) ? 16 : 0;
                const __half* sa = Ah + (size_t)(bm + row) * K + cc + c8;
                uint32_t doff = (uint32_t)(row * ASTR + c8) * 2;
                CP_ASYNC16(sb + STG_A + doff, sa, sz);
            }
            {
                int row = tid >> 2, c8 = (tid & 3) << 3;
                const __half* sh = Bh + (size_t)(bn + row) * K + cc + c8;
                const __half* sl = Bl + (size_t)(bn + row) * K + cc + c8;
                uint32_t doff = (uint32_t)(row * ASTR + c8) * 2;
                CP_ASYNC16(sb + STG_B_HI + doff, sh, 16);
                CP_ASYNC16(sb + STG_B_LO + doff, sl, 16);
            }
        };
        auto issue_sync = [&](int ch, int stg) {
            int cc = ch << 5;
            char* sb = dsm + stg * STG_SZ;
#pragma unroll
            for (int it = 0; it < 4; it++) {
                int i = tid + it * 256;
                int row = i >> 3, c4 = (i & 7) << 2;
                float4 v = make_float4(0.f, 0.f, 0.f, 0.f);
                if (bm + row < M) {
                    v = *(const float4*)(Af + (size_t)(bm + row) * K + cc + c4);
                    float4 w = *(const float4*)(Af2 + (size_t)(bm + row) * K + cc + c4);
                    v.x += w.x; v.y += w.y; v.z += w.z; v.w += w.w;
                }
                uint2 p;
                p.x = (uint32_t)f16u(v.x) | ((uint32_t)f16u(v.y) << 16);
                p.y = (uint32_t)f16u(v.z) | ((uint32_t)f16u(v.w) << 16);
                *(uint2*)(sb + STG_A + (row * ASTR + c4) * 2) = p;
            }
            {
                int row = tid >> 2, c8 = (tid & 3) << 3;
                uint4 vh = *(const uint4*)(Bh + (size_t)(bn + row) * K + cc + c8);
                uint4 vl = *(const uint4*)(Bl + (size_t)(bn + row) * K + cc + c8);
                int off = (row * ASTR + c8) * 2;
                *(uint4*)(sb + STG_B_HI + off) = vh;
                *(uint4*)(sb + STG_B_LO + off) = vl;
            }
        };

        if (fp32A) issue_sync(0, 0);
        else       issue_async(0, 0);
        CP_COMMIT();

        for (int ch = 0; ch < nch; ch++) {
            if (ch + 1 < nch) {
                if (fp32A) issue_sync(ch + 1, (ch + 1) & 1);
                else       issue_async(ch + 1, (ch + 1) & 1);
            }
            CP_COMMIT();
            CP_WAIT1();
            __syncthreads();

            uint32_t sb = smbase + (ch & 1) * STG_SZ;
#pragma unroll
            for (int ks = 0; ks < 2; ks++) {
                int kk = ks << 4;
                uint32_t a0, a1, a2, a3, a4, a5, a6, a7;
                uint32_t bh0, bh1, bh2, bh3, bh4, bh5, bh6, bh7;
                uint32_t bl0, bl1, bl2, bl3, bl4, bl5, bl6, bl7;
                {
                    uint32_t ad0 = sb + STG_A + ((arow) * ASTR + kk + acolg) * 2;
                    uint32_t ad1 = sb + STG_A + ((arow + 16) * ASTR + kk + acolg) * 2;
                    LDSM_X4(a0, a1, a2, a3, ad0);
                    LDSM_X4(a4, a5, a6, a7, ad1);
                    uint32_t bd0 = sb + STG_B_HI + ((brow) * ASTR + kk + bcolg) * 2;
                    uint32_t bd1 = sb + STG_B_HI + ((brow + 16) * ASTR + kk + bcolg) * 2;
                    LDSM_X4(bh0, bh1, bh2, bh3, bd0);
                    LDSM_X4(bh4, bh5, bh6, bh7, bd1);
                    LDSM_X4(bl0, bl1, bl2, bl3, bd0 + (STG_B_LO - STG_B_HI));
                    LDSM_X4(bl4, bl5, bl6, bl7, bd1 + (STG_B_LO - STG_B_HI));
                }
#define DO_NT(mt, nt, BH0, BH1, BL0, BL1, A0, A1, A2_, A3)                      \
                MMA_F16(acc[mt][nt][0], acc[mt][nt][1], acc[mt][nt][2],         \
                        acc[mt][nt][3], A0, A1, A2_, A3, BH0, BH1);             \
                MMA_F16(acc[mt][nt][0], acc[mt][nt][1], acc[mt][nt][2],         \
                        acc[mt][nt][3], A0, A1, A2_, A3, BL0, BL1);
                DO_NT(0, 0, bh0, bh1, bl0, bl1, a0, a1, a2, a3)
                DO_NT(0, 1, bh2, bh3, bl2, bl3, a0, a1, a2, a3)
                DO_NT(0, 2, bh4, bh5, bl4, bl5, a0, a1, a2, a3)
                DO_NT(0, 3, bh6, bh7, bl6, bl7, a0, a1, a2, a3)
                DO_NT(1, 0, bh0, bh1, bl0, bl1, a4, a5, a6, a7)
                DO_NT(1, 1, bh2, bh3, bl2, bl3, a4, a5, a6, a7)
                DO_NT(1, 2, bh4, bh5, bl4, bl5, a4, a5, a6, a7)
                DO_NT(1, 3, bh6, bh7, bl6, bl7, a4, a5, a6, a7)
#undef DO_NT
            }
            __syncthreads();
        }

        // ---- epilogue
        int rq = lane >> 2, cq = (lane & 3) * 2;
        bool outF16 = (Ch != (__half*)0);
#pragma unroll
        for (int mt = 0; mt < 2; mt++) {
            int r0 = bm + wm + mt * 16 + rq;
#pragma unroll
            for (int nt = 0; nt < 4; nt++) {
                int c0 = wn + nt * 8 + cq;
                float s0 = s_sc[c0], s1 = s_sc[c0 + 1];
                float t0 = s_sb[c0], t1 = s_sb[c0 + 1];
                float v0 = acc[mt][nt][0] * s0 + t0;
                float v1 = acc[mt][nt][1] * s1 + t1;
                float v2 = acc[mt][nt][2] * s0 + t0;
                float v3 = acc[mt][nt][3] * s1 + t1;
                if (do_relu) {
                    v0 = fmaxf(v0, 0.f); v1 = fmaxf(v1, 0.f);
                    v2 = fmaxf(v2, 0.f); v3 = fmaxf(v3, 0.f);
                }
                if (outF16) {
                    if (r0 < M)
                        *(uint32_t*)(Ch + (size_t)r0 * N + bn + c0) =
                            (uint32_t)f16u(v0) | ((uint32_t)f16u(v1) << 16);
                    if (r0 + 8 < M)
                        *(uint32_t*)(Ch + (size_t)(r0 + 8) * N + bn + c0) =
                            (uint32_t)f16u(v2) | ((uint32_t)f16u(v3) << 16);
                } else {
                    if (r0 < M)
                        *(float2*)(Cf + (size_t)r0 * N + bn + c0) = make_float2(v0, v1);
                    if (r0 + 8 < M)
                        *(float2*)(Cf + (size_t)(r0 + 8) * N + bn + c0) = make_float2(v2, v3);
                }
            }
        }
    }
}

// ---------------------------------------------------------------------------
// Host driver
// ---------------------------------------------------------------------------
extern "C" void kernel_launch(void* const* d_in, const int* in_sizes, int n_in,
                              void* d_out, int out_size) {
    const int*   x_atom  = (const int*)d_in[0];
    const int*   ei      = (const int*)d_in[1];
    const int*   ea      = (const int*)d_in[2];
    const int*   batch   = (const int*)d_in[3];
    const float* atomemb = (const float*)d_in[4];
    const float* vn0     = (const float*)d_in[5];
    const float* bond    = (const float*)d_in[6];
    const float* eps     = (const float*)d_in[7];
    const float* W1      = (const float*)d_in[8];
    const float* b1v     = (const float*)d_in[9];
    const float* bn1g    = (const float*)d_in[10];
    const float* bn1b    = (const float*)d_in[11];
    const float* bn1m    = (const float*)d_in[12];
    const float* bn1v    = (const float*)d_in[13];
    const float* W2      = (const float*)d_in[14];
    const float* b2v     = (const float*)d_in[15];
    const float* bng     = (const float*)d_in[16];
    const float* bnb     = (const float*)d_in[17];
    const float* bnm     = (const float*)d_in[18];
    const float* bnv     = (const float*)d_in[19];
    const float* vnW1    = (const float*)d_in[20];
    const float* vnb1    = (const float*)d_in[21];
    const float* vbn1g   = (const float*)d_in[22];
    const float* vbn1b   = (const float*)d_in[23];
    const float* vbn1m   = (const float*)d_in[24];
    const float* vbn1v   = (const float*)d_in[25];
    const float* vnW2    = (const float*)d_in[26];
    const float* vnb2    = (const float*)d_in[27];
    const float* vbn2g   = (const float*)d_in[28];
    const float* vbn2b   = (const float*)d_in[29];
    const float* vbn2m   = (const float*)d_in[30];
    const float* vbn2v   = (const float*)d_in[31];

    int n = in_sizes[3];
    int ecnt = in_sizes[1] / 2;

    float *h, *vn, *gsum;
    __half *h16, *zh, *th, *vth, *cb16, *Bhi, *Blo;
    int *cnt, *off, *rank;
    int2* csr;
    cudaGetSymbolAddress((void**)&h, g_h);
    cudaGetSymbolAddress((void**)&h16, g_h16);
    cudaGetSymbolAddress((void**)&zh, g_zh);
    cudaGetSymbolAddress((void**)&th, g_th);
    cudaGetSymbolAddress((void**)&vn, g_vn);
    cudaGetSymbolAddress((void**)&gsum, g_gsum);
    cudaGetSymbolAddress((void**)&vth, g_vth);
    cudaGetSymbolAddress((void**)&cb16, g_cb16);
    cudaGetSymbolAddress((void**)&cnt, g_cnt);
    cudaGetSymbolAddress((void**)&off, g_off);
    cudaGetSymbolAddress((void**)&rank, g_rank);
    cudaGetSymbolAddress((void**)&csr, g_csr);
    cudaGetSymbolAddress((void**)&Bhi, g_Bhi);
    cudaGetSymbolAddress((void**)&Blo, g_Blo);

    cudaFuncSetAttribute(gemm_uni_k, cudaFuncAttributeMaxDynamicSharedMemorySize,
                         SM_TOT);

    const int WSLOT = 32768;
    int gridND = (n * 32 + 255) / 256;

    int c1 = (10 * 32768 + 255) / 256;
    int c2 = c1 + (LL * 1000 * 32 + 255) / 256;
    int c3 = c2 + (n + 255) / 256;
    int c4b = c3 + (GG * 32 + 255) / 256;
    int c5 = c4b + gridND;
    int c6 = c5 + (GG * 32 + 255) / 256;
    fused_pre_k<<<c6, 256>>>(W1, W2, vnW1, vnW2, Bhi, Blo, bond, cb16,
                             cnt, gsum, x_atom, atomemb, h, vn0, vn,
                             n, c1, c2, c3, c4b, c5);
    count_k<<<(ecnt / 4 + 255) / 256, 256>>>(ei, cnt, rank, ecnt);
    scan_k<<<1, 1024>>>(cnt, off, n, ecnt);
    scatter_k<<<(ecnt + 255) / 256, 256>>>(ei, ea, off, rank, csr, ecnt);

    int gridM = (n + 127) / 128;
    int gxv = GG / 128;
    const int PERSIST = 296;   // 148 SMs x 2 CTAs
    for (int l = 0; l < LL; l++) {
        int hasVN = (l < LL - 1) ? 1 : 0;
        add_vn_k<<<gridND, 256>>>(h, h16, vn, batch, gsum, n, hasVN);
        edge_csr_k<<<gridND, 256>>>(off, csr, cb16 + (size_t)l * 1000 * DD,
                                    h, h16, eps + l, zh, n);
        {
            int ny0 = 4, ny1 = 4;
            int gx1 = hasVN ? gxv : 0;
            int total = gridM * ny0 + gx1 * ny1;
            int grid = total < PERSIST ? total : PERSIST;
            gemm_uni_k<<<grid, 256, SM_TOT>>>(
                gridM, ny0, n,
                zh,
                Bhi + (size_t)l * WSLOT, Blo + (size_t)l * WSLOT,
                b1v + l * 256, bn1g + l * 256, bn1b + l * 256,
                bn1m + l * 256, bn1v + l * 256,
                nullptr, th,
                gx1, ny1, hasVN ? GG : 0,
                vn, gsum, nullptr,
                Bhi + (size_t)(6 + l) * WSLOT, Blo + (size_t)(6 + l) * WSLOT,
                vnb1 + l * 256, vbn1g + l * 256, vbn1b + l * 256,
                vbn1m + l * 256, vbn1v + l * 256,
                nullptr, vth,
                nullptr, 0,
                256, 128, 1);
        }
        {
            float* outp = (l == LL - 1) ? (float*)d_out : h;
            int ny0 = 2, ny1 = 2;
            int gx1 = hasVN ? gxv : 0;
            int total = gridM * ny0 + gx1 * ny1;
            int grid = total < PERSIST ? total : PERSIST;
            gemm_uni_k<<<grid, 256, SM_TOT>>>(
                gridM, ny0, n,
                th,
                Bhi + (size_t)(3 + l) * WSLOT, Blo + (size_t)(3 + l) * WSLOT,
                b2v + l * 128, bng + l * 128, bnb + l * 128,
                bnm + l * 128, bnv + l * 128,
                outp, nullptr,
                gx1, ny1, hasVN ? GG : 0,
                nullptr, nullptr, vth,
                Bhi + (size_t)(8 + l) * WSLOT, Blo + (size_t)(8 + l) * WSLOT,
                vnb2 + l * 128, vbn2g + l * 128, vbn2b + l * 128,
                vbn2m + l * 128, vbn2v + l * 128,
                vn, nullptr,
                (l == 0) ? (float4*)gsum : nullptr, GG * 32,
                128, 256, hasVN);
        }
    }
}

// round 16
// speedup vs baseline: 1.5330x; 1.0905x over previous
#include <cuda_runtime.h>
#include <cuda_fp16.h>
#include <cstdint>

#define MAXN 50000
#define MAXE 800000
#define GG   1024
#define DD   128
#define LL   3

// ---------------------------------------------------------------------------
// Static scratch
// ---------------------------------------------------------------------------
__device__ float g_h[MAXN * DD];
__device__ __half g_h16[MAXN * DD];           // fp16 mirror of h (edge gather)
__device__ __half g_zh[MAXN * DD];            // GIN input z, fp16
__device__ __half g_th[MAXN * 2 * DD];        // MLP hidden t, fp16
__device__ float g_vn[GG * DD];
__device__ float g_gsum[GG * DD];
__device__ __half g_vth[GG * 2 * DD];         // vn hidden, fp16
__device__ __half g_cb16[LL * 1000 * DD];     // combined bond table, fp16
__device__ int   g_cnt[MAXN];
__device__ int   g_off[MAXN + 1];
__device__ int   g_rank[MAXE];
__device__ int2  g_csr[MAXE];                  // packed {src, combo}
// Preconverted weights: B^T [N][K] fp16 hi/lo limbs. 10 slots of 32768:
// W1 l0..2, W2 l0..2, vn1 l0..1, vn2 l0..1
__device__ __half g_Bhi[10 * 32768];
__device__ __half g_Blo[10 * 32768];

// ---------------------------------------------------------------------------
// PTX helpers
// ---------------------------------------------------------------------------
__device__ __forceinline__ uint32_t cvta_s(const void* p) {
    uint32_t a;
    asm("{ .reg .u64 t; cvta.to.shared.u64 t, %1; cvt.u32.u64 %0, t; }"
        : "=r"(a) : "l"(p));
    return a;
}
#define LDSM_X4(r0, r1, r2, r3, addr)                                          \
    asm volatile("ldmatrix.sync.aligned.m8n8.x4.shared.b16 {%0,%1,%2,%3}, [%4];"\
                 : "=r"(r0), "=r"(r1), "=r"(r2), "=r"(r3) : "r"(addr))
#define MMA_F16(d0, d1, d2, d3, a0, a1, a2, a3, b0, b1)                        \
    asm volatile("mma.sync.aligned.m16n8k16.row.col.f32.f16.f16.f32 "          \
                 "{%0,%1,%2,%3}, {%4,%5,%6,%7}, {%8,%9}, {%0,%1,%2,%3};"       \
                 : "+f"(d0), "+f"(d1), "+f"(d2), "+f"(d3)                      \
                 : "r"(a0), "r"(a1), "r"(a2), "r"(a3), "r"(b0), "r"(b1))
#define CP_ASYNC16(dst, src, sz)                                               \
    asm volatile("cp.async.cg.shared.global [%0], [%1], 16, %2;"               \
                 :: "r"(dst), "l"(src), "r"(sz))
#define CP_COMMIT() asm volatile("cp.async.commit_group;" ::: "memory")
#define CP_WAIT1()  asm volatile("cp.async.wait_group 1;" ::: "memory")

__device__ __forceinline__ void split_f16(float v, unsigned short& hi,
                                          unsigned short& lo) {
    __half h = __float2half_rn(v);
    hi = __half_as_ushort(h);
    lo = __half_as_ushort(__float2half_rn(v - __half2float(h)));
}
__device__ __forceinline__ unsigned short f16u(float v) {
    return __half_as_ushort(__float2half_rn(v));
}

// ---------------------------------------------------------------------------
// Mega-fused preprocessing (weights + combo table + zeros + atom + vn init)
// ---------------------------------------------------------------------------
__global__ void fused_pre_k(
    const float* __restrict__ W1, const float* __restrict__ W2,
    const float* __restrict__ vnW1, const float* __restrict__ vnW2,
    __half* __restrict__ Bhi, __half* __restrict__ Blo,
    const float* __restrict__ bond, __half* __restrict__ cb16,
    int* __restrict__ cnt, float* __restrict__ gsum,
    const int* __restrict__ xa, const float* __restrict__ emb,
    float* __restrict__ h,
    const float* __restrict__ v0, float* __restrict__ vn,
    int n, int c1, int c2, int c3, int c4b, int c5) {
    int blk = blockIdx.x;
    int tid = threadIdx.x;
    if (blk < c1) {
        int idx = blk * 256 + tid;
        if (idx < 10 * 32768) {
            int slot = idx >> 15;
            int r = idx & 32767;
            const float* W;
            int Nd;
            if (slot < 3)      { W = W1 + (size_t)slot * 32768;         Nd = 256; }
            else if (slot < 6) { W = W2 + (size_t)(slot - 3) * 32768;   Nd = 128; }
            else if (slot < 8) { W = vnW1 + (size_t)(slot - 6) * 32768; Nd = 256; }
            else               { W = vnW2 + (size_t)(slot - 8) * 32768; Nd = 128; }
            int Kd = 32768 / Nd;
            int k = r / Nd, nn = r % Nd;
            unsigned short hi, lo;
            split_f16(W[r], hi, lo);
            size_t o = (size_t)slot * 32768 + (size_t)nn * Kd + k;
            Bhi[o] = __ushort_as_half(hi);
            Blo[o] = __ushort_as_half(lo);
        }
    } else if (blk < c2) {
        int idx = (blk - c1) * 256 + tid;
        if (idx < LL * 1000 * 32) {
            int cc4 = (idx & 31) << 2;
            int i = (idx >> 5) % 1000;
            int l = (idx >> 5) / 1000;
            int f0 = i / 100, f1 = (i / 10) % 10, f2 = i % 10;
            float4 a = *(const float4*)(bond + ((size_t)(l * 3 + 0) * 10 + f0) * DD + cc4);
            float4 b = *(const float4*)(bond + ((size_t)(l * 3 + 1) * 10 + f1) * DD + cc4);
            float4 c = *(const float4*)(bond + ((size_t)(l * 3 + 2) * 10 + f2) * DD + cc4);
            float4 o;
            o.x = a.x + b.x + c.x; o.y = a.y + b.y + c.y;
            o.z = a.z + b.z + c.z; o.w = a.w + b.w + c.w;
            uint2 p;
            p.x = (uint32_t)f16u(o.x) | ((uint32_t)f16u(o.y) << 16);
            p.y = (uint32_t)f16u(o.z) | ((uint32_t)f16u(o.w) << 16);
            *(uint2*)(cb16 + ((size_t)(l * 1000 + i)) * DD + cc4) = p;
        }
    } else if (blk < c3) {
        int i = (blk - c2) * 256 + tid;
        if (i < n) cnt[i] = 0;
    } else if (blk < c4b) {
        int i = (blk - c3) * 256 + tid;
        if (i < GG * 32)
            *(float4*)(gsum + i * 4) = make_float4(0.f, 0.f, 0.f, 0.f);
    } else if (blk < c5) {
        int idx = (blk - c4b) * 256 + tid;
        if (idx < n * 32) {
            int node = idx >> 5;
            int cc4 = (idx & 31) << 2;
            float4 s = make_float4(0.f, 0.f, 0.f, 0.f);
#pragma unroll
            for (int f = 0; f < 9; f++) {
                int v = xa[node * 9 + f];
                float4 e = *(const float4*)(emb + (f * 100 + v) * DD + cc4);
                s.x += e.x; s.y += e.y; s.z += e.z; s.w += e.w;
            }
            *(float4*)(h + node * DD + cc4) = s;
        }
    } else {
        int idx = (blk - c5) * 256 + tid;
        if (idx < GG * 32) {
            int cc4 = (idx & 31) << 2;
            *(float4*)(vn + idx * 4) = *(const float4*)(v0 + cc4);
        }
    }
}

// ---------------------------------------------------------------------------
// CSR build
// ---------------------------------------------------------------------------
__global__ void count_k(const int* __restrict__ ei, int* __restrict__ cnt,
                        int* __restrict__ rank, int ecnt) {
    int j = (blockIdx.x * blockDim.x + threadIdx.x) * 4;
    if (j + 3 < ecnt) {
        int4 d = *(const int4*)(ei + ecnt + j);
        rank[j + 0] = atomicAdd(&cnt[d.x], 1);
        rank[j + 1] = atomicAdd(&cnt[d.y], 1);
        rank[j + 2] = atomicAdd(&cnt[d.z], 1);
        rank[j + 3] = atomicAdd(&cnt[d.w], 1);
    } else {
        for (int q = j; q < ecnt; q++)
            rank[q] = atomicAdd(&cnt[ei[ecnt + q]], 1);
    }
}
__global__ void scan_k(const int* __restrict__ cnt, int* __restrict__ off,
                       int n, int ecnt) {
    __shared__ int part[1024];
    int t = threadIdx.x;
    int chunk = (n + 1023) >> 10;
    int beg = t * chunk;
    int end = min(beg + chunk, n);
    int s = 0;
    for (int i = beg; i < end; i++) s += cnt[i];
    part[t] = s;
    __syncthreads();
    for (int d = 1; d < 1024; d <<= 1) {
        int v = (t >= d) ? part[t - d] : 0;
        __syncthreads();
        if (t >= d) part[t] += v;
        __syncthreads();
    }
    int run = (t == 0) ? 0 : part[t - 1];
    for (int i = beg; i < end; i++) {
        off[i] = run;
        run += cnt[i];
    }
    if (t == 0) off[n] = ecnt;
}
__global__ void scatter_k(const int* __restrict__ ei, const int* __restrict__ ea,
                          const int* __restrict__ off, const int* __restrict__ rank,
                          int2* __restrict__ csr, int ecnt) {
    int j = blockIdx.x * blockDim.x + threadIdx.x;
    if (j >= ecnt) return;
    int dst = ei[ecnt + j];
    int cm = ea[j * 3] * 100 + ea[j * 3 + 1] * 10 + ea[j * 3 + 2];
    csr[off[dst] + rank[j]] = make_int2(ei[j], cm);
}

// ---------------------------------------------------------------------------
// h += vn[batch]; write fp16 mirror; optionally gsum[batch] += h (post-update)
// ---------------------------------------------------------------------------
__global__ void add_vn_k(float* __restrict__ h, __half* __restrict__ h16,
                         const float* __restrict__ vn,
                         const int* __restrict__ batch,
                         float* __restrict__ gsum, int n, int dosum) {
    int idx = blockIdx.x * blockDim.x + threadIdx.x;
    if (idx >= n * 32) return;
    int node = idx >> 5;
    int c4 = (idx & 31) << 2;
    int g = batch[node];
    float4 hv = *(float4*)(h + idx * 4);
    float4 vv = *(const float4*)(vn + g * DD + c4);
    hv.x += vv.x; hv.y += vv.y; hv.z += vv.z; hv.w += vv.w;
    *(float4*)(h + idx * 4) = hv;
    uint2 p;
    p.x = (uint32_t)f16u(hv.x) | ((uint32_t)f16u(hv.y) << 16);
    p.y = (uint32_t)f16u(hv.z) | ((uint32_t)f16u(hv.w) << 16);
    *(uint2*)(h16 + idx * 4) = p;
    if (dosum) {
        float* p2 = gsum + g * DD + c4;
        asm volatile("red.global.add.v4.f32 [%0], {%1,%2,%3,%4};"
                     :: "l"(p2), "f"(hv.x), "f"(hv.y), "f"(hv.z), "f"(hv.w)
                     : "memory");
    }
}

// ---------------------------------------------------------------------------
// Edge gather (CSR, fp16 h16/cb16, half2 math), 4x unrolled.
// z = fp16( (1+eps)*h + sum relu2(h16[src] + cb16[combo]) )
// ---------------------------------------------------------------------------
__global__ void edge_csr_k(const int* __restrict__ off,
                           const int2* __restrict__ csr,
                           const __half* __restrict__ cb16,
                           const float* __restrict__ h,
                           const __half* __restrict__ h16,
                           const float* __restrict__ eps_p,
                           __half* __restrict__ zh, int n) {
    int warp = (blockIdx.x * blockDim.x + threadIdx.x) >> 5;
    if (warp >= n) return;
    int lane = threadIdx.x & 31;
    int c4 = lane << 2;
    float4 acc = make_float4(0.f, 0.f, 0.f, 0.f);
    int beg = off[warp], end = off[warp + 1];
    const unsigned FULL = 0xffffffffu;
    const __half2 z2 = __half2half2(__ushort_as_half(0));
#define EACC(HP, EP)                                                            \
    {                                                                           \
        __half2 r0_ = __hmax2(__hadd2(*(__half2*)&(HP).x, *(__half2*)&(EP).x), z2); \
        __half2 r1_ = __hmax2(__hadd2(*(__half2*)&(HP).y, *(__half2*)&(EP).y), z2); \
        float2 f0_ = __half22float2(r0_), f1_ = __half22float2(r1_);            \
        acc.x += f0_.x; acc.y += f0_.y; acc.z += f1_.x; acc.w += f1_.y;         \
    }
    for (int base = beg; base < end; base += 32) {
        int m = min(32, end - base);
        int s = 0, cm = 0;
        if (base + lane < end) {
            int2 e = csr[base + lane];
            s = e.x; cm = e.y;
        }
        int k = 0;
        for (; k + 4 <= m; k += 4) {
            int s0 = __shfl_sync(FULL, s, k),     c0 = __shfl_sync(FULL, cm, k);
            int s1 = __shfl_sync(FULL, s, k + 1), c1 = __shfl_sync(FULL, cm, k + 1);
            int s2 = __shfl_sync(FULL, s, k + 2), c2 = __shfl_sync(FULL, cm, k + 2);
            int s3 = __shfl_sync(FULL, s, k + 3), c3 = __shfl_sync(FULL, cm, k + 3);
            uint2 hp0 = *(const uint2*)(h16 + (size_t)s0 * DD + c4);
            uint2 ep0 = *(const uint2*)(cb16 + (size_t)c0 * DD + c4);
            uint2 hp1 = *(const uint2*)(h16 + (size_t)s1 * DD + c4);
            uint2 ep1 = *(const uint2*)(cb16 + (size_t)c1 * DD + c4);
            uint2 hp2 = *(const uint2*)(h16 + (size_t)s2 * DD + c4);
            uint2 ep2 = *(const uint2*)(cb16 + (size_t)c2 * DD + c4);
            uint2 hp3 = *(const uint2*)(h16 + (size_t)s3 * DD + c4);
            uint2 ep3 = *(const uint2*)(cb16 + (size_t)c3 * DD + c4);
            EACC(hp0, ep0) EACC(hp1, ep1) EACC(hp2, ep2) EACC(hp3, ep3)
        }
        for (; k < m; k++) {
            int ss = __shfl_sync(FULL, s, k);
            int cc = __shfl_sync(FULL, cm, k);
            uint2 hp = *(const uint2*)(h16 + (size_t)ss * DD + c4);
            uint2 ep = *(const uint2*)(cb16 + (size_t)cc * DD + c4);
            EACC(hp, ep)
        }
    }
#undef EACC
    float al = 1.0f + *eps_p;
    float4 hv = *(const float4*)(h + (size_t)warp * DD + c4);
    uint2 zp;
    zp.x = (uint32_t)f16u(al * hv.x + acc.x) |
           ((uint32_t)f16u(al * hv.y + acc.y) << 16);
    zp.y = (uint32_t)f16u(al * hv.z + acc.z) |
           ((uint32_t)f16u(al * hv.w + acc.w) << 16);
    *(uint2*)(zh + (size_t)warp * DD + c4) = zp;
}

// ---------------------------------------------------------------------------
// Persistent unified GEMM, fp16 A single limb; B hi (+ optional lo limb):
//   D = A @ Bhi [+ A @ Blo]   (Blo == nullptr -> single-limb weights)
// cp.async 2-stage, BK=32, vn rider tiles. Stage = 20 KB.
// ---------------------------------------------------------------------------
#define ASTR 40
#define STG_A    0
#define STG_B_HI 10240
#define STG_B_LO 15360
#define STG_SZ   20480
#define SM_TOT   40960

__global__ void __launch_bounds__(256, 2)
gemm_uni_k(int gx0, int ny0, int M0,
           const __half* __restrict__ A0h,
           const __half* __restrict__ B0hi, const __half* __restrict__ B0lo,
           const float* __restrict__ lb0, const float* __restrict__ g0,
           const float* __restrict__ be0, const float* __restrict__ m0,
           const float* __restrict__ vv0,
           float* __restrict__ C0f, __half* __restrict__ C0h,
           int gx1, int ny1, int M1,
           const float* __restrict__ A1f, const float* __restrict__ A1f2,
           const __half* __restrict__ A1h,
           const __half* __restrict__ B1hi, const __half* __restrict__ B1lo,
           const float* __restrict__ lb1, const float* __restrict__ g1,
           const float* __restrict__ be1, const float* __restrict__ m1,
           const float* __restrict__ vv1,
           float* __restrict__ C1f, __half* __restrict__ C1h,
           float4* __restrict__ zbuf, int zcnt4,
           int N, int K, int do_relu) {
    extern __shared__ char dsm[];
    __shared__ float s_sc[64], s_sb[64];

    int tid = threadIdx.x;
    int lane = tid & 31, wid = tid >> 5;
    uint32_t smbase = cvta_s(dsm);

    if (zbuf) {
        for (int i = blockIdx.x * 256 + tid; i < zcnt4; i += gridDim.x * 256)
            zbuf[i] = make_float4(0.f, 0.f, 0.f, 0.f);
    }

    int ntile0 = gx0 * ny0;
    int total = ntile0 + gx1 * ny1;

    int wm = (wid >> 1) * 32;
    int wn = (wid & 1) * 32;
    int r8 = lane & 7, g = lane >> 3;
    int acolg = (g >> 1) << 3;
    int bcolg = (g & 1) << 3;
    int nch = K >> 5;

    for (int tile = blockIdx.x; tile < total; tile += gridDim.x) {
        int part = 0, bx, by;
        int q = tile;
        if (q < ntile0) { bx = q / ny0; by = q % ny0; }
        else { part = 1; q -= ntile0; bx = q / ny1; by = q % ny1; }

        int M = part ? M1 : M0;
        const __half* Ah = part ? A1h : A0h;
        const __half* Bh = part ? B1hi : B0hi;
        const __half* Bl = part ? B1lo : B0lo;
        const float* lb = part ? lb1 : lb0;
        const float* gg = part ? g1 : g0;
        const float* bbp = part ? be1 : be0;
        const float* mmp = part ? m1 : m0;
        const float* vvp = part ? vv1 : vv0;
        float* Cf = part ? C1f : C0f;
        __half* Ch = part ? C1h : C0h;
        const float* Af  = part ? A1f  : (const float*)0;
        const float* Af2 = part ? A1f2 : (const float*)0;
        bool fp32A = (part && Af);
        bool useLo = (Bl != (const __half*)0);

        int bm = bx * 128;
        int bn = by * 64;

        __syncthreads();   // guard s_sc reuse vs previous tile's epilogue
        if (tid < 64) {
            int col = bn + tid;
            float s = gg[col] * rsqrtf(vvp[col] + 1e-5f);
            s_sc[tid] = s;
            s_sb[tid] = (lb[col] - mmp[col]) * s + bbp[col];
        }

        float acc[2][4][4];
#pragma unroll
        for (int a = 0; a < 2; a++)
#pragma unroll
            for (int b = 0; b < 4; b++)
#pragma unroll
                for (int qq = 0; qq < 4; qq++) acc[a][b][qq] = 0.f;

        int arow = wm + ((g & 1) << 3) + r8;
        int brow = wn + ((g >> 1) << 3) + r8;

        auto issue_async = [&](int ch, int stg) {
            int cc = ch << 5;
            uint32_t sb = smbase + stg * STG_SZ;
#pragma unroll
            for (int it = 0; it < 2; it++) {
                int i = tid + it * 256;
                int row = i >> 2, c8 = (i & 3) << 3;
                int sz = (bm + row < M) ? 16 : 0;
                const __half* sa = Ah + (size_t)(bm + row) * K + cc + c8;
                uint32_t doff = (uint32_t)(row * ASTR + c8) * 2;
                CP_ASYNC16(sb + STG_A + doff, sa, sz);
            }
            {
                int row = tid >> 2, c8 = (tid & 3) << 3;
                const __half* sh = Bh + (size_t)(bn + row) * K + cc + c8;
                uint32_t doff = (uint32_t)(row * ASTR + c8) * 2;
                CP_ASYNC16(sb + STG_B_HI + doff, sh, 16);
                if (useLo) {
                    const __half* sl = Bl + (size_t)(bn + row) * K + cc + c8;
                    CP_ASYNC16(sb + STG_B_LO + doff, sl, 16);
                }
            }
        };
        auto issue_sync = [&](int ch, int stg) {
            int cc = ch << 5;
            char* sb = dsm + stg * STG_SZ;
#pragma unroll
            for (int it = 0; it < 4; it++) {
                int i = tid + it * 256;
                int row = i >> 3, c4 = (i & 7) << 2;
                float4 v = make_float4(0.f, 0.f, 0.f, 0.f);
                if (bm + row < M) {
                    v = *(const float4*)(Af + (size_t)(bm + row) * K + cc + c4);
                    float4 w = *(const float4*)(Af2 + (size_t)(bm + row) * K + cc + c4);
                    v.x += w.x; v.y += w.y; v.z += w.z; v.w += w.w;
                }
                uint2 p;
                p.x = (uint32_t)f16u(v.x) | ((uint32_t)f16u(v.y) << 16);
                p.y = (uint32_t)f16u(v.z) | ((uint32_t)f16u(v.w) << 16);
                *(uint2*)(sb + STG_A + (row * ASTR + c4) * 2) = p;
            }
            {
                int row = tid >> 2, c8 = (tid & 3) << 3;
                uint4 vh = *(const uint4*)(Bh + (size_t)(bn + row) * K + cc + c8);
                int off = (row * ASTR + c8) * 2;
                *(uint4*)(sb + STG_B_HI + off) = vh;
                if (useLo) {
                    uint4 vl = *(const uint4*)(Bl + (size_t)(bn + row) * K + cc + c8);
                    *(uint4*)(sb + STG_B_LO + off) = vl;
                }
            }
        };

        if (fp32A) issue_sync(0, 0);
        else       issue_async(0, 0);
        CP_COMMIT();

        for (int ch = 0; ch < nch; ch++) {
            if (ch + 1 < nch) {
                if (fp32A) issue_sync(ch + 1, (ch + 1) & 1);
                else       issue_async(ch + 1, (ch + 1) & 1);
            }
            CP_COMMIT();
            CP_WAIT1();
            __syncthreads();

            uint32_t sb = smbase + (ch & 1) * STG_SZ;
#pragma unroll
            for (int ks = 0; ks < 2; ks++) {
                int kk = ks << 4;
                uint32_t a0, a1, a2, a3, a4, a5, a6, a7;
                uint32_t bh0, bh1, bh2, bh3, bh4, bh5, bh6, bh7;
                {
                    uint32_t ad0 = sb + STG_A + ((arow) * ASTR + kk + acolg) * 2;
                    uint32_t ad1 = sb + STG_A + ((arow + 16) * ASTR + kk + acolg) * 2;
                    LDSM_X4(a0, a1, a2, a3, ad0);
                    LDSM_X4(a4, a5, a6, a7, ad1);
                    uint32_t bd0 = sb + STG_B_HI + ((brow) * ASTR + kk + bcolg) * 2;
                    uint32_t bd1 = sb + STG_B_HI + ((brow + 16) * ASTR + kk + bcolg) * 2;
                    LDSM_X4(bh0, bh1, bh2, bh3, bd0);
                    LDSM_X4(bh4, bh5, bh6, bh7, bd1);
                }
                // hi-limb MMAs
                MMA_F16(acc[0][0][0], acc[0][0][1], acc[0][0][2], acc[0][0][3],
                        a0, a1, a2, a3, bh0, bh1);
                MMA_F16(acc[0][1][0], acc[0][1][1], acc[0][1][2], acc[0][1][3],
                        a0, a1, a2, a3, bh2, bh3);
                MMA_F16(acc[0][2][0], acc[0][2][1], acc[0][2][2], acc[0][2][3],
                        a0, a1, a2, a3, bh4, bh5);
                MMA_F16(acc[0][3][0], acc[0][3][1], acc[0][3][2], acc[0][3][3],
                        a0, a1, a2, a3, bh6, bh7);
                MMA_F16(acc[1][0][0], acc[1][0][1], acc[1][0][2], acc[1][0][3],
                        a4, a5, a6, a7, bh0, bh1);
                MMA_F16(acc[1][1][0], acc[1][1][1], acc[1][1][2], acc[1][1][3],
                        a4, a5, a6, a7, bh2, bh3);
                MMA_F16(acc[1][2][0], acc[1][2][1], acc[1][2][2], acc[1][2][3],
                        a4, a5, a6, a7, bh4, bh5);
                MMA_F16(acc[1][3][0], acc[1][3][1], acc[1][3][2], acc[1][3][3],
                        a4, a5, a6, a7, bh6, bh7);
                if (useLo) {
                    uint32_t bl0, bl1, bl2, bl3, bl4, bl5, bl6, bl7;
                    uint32_t bd0 = sb + STG_B_LO + ((brow) * ASTR + kk + bcolg) * 2;
                    uint32_t bd1 = sb + STG_B_LO + ((brow + 16) * ASTR + kk + bcolg) * 2;
                    LDSM_X4(bl0, bl1, bl2, bl3, bd0);
                    LDSM_X4(bl4, bl5, bl6, bl7, bd1);
                    MMA_F16(acc[0][0][0], acc[0][0][1], acc[0][0][2], acc[0][0][3],
                            a0, a1, a2, a3, bl0, bl1);
                    MMA_F16(acc[0][1][0], acc[0][1][1], acc[0][1][2], acc[0][1][3],
                            a0, a1, a2, a3, bl2, bl3);
                    MMA_F16(acc[0][2][0], acc[0][2][1], acc[0][2][2], acc[0][2][3],
                            a0, a1, a2, a3, bl4, bl5);
                    MMA_F16(acc[0][3][0], acc[0][3][1], acc[0][3][2], acc[0][3][3],
                            a0, a1, a2, a3, bl6, bl7);
                    MMA_F16(acc[1][0][0], acc[1][0][1], acc[1][0][2], acc[1][0][3],
                            a4, a5, a6, a7, bl0, bl1);
                    MMA_F16(acc[1][1][0], acc[1][1][1], acc[1][1][2], acc[1][1][3],
                            a4, a5, a6, a7, bl2, bl3);
                    MMA_F16(acc[1][2][0], acc[1][2][1], acc[1][2][2], acc[1][2][3],
                            a4, a5, a6, a7, bl4, bl5);
                    MMA_F16(acc[1][3][0], acc[1][3][1], acc[1][3][2], acc[1][3][3],
                            a4, a5, a6, a7, bl6, bl7);
                }
            }
            __syncthreads();
        }

        // ---- epilogue
        int rq = lane >> 2, cq = (lane & 3) * 2;
        bool outF16 = (Ch != (__half*)0);
#pragma unroll
        for (int mt = 0; mt < 2; mt++) {
            int r0 = bm + wm + mt * 16 + rq;
#pragma unroll
            for (int nt = 0; nt < 4; nt++) {
                int c0 = wn + nt * 8 + cq;
                float s0 = s_sc[c0], s1 = s_sc[c0 + 1];
                float t0 = s_sb[c0], t1 = s_sb[c0 + 1];
                float v0 = acc[mt][nt][0] * s0 + t0;
                float v1 = acc[mt][nt][1] * s1 + t1;
                float v2 = acc[mt][nt][2] * s0 + t0;
                float v3 = acc[mt][nt][3] * s1 + t1;
                if (do_relu) {
                    v0 = fmaxf(v0, 0.f); v1 = fmaxf(v1, 0.f);
                    v2 = fmaxf(v2, 0.f); v3 = fmaxf(v3, 0.f);
                }
                if (outF16) {
                    if (r0 < M)
                        *(uint32_t*)(Ch + (size_t)r0 * N + bn + c0) =
                            (uint32_t)f16u(v0) | ((uint32_t)f16u(v1) << 16);
                    if (r0 + 8 < M)
                        *(uint32_t*)(Ch + (size_t)(r0 + 8) * N + bn + c0) =
                            (uint32_t)f16u(v2) | ((uint32_t)f16u(v3) << 16);
                } else {
                    if (r0 < M)
                        *(float2*)(Cf + (size_t)r0 * N + bn + c0) = make_float2(v0, v1);
                    if (r0 + 8 < M)
                        *(float2*)(Cf + (size_t)(r0 + 8) * N + bn + c0) = make_float2(v2, v3);
                }
            }
        }
    }
}

// ---------------------------------------------------------------------------
// Host driver
// ---------------------------------------------------------------------------
extern "C" void kernel_launch(void* const* d_in, const int* in_sizes, int n_in,
                              void* d_out, int out_size) {
    const int*   x_atom  = (const int*)d_in[0];
    const int*   ei      = (const int*)d_in[1];
    const int*   ea      = (const int*)d_in[2];
    const int*   batch   = (const int*)d_in[3];
    const float* atomemb = (const float*)d_in[4];
    const float* vn0     = (const float*)d_in[5];
    const float* bond    = (const float*)d_in[6];
    const float* eps     = (const float*)d_in[7];
    const float* W1      = (const float*)d_in[8];
    const float* b1v     = (const float*)d_in[9];
    const float* bn1g    = (const float*)d_in[10];
    const float* bn1b    = (const float*)d_in[11];
    const float* bn1m    = (const float*)d_in[12];
    const float* bn1v    = (const float*)d_in[13];
    const float* W2      = (const float*)d_in[14];
    const float* b2v     = (const float*)d_in[15];
    const float* bng     = (const float*)d_in[16];
    const float* bnb     = (const float*)d_in[17];
    const float* bnm     = (const float*)d_in[18];
    const float* bnv     = (const float*)d_in[19];
    const float* vnW1    = (const float*)d_in[20];
    const float* vnb1    = (const float*)d_in[21];
    const float* vbn1g   = (const float*)d_in[22];
    const float* vbn1b   = (const float*)d_in[23];
    const float* vbn1m   = (const float*)d_in[24];
    const float* vbn1v   = (const float*)d_in[25];
    const float* vnW2    = (const float*)d_in[26];
    const float* vnb2    = (const float*)d_in[27];
    const float* vbn2g   = (const float*)d_in[28];
    const float* vbn2b   = (const float*)d_in[29];
    const float* vbn2m   = (const float*)d_in[30];
    const float* vbn2v   = (const float*)d_in[31];

    int n = in_sizes[3];
    int ecnt = in_sizes[1] / 2;

    float *h, *vn, *gsum;
    __half *h16, *zh, *th, *vth, *cb16, *Bhi, *Blo;
    int *cnt, *off, *rank;
    int2* csr;
    cudaGetSymbolAddress((void**)&h, g_h);
    cudaGetSymbolAddress((void**)&h16, g_h16);
    cudaGetSymbolAddress((void**)&zh, g_zh);
    cudaGetSymbolAddress((void**)&th, g_th);
    cudaGetSymbolAddress((void**)&vn, g_vn);
    cudaGetSymbolAddress((void**)&gsum, g_gsum);
    cudaGetSymbolAddress((void**)&vth, g_vth);
    cudaGetSymbolAddress((void**)&cb16, g_cb16);
    cudaGetSymbolAddress((void**)&cnt, g_cnt);
    cudaGetSymbolAddress((void**)&off, g_off);
    cudaGetSymbolAddress((void**)&rank, g_rank);
    cudaGetSymbolAddress((void**)&csr, g_csr);
    cudaGetSymbolAddress((void**)&Bhi, g_Bhi);
    cudaGetSymbolAddress((void**)&Blo, g_Blo);

    cudaFuncSetAttribute(gemm_uni_k, cudaFuncAttributeMaxDynamicSharedMemorySize,
                         SM_TOT);

    const int WSLOT = 32768;
    int gridND = (n * 32 + 255) / 256;

    int c1 = (10 * 32768 + 255) / 256;
    int c2 = c1 + (LL * 1000 * 32 + 255) / 256;
    int c3 = c2 + (n + 255) / 256;
    int c4b = c3 + (GG * 32 + 255) / 256;
    int c5 = c4b + gridND;
    int c6 = c5 + (GG * 32 + 255) / 256;
    fused_pre_k<<<c6, 256>>>(W1, W2, vnW1, vnW2, Bhi, Blo, bond, cb16,
                             cnt, gsum, x_atom, atomemb, h, vn0, vn,
                             n, c1, c2, c3, c4b, c5);
    count_k<<<(ecnt / 4 + 255) / 256, 256>>>(ei, cnt, rank, ecnt);
    scan_k<<<1, 1024>>>(cnt, off, n, ecnt);
    scatter_k<<<(ecnt + 255) / 256, 256>>>(ei, ea, off, rank, csr, ecnt);

    int gridM = (n + 127) / 128;
    int gxv = GG / 128;
    const int PERSIST = 296;   // 148 SMs x 2 CTAs
    for (int l = 0; l < LL; l++) {
        int hasVN = (l < LL - 1) ? 1 : 0;
        add_vn_k<<<gridND, 256>>>(h, h16, vn, batch, gsum, n, hasVN);
        edge_csr_k<<<gridND, 256>>>(off, csr, cb16 + (size_t)l * 1000 * DD,
                                    h, h16, eps + l, zh, n);
        {
            // GEMM1: single-limb W1 (Blo = nullptr); vn rider keeps 2 limbs.
            int ny0 = 4, ny1 = 4;
            int gx1 = hasVN ? gxv : 0;
            int total = gridM * ny0 + gx1 * ny1;
            int grid = total < PERSIST ? total : PERSIST;
            gemm_uni_k<<<grid, 256, SM_TOT>>>(
                gridM, ny0, n,
                zh,
                Bhi + (size_t)l * WSLOT, nullptr,
                b1v + l * 256, bn1g + l * 256, bn1b + l * 256,
                bn1m + l * 256, bn1v + l * 256,
                nullptr, th,
                gx1, ny1, hasVN ? GG : 0,
                vn, gsum, nullptr,
                Bhi + (size_t)(6 + l) * WSLOT, Blo + (size_t)(6 + l) * WSLOT,
                vnb1 + l * 256, vbn1g + l * 256, vbn1b + l * 256,
                vbn1m + l * 256, vbn1v + l * 256,
                nullptr, vth,
                nullptr, 0,
                256, 128, 1);
        }
        {
            float* outp = (l == LL - 1) ? (float*)d_out : h;
            int ny0 = 2, ny1 = 2;
            int gx1 = hasVN ? gxv : 0;
            int total = gridM * ny0 + gx1 * ny1;
            int grid = total < PERSIST ? total : PERSIST;
            gemm_uni_k<<<grid, 256, SM_TOT>>>(
                gridM, ny0, n,
                th,
                Bhi + (size_t)(3 + l) * WSLOT, Blo + (size_t)(3 + l) * WSLOT,
                b2v + l * 128, bng + l * 128, bnb + l * 128,
                bnm + l * 128, bnv + l * 128,
                outp, nullptr,
                gx1, ny1, hasVN ? GG : 0,
                nullptr, nullptr, vth,
                Bhi + (size_t)(8 + l) * WSLOT, Blo + (size_t)(8 + l) * WSLOT,
                vnb2 + l * 128, vbn2g + l * 128, vbn2b + l * 128,
                vbn2m + l * 128, vbn2v + l * 128,
                vn, nullptr,
                (l == 0) ? (float4*)gsum : nullptr, GG * 32,
                128, 256, hasVN);
        }
    }
}

// round 17
// speedup vs baseline: 1.6227x; 1.0585x over previous
#include <cuda_runtime.h>
#include <cuda_fp16.h>
#include <cstdint>

#define MAXN 50000
#define MAXE 800000
#define GG   1024
#define DD   128
#define LL   3

// ---------------------------------------------------------------------------
// Static scratch
// ---------------------------------------------------------------------------
__device__ float g_h[MAXN * DD];
__device__ __half g_h16[MAXN * DD];           // fp16 mirror of h (edge gather)
__device__ __half g_zh[MAXN * DD];            // GIN input z, fp16
__device__ __half g_th[MAXN * 2 * DD];        // MLP hidden t, fp16
__device__ float g_vn[GG * DD];
__device__ float g_gsum[GG * DD];
__device__ __half g_vth[GG * 2 * DD];         // vn hidden, fp16
__device__ __half g_cb16[LL * 1000 * DD];     // combined bond table, fp16
__device__ int   g_cnt[MAXN];
__device__ int   g_off[MAXN + 1];
__device__ int   g_rank[MAXE];
__device__ int2  g_csr[MAXE];                  // packed {src, combo}
// Preconverted weights: B^T [N][K] fp16 hi/lo limbs. 10 slots of 32768:
// W1 l0..2, W2 l0..2, vn1 l0..1, vn2 l0..1
__device__ __half g_Bhi[10 * 32768];
__device__ __half g_Blo[10 * 32768];

// ---------------------------------------------------------------------------
// PTX helpers
// ---------------------------------------------------------------------------
__device__ __forceinline__ uint32_t cvta_s(const void* p) {
    uint32_t a;
    asm("{ .reg .u64 t; cvta.to.shared.u64 t, %1; cvt.u32.u64 %0, t; }"
        : "=r"(a) : "l"(p));
    return a;
}
#define LDSM_X4(r0, r1, r2, r3, addr)                                          \
    asm volatile("ldmatrix.sync.aligned.m8n8.x4.shared.b16 {%0,%1,%2,%3}, [%4];"\
                 : "=r"(r0), "=r"(r1), "=r"(r2), "=r"(r3) : "r"(addr))
#define MMA_F16(d0, d1, d2, d3, a0, a1, a2, a3, b0, b1)                        \
    asm volatile("mma.sync.aligned.m16n8k16.row.col.f32.f16.f16.f32 "          \
                 "{%0,%1,%2,%3}, {%4,%5,%6,%7}, {%8,%9}, {%0,%1,%2,%3};"       \
                 : "+f"(d0), "+f"(d1), "+f"(d2), "+f"(d3)                      \
                 : "r"(a0), "r"(a1), "r"(a2), "r"(a3), "r"(b0), "r"(b1))
#define CP_ASYNC16(dst, src, sz)                                               \
    asm volatile("cp.async.cg.shared.global [%0], [%1], 16, %2;"               \
                 :: "r"(dst), "l"(src), "r"(sz))
#define CP_COMMIT() asm volatile("cp.async.commit_group;" ::: "memory")
#define CP_WAIT1()  asm volatile("cp.async.wait_group 1;" ::: "memory")

__device__ __forceinline__ void split_f16(float v, unsigned short& hi,
                                          unsigned short& lo) {
    __half h = __float2half_rn(v);
    hi = __half_as_ushort(h);
    lo = __half_as_ushort(__float2half_rn(v - __half2float(h)));
}
__device__ __forceinline__ unsigned short f16u(float v) {
    return __half_as_ushort(__float2half_rn(v));
}

// ---------------------------------------------------------------------------
// Mega-fused preprocessing (weights + combo table + zeros + atom + vn init)
// ---------------------------------------------------------------------------
__global__ void fused_pre_k(
    const float* __restrict__ W1, const float* __restrict__ W2,
    const float* __restrict__ vnW1, const float* __restrict__ vnW2,
    __half* __restrict__ Bhi, __half* __restrict__ Blo,
    const float* __restrict__ bond, __half* __restrict__ cb16,
    int* __restrict__ cnt, float* __restrict__ gsum,
    const int* __restrict__ xa, const float* __restrict__ emb,
    float* __restrict__ h,
    const float* __restrict__ v0, float* __restrict__ vn,
    int n, int c1, int c2, int c3, int c4b, int c5) {
    int blk = blockIdx.x;
    int tid = threadIdx.x;
    if (blk < c1) {
        int idx = blk * 256 + tid;
        if (idx < 10 * 32768) {
            int slot = idx >> 15;
            int r = idx & 32767;
            const float* W;
            int Nd;
            if (slot < 3)      { W = W1 + (size_t)slot * 32768;         Nd = 256; }
            else if (slot < 6) { W = W2 + (size_t)(slot - 3) * 32768;   Nd = 128; }
            else if (slot < 8) { W = vnW1 + (size_t)(slot - 6) * 32768; Nd = 256; }
            else               { W = vnW2 + (size_t)(slot - 8) * 32768; Nd = 128; }
            int Kd = 32768 / Nd;
            int k = r / Nd, nn = r % Nd;
            unsigned short hi, lo;
            split_f16(W[r], hi, lo);
            size_t o = (size_t)slot * 32768 + (size_t)nn * Kd + k;
            Bhi[o] = __ushort_as_half(hi);
            Blo[o] = __ushort_as_half(lo);
        }
    } else if (blk < c2) {
        int idx = (blk - c1) * 256 + tid;
        if (idx < LL * 1000 * 32) {
            int cc4 = (idx & 31) << 2;
            int i = (idx >> 5) % 1000;
            int l = (idx >> 5) / 1000;
            int f0 = i / 100, f1 = (i / 10) % 10, f2 = i % 10;
            float4 a = *(const float4*)(bond + ((size_t)(l * 3 + 0) * 10 + f0) * DD + cc4);
            float4 b = *(const float4*)(bond + ((size_t)(l * 3 + 1) * 10 + f1) * DD + cc4);
            float4 c = *(const float4*)(bond + ((size_t)(l * 3 + 2) * 10 + f2) * DD + cc4);
            float4 o;
            o.x = a.x + b.x + c.x; o.y = a.y + b.y + c.y;
            o.z = a.z + b.z + c.z; o.w = a.w + b.w + c.w;
            uint2 p;
            p.x = (uint32_t)f16u(o.x) | ((uint32_t)f16u(o.y) << 16);
            p.y = (uint32_t)f16u(o.z) | ((uint32_t)f16u(o.w) << 16);
            *(uint2*)(cb16 + ((size_t)(l * 1000 + i)) * DD + cc4) = p;
        }
    } else if (blk < c3) {
        int i = (blk - c2) * 256 + tid;
        if (i < n) cnt[i] = 0;
    } else if (blk < c4b) {
        int i = (blk - c3) * 256 + tid;
        if (i < GG * 32)
            *(float4*)(gsum + i * 4) = make_float4(0.f, 0.f, 0.f, 0.f);
    } else if (blk < c5) {
        int idx = (blk - c4b) * 256 + tid;
        if (idx < n * 32) {
            int node = idx >> 5;
            int cc4 = (idx & 31) << 2;
            float4 s = make_float4(0.f, 0.f, 0.f, 0.f);
#pragma unroll
            for (int f = 0; f < 9; f++) {
                int v = xa[node * 9 + f];
                float4 e = *(const float4*)(emb + (f * 100 + v) * DD + cc4);
                s.x += e.x; s.y += e.y; s.z += e.z; s.w += e.w;
            }
            *(float4*)(h + node * DD + cc4) = s;
        }
    } else {
        int idx = (blk - c5) * 256 + tid;
        if (idx < GG * 32) {
            int cc4 = (idx & 31) << 2;
            *(float4*)(vn + idx * 4) = *(const float4*)(v0 + cc4);
        }
    }
}

// ---------------------------------------------------------------------------
// CSR build
// ---------------------------------------------------------------------------
__global__ void count_k(const int* __restrict__ ei, int* __restrict__ cnt,
                        int* __restrict__ rank, int ecnt) {
    int j = (blockIdx.x * blockDim.x + threadIdx.x) * 4;
    if (j + 3 < ecnt) {
        int4 d = *(const int4*)(ei + ecnt + j);
        rank[j + 0] = atomicAdd(&cnt[d.x], 1);
        rank[j + 1] = atomicAdd(&cnt[d.y], 1);
        rank[j + 2] = atomicAdd(&cnt[d.z], 1);
        rank[j + 3] = atomicAdd(&cnt[d.w], 1);
    } else {
        for (int q = j; q < ecnt; q++)
            rank[q] = atomicAdd(&cnt[ei[ecnt + q]], 1);
    }
}
__global__ void scan_k(const int* __restrict__ cnt, int* __restrict__ off,
                       int n, int ecnt) {
    __shared__ int part[1024];
    int t = threadIdx.x;
    int chunk = (n + 1023) >> 10;
    int beg = t * chunk;
    int end = min(beg + chunk, n);
    int s = 0;
    for (int i = beg; i < end; i++) s += cnt[i];
    part[t] = s;
    __syncthreads();
    for (int d = 1; d < 1024; d <<= 1) {
        int v = (t >= d) ? part[t - d] : 0;
        __syncthreads();
        if (t >= d) part[t] += v;
        __syncthreads();
    }
    int run = (t == 0) ? 0 : part[t - 1];
    for (int i = beg; i < end; i++) {
        off[i] = run;
        run += cnt[i];
    }
    if (t == 0) off[n] = ecnt;
}
__global__ void scatter_k(const int* __restrict__ ei, const int* __restrict__ ea,
                          const int* __restrict__ off, const int* __restrict__ rank,
                          int2* __restrict__ csr, int ecnt) {
    int j = blockIdx.x * blockDim.x + threadIdx.x;
    if (j >= ecnt) return;
    int dst = ei[ecnt + j];
    int cm = ea[j * 3] * 100 + ea[j * 3 + 1] * 10 + ea[j * 3 + 2];
    csr[off[dst] + rank[j]] = make_int2(ei[j], cm);
}

// ---------------------------------------------------------------------------
// h += vn[batch]; write fp16 mirror; optionally gsum[batch] += h (post-update)
// ---------------------------------------------------------------------------
__global__ void add_vn_k(float* __restrict__ h, __half* __restrict__ h16,
                         const float* __restrict__ vn,
                         const int* __restrict__ batch,
                         float* __restrict__ gsum, int n, int dosum) {
    int idx = blockIdx.x * blockDim.x + threadIdx.x;
    if (idx >= n * 32) return;
    int node = idx >> 5;
    int c4 = (idx & 31) << 2;
    int g = batch[node];
    float4 hv = *(float4*)(h + idx * 4);
    float4 vv = *(const float4*)(vn + g * DD + c4);
    hv.x += vv.x; hv.y += vv.y; hv.z += vv.z; hv.w += vv.w;
    *(float4*)(h + idx * 4) = hv;
    uint2 p;
    p.x = (uint32_t)f16u(hv.x) | ((uint32_t)f16u(hv.y) << 16);
    p.y = (uint32_t)f16u(hv.z) | ((uint32_t)f16u(hv.w) << 16);
    *(uint2*)(h16 + idx * 4) = p;
    if (dosum) {
        float* p2 = gsum + g * DD + c4;
        asm volatile("red.global.add.v4.f32 [%0], {%1,%2,%3,%4};"
                     :: "l"(p2), "f"(hv.x), "f"(hv.y), "f"(hv.z), "f"(hv.w)
                     : "memory");
    }
}

// ---------------------------------------------------------------------------
// Edge gather (CSR, fp16 h16/cb16, half2 math), 4x unrolled.
// z = fp16( (1+eps)*h + sum relu2(h16[src] + cb16[combo]) )
// ---------------------------------------------------------------------------
__global__ void edge_csr_k(const int* __restrict__ off,
                           const int2* __restrict__ csr,
                           const __half* __restrict__ cb16,
                           const float* __restrict__ h,
                           const __half* __restrict__ h16,
                           const float* __restrict__ eps_p,
                           __half* __restrict__ zh, int n) {
    int warp = (blockIdx.x * blockDim.x + threadIdx.x) >> 5;
    if (warp >= n) return;
    int lane = threadIdx.x & 31;
    int c4 = lane << 2;
    float4 acc = make_float4(0.f, 0.f, 0.f, 0.f);
    int beg = off[warp], end = off[warp + 1];
    const unsigned FULL = 0xffffffffu;
    const __half2 z2 = __half2half2(__ushort_as_half(0));
#define EACC(HP, EP)                                                            \
    {                                                                           \
        __half2 r0_ = __hmax2(__hadd2(*(__half2*)&(HP).x, *(__half2*)&(EP).x), z2); \
        __half2 r1_ = __hmax2(__hadd2(*(__half2*)&(HP).y, *(__half2*)&(EP).y), z2); \
        float2 f0_ = __half22float2(r0_), f1_ = __half22float2(r1_);            \
        acc.x += f0_.x; acc.y += f0_.y; acc.z += f1_.x; acc.w += f1_.y;         \
    }
    for (int base = beg; base < end; base += 32) {
        int m = min(32, end - base);
        int s = 0, cm = 0;
        if (base + lane < end) {
            int2 e = csr[base + lane];
            s = e.x; cm = e.y;
        }
        int k = 0;
        for (; k + 4 <= m; k += 4) {
            int s0 = __shfl_sync(FULL, s, k),     c0 = __shfl_sync(FULL, cm, k);
            int s1 = __shfl_sync(FULL, s, k + 1), c1 = __shfl_sync(FULL, cm, k + 1);
            int s2 = __shfl_sync(FULL, s, k + 2), c2 = __shfl_sync(FULL, cm, k + 2);
            int s3 = __shfl_sync(FULL, s, k + 3), c3 = __shfl_sync(FULL, cm, k + 3);
            uint2 hp0 = *(const uint2*)(h16 + (size_t)s0 * DD + c4);
            uint2 ep0 = *(const uint2*)(cb16 + (size_t)c0 * DD + c4);
            uint2 hp1 = *(const uint2*)(h16 + (size_t)s1 * DD + c4);
            uint2 ep1 = *(const uint2*)(cb16 + (size_t)c1 * DD + c4);
            uint2 hp2 = *(const uint2*)(h16 + (size_t)s2 * DD + c4);
            uint2 ep2 = *(const uint2*)(cb16 + (size_t)c2 * DD + c4);
            uint2 hp3 = *(const uint2*)(h16 + (size_t)s3 * DD + c4);
            uint2 ep3 = *(const uint2*)(cb16 + (size_t)c3 * DD + c4);
            EACC(hp0, ep0) EACC(hp1, ep1) EACC(hp2, ep2) EACC(hp3, ep3)
        }
        for (; k < m; k++) {
            int ss = __shfl_sync(FULL, s, k);
            int cc = __shfl_sync(FULL, cm, k);
            uint2 hp = *(const uint2*)(h16 + (size_t)ss * DD + c4);
            uint2 ep = *(const uint2*)(cb16 + (size_t)cc * DD + c4);
            EACC(hp, ep)
        }
    }
#undef EACC
    float al = 1.0f + *eps_p;
    float4 hv = *(const float4*)(h + (size_t)warp * DD + c4);
    uint2 zp;
    zp.x = (uint32_t)f16u(al * hv.x + acc.x) |
           ((uint32_t)f16u(al * hv.y + acc.y) << 16);
    zp.y = (uint32_t)f16u(al * hv.z + acc.z) |
           ((uint32_t)f16u(al * hv.w + acc.w) << 16);
    *(uint2*)(zh + (size_t)warp * DD + c4) = zp;
}

// ---------------------------------------------------------------------------
// Persistent unified GEMM, fp16 A single limb; B hi (+ optional lo limb):
//   D = A @ Bhi [+ A @ Blo]   (Blo == nullptr -> single-limb weights)
// cp.async 2-stage, BK=32, vn rider tiles. Stage = 20 KB.
// ---------------------------------------------------------------------------
#define ASTR 40
#define STG_A    0
#define STG_B_HI 10240
#define STG_B_LO 15360
#define STG_SZ   20480
#define SM_TOT   40960

__global__ void __launch_bounds__(256, 2)
gemm_uni_k(int gx0, int ny0, int M0,
           const __half* __restrict__ A0h,
           const __half* __restrict__ B0hi, const __half* __restrict__ B0lo,
           const float* __restrict__ lb0, const float* __restrict__ g0,
           const float* __restrict__ be0, const float* __restrict__ m0,
           const float* __restrict__ vv0,
           float* __restrict__ C0f, __half* __restrict__ C0h,
           int gx1, int ny1, int M1,
           const float* __restrict__ A1f, const float* __restrict__ A1f2,
           const __half* __restrict__ A1h,
           const __half* __restrict__ B1hi, const __half* __restrict__ B1lo,
           const float* __restrict__ lb1, const float* __restrict__ g1,
           const float* __restrict__ be1, const float* __restrict__ m1,
           const float* __restrict__ vv1,
           float* __restrict__ C1f, __half* __restrict__ C1h,
           float4* __restrict__ zbuf, int zcnt4,
           int N, int K, int do_relu) {
    extern __shared__ char dsm[];
    __shared__ float s_sc[64], s_sb[64];

    int tid = threadIdx.x;
    int lane = tid & 31, wid = tid >> 5;
    uint32_t smbase = cvta_s(dsm);

    if (zbuf) {
        for (int i = blockIdx.x * 256 + tid; i < zcnt4; i += gridDim.x * 256)
            zbuf[i] = make_float4(0.f, 0.f, 0.f, 0.f);
    }

    int ntile0 = gx0 * ny0;
    int total = ntile0 + gx1 * ny1;

    int wm = (wid >> 1) * 32;
    int wn = (wid & 1) * 32;
    int r8 = lane & 7, g = lane >> 3;
    int acolg = (g >> 1) << 3;
    int bcolg = (g & 1) << 3;
    int nch = K >> 5;

    for (int tile = blockIdx.x; tile < total; tile += gridDim.x) {
        int part = 0, bx, by;
        int q = tile;
        if (q < ntile0) { bx = q / ny0; by = q % ny0; }
        else { part = 1; q -= ntile0; bx = q / ny1; by = q % ny1; }

        int M = part ? M1 : M0;
        const __half* Ah = part ? A1h : A0h;
        const __half* Bh = part ? B1hi : B0hi;
        const __half* Bl = part ? B1lo : B0lo;
        const float* lb = part ? lb1 : lb0;
        const float* gg = part ? g1 : g0;
        const float* bbp = part ? be1 : be0;
        const float* mmp = part ? m1 : m0;
        const float* vvp = part ? vv1 : vv0;
        float* Cf = part ? C1f : C0f;
        __half* Ch = part ? C1h : C0h;
        const float* Af  = part ? A1f  : (const float*)0;
        const float* Af2 = part ? A1f2 : (const float*)0;
        bool fp32A = (part && Af);
        bool useLo = (Bl != (const __half*)0);

        int bm = bx * 128;
        int bn = by * 64;

        __syncthreads();   // guard s_sc reuse vs previous tile's epilogue
        if (tid < 64) {
            int col = bn + tid;
            float s = gg[col] * rsqrtf(vvp[col] + 1e-5f);
            s_sc[tid] = s;
            s_sb[tid] = (lb[col] - mmp[col]) * s + bbp[col];
        }

        float acc[2][4][4];
#pragma unroll
        for (int a = 0; a < 2; a++)
#pragma unroll
            for (int b = 0; b < 4; b++)
#pragma unroll
                for (int qq = 0; qq < 4; qq++) acc[a][b][qq] = 0.f;

        int arow = wm + ((g & 1) << 3) + r8;
        int brow = wn + ((g >> 1) << 3) + r8;

        auto issue_async = [&](int ch, int stg) {
            int cc = ch << 5;
            uint32_t sb = smbase + stg * STG_SZ;
#pragma unroll
            for (int it = 0; it < 2; it++) {
                int i = tid + it * 256;
                int row = i >> 2, c8 = (i & 3) << 3;
                int sz = (bm + row < M) ? 16 : 0;
                const __half* sa = Ah + (size_t)(bm + row) * K + cc + c8;
                uint32_t doff = (uint32_t)(row * ASTR + c8) * 2;
                CP_ASYNC16(sb + STG_A + doff, sa, sz);
            }
            {
                int row = tid >> 2, c8 = (tid & 3) << 3;
                const __half* sh = Bh + (size_t)(bn + row) * K + cc + c8;
                uint32_t doff = (uint32_t)(row * ASTR + c8) * 2;
                CP_ASYNC16(sb + STG_B_HI + doff, sh, 16);
                if (useLo) {
                    const __half* sl = Bl + (size_t)(bn + row) * K + cc + c8;
                    CP_ASYNC16(sb + STG_B_LO + doff, sl, 16);
                }
            }
        };
        auto issue_sync = [&](int ch, int stg) {
            int cc = ch << 5;
            char* sb = dsm + stg * STG_SZ;
#pragma unroll
            for (int it = 0; it < 4; it++) {
                int i = tid + it * 256;
                int row = i >> 3, c4 = (i & 7) << 2;
                float4 v = make_float4(0.f, 0.f, 0.f, 0.f);
                if (bm + row < M) {
                    v = *(const float4*)(Af + (size_t)(bm + row) * K + cc + c4);
                    float4 w = *(const float4*)(Af2 + (size_t)(bm + row) * K + cc + c4);
                    v.x += w.x; v.y += w.y; v.z += w.z; v.w += w.w;
                }
                uint2 p;
                p.x = (uint32_t)f16u(v.x) | ((uint32_t)f16u(v.y) << 16);
                p.y = (uint32_t)f16u(v.z) | ((uint32_t)f16u(v.w) << 16);
                *(uint2*)(sb + STG_A + (row * ASTR + c4) * 2) = p;
            }
            {
                int row = tid >> 2, c8 = (tid & 3) << 3;
                uint4 vh = *(const uint4*)(Bh + (size_t)(bn + row) * K + cc + c8);
                int off = (row * ASTR + c8) * 2;
                *(uint4*)(sb + STG_B_HI + off) = vh;
                if (useLo) {
                    uint4 vl = *(const uint4*)(Bl + (size_t)(bn + row) * K + cc + c8);
                    *(uint4*)(sb + STG_B_LO + off) = vl;
                }
            }
        };

        if (fp32A) issue_sync(0, 0);
        else       issue_async(0, 0);
        CP_COMMIT();

        for (int ch = 0; ch < nch; ch++) {
            if (ch + 1 < nch) {
                if (fp32A) issue_sync(ch + 1, (ch + 1) & 1);
                else       issue_async(ch + 1, (ch + 1) & 1);
            }
            CP_COMMIT();
            CP_WAIT1();
            __syncthreads();

            uint32_t sb = smbase + (ch & 1) * STG_SZ;
#pragma unroll
            for (int ks = 0; ks < 2; ks++) {
                int kk = ks << 4;
                uint32_t a0, a1, a2, a3, a4, a5, a6, a7;
                uint32_t bh0, bh1, bh2, bh3, bh4, bh5, bh6, bh7;
                {
                    uint32_t ad0 = sb + STG_A + ((arow) * ASTR + kk + acolg) * 2;
                    uint32_t ad1 = sb + STG_A + ((arow + 16) * ASTR + kk + acolg) * 2;
                    LDSM_X4(a0, a1, a2, a3, ad0);
                    LDSM_X4(a4, a5, a6, a7, ad1);
                    uint32_t bd0 = sb + STG_B_HI + ((brow) * ASTR + kk + bcolg) * 2;
                    uint32_t bd1 = sb + STG_B_HI + ((brow + 16) * ASTR + kk + bcolg) * 2;
                    LDSM_X4(bh0, bh1, bh2, bh3, bd0);
                    LDSM_X4(bh4, bh5, bh6, bh7, bd1);
                }
                // hi-limb MMAs
                MMA_F16(acc[0][0][0], acc[0][0][1], acc[0][0][2], acc[0][0][3],
                        a0, a1, a2, a3, bh0, bh1);
                MMA_F16(acc[0][1][0], acc[0][1][1], acc[0][1][2], acc[0][1][3],
                        a0, a1, a2, a3, bh2, bh3);
                MMA_F16(acc[0][2][0], acc[0][2][1], acc[0][2][2], acc[0][2][3],
                        a0, a1, a2, a3, bh4, bh5);
                MMA_F16(acc[0][3][0], acc[0][3][1], acc[0][3][2], acc[0][3][3],
                        a0, a1, a2, a3, bh6, bh7);
                MMA_F16(acc[1][0][0], acc[1][0][1], acc[1][0][2], acc[1][0][3],
                        a4, a5, a6, a7, bh0, bh1);
                MMA_F16(acc[1][1][0], acc[1][1][1], acc[1][1][2], acc[1][1][3],
                        a4, a5, a6, a7, bh2, bh3);
                MMA_F16(acc[1][2][0], acc[1][2][1], acc[1][2][2], acc[1][2][3],
                        a4, a5, a6, a7, bh4, bh5);
                MMA_F16(acc[1][3][0], acc[1][3][1], acc[1][3][2], acc[1][3][3],
                        a4, a5, a6, a7, bh6, bh7);
                if (useLo) {
                    uint32_t bl0, bl1, bl2, bl3, bl4, bl5, bl6, bl7;
                    uint32_t bd0 = sb + STG_B_LO + ((brow) * ASTR + kk + bcolg) * 2;
                    uint32_t bd1 = sb + STG_B_LO + ((brow + 16) * ASTR + kk + bcolg) * 2;
                    LDSM_X4(bl0, bl1, bl2, bl3, bd0);
                    LDSM_X4(bl4, bl5, bl6, bl7, bd1);
                    MMA_F16(acc[0][0][0], acc[0][0][1], acc[0][0][2], acc[0][0][3],
                            a0, a1, a2, a3, bl0, bl1);
                    MMA_F16(acc[0][1][0], acc[0][1][1], acc[0][1][2], acc[0][1][3],
                            a0, a1, a2, a3, bl2, bl3);
                    MMA_F16(acc[0][2][0], acc[0][2][1], acc[0][2][2], acc[0][2][3],
                            a0, a1, a2, a3, bl4, bl5);
                    MMA_F16(acc[0][3][0], acc[0][3][1], acc[0][3][2], acc[0][3][3],
                            a0, a1, a2, a3, bl6, bl7);
                    MMA_F16(acc[1][0][0], acc[1][0][1], acc[1][0][2], acc[1][0][3],
                            a4, a5, a6, a7, bl0, bl1);
                    MMA_F16(acc[1][1][0], acc[1][1][1], acc[1][1][2], acc[1][1][3],
                            a4, a5, a6, a7, bl2, bl3);
                    MMA_F16(acc[1][2][0], acc[1][2][1], acc[1][2][2], acc[1][2][3],
                            a4, a5, a6, a7, bl4, bl5);
                    MMA_F16(acc[1][3][0], acc[1][3][1], acc[1][3][2], acc[1][3][3],
                            a4, a5, a6, a7, bl6, bl7);
                }
            }
            __syncthreads();
        }

        // ---- epilogue
        int rq = lane >> 2, cq = (lane & 3) * 2;
        bool outF16 = (Ch != (__half*)0);
#pragma unroll
        for (int mt = 0; mt < 2; mt++) {
            int r0 = bm + wm + mt * 16 + rq;
#pragma unroll
            for (int nt = 0; nt < 4; nt++) {
                int c0 = wn + nt * 8 + cq;
                float s0 = s_sc[c0], s1 = s_sc[c0 + 1];
                float t0 = s_sb[c0], t1 = s_sb[c0 + 1];
                float v0 = acc[mt][nt][0] * s0 + t0;
                float v1 = acc[mt][nt][1] * s1 + t1;
                float v2 = acc[mt][nt][2] * s0 + t0;
                float v3 = acc[mt][nt][3] * s1 + t1;
                if (do_relu) {
                    v0 = fmaxf(v0, 0.f); v1 = fmaxf(v1, 0.f);
                    v2 = fmaxf(v2, 0.f); v3 = fmaxf(v3, 0.f);
                }
                if (outF16) {
                    if (r0 < M)
                        *(uint32_t*)(Ch + (size_t)r0 * N + bn + c0) =
                            (uint32_t)f16u(v0) | ((uint32_t)f16u(v1) << 16);
                    if (r0 + 8 < M)
                        *(uint32_t*)(Ch + (size_t)(r0 + 8) * N + bn + c0) =
                            (uint32_t)f16u(v2) | ((uint32_t)f16u(v3) << 16);
                } else {
                    if (r0 < M)
                        *(float2*)(Cf + (size_t)r0 * N + bn + c0) = make_float2(v0, v1);
                    if (r0 + 8 < M)
                        *(float2*)(Cf + (size_t)(r0 + 8) * N + bn + c0) = make_float2(v2, v3);
                }
            }
        }
    }
}

// ---------------------------------------------------------------------------
// Host driver
// ---------------------------------------------------------------------------
extern "C" void kernel_launch(void* const* d_in, const int* in_sizes, int n_in,
                              void* d_out, int out_size) {
    const int*   x_atom  = (const int*)d_in[0];
    const int*   ei      = (const int*)d_in[1];
    const int*   ea      = (const int*)d_in[2];
    const int*   batch   = (const int*)d_in[3];
    const float* atomemb = (const float*)d_in[4];
    const float* vn0     = (const float*)d_in[5];
    const float* bond    = (const float*)d_in[6];
    const float* eps     = (const float*)d_in[7];
    const float* W1      = (const float*)d_in[8];
    const float* b1v     = (const float*)d_in[9];
    const float* bn1g    = (const float*)d_in[10];
    const float* bn1b    = (const float*)d_in[11];
    const float* bn1m    = (const float*)d_in[12];
    const float* bn1v    = (const float*)d_in[13];
    const float* W2      = (const float*)d_in[14];
    const float* b2v     = (const float*)d_in[15];
    const float* bng     = (const float*)d_in[16];
    const float* bnb     = (const float*)d_in[17];
    const float* bnm     = (const float*)d_in[18];
    const float* bnv     = (const float*)d_in[19];
    const float* vnW1    = (const float*)d_in[20];
    const float* vnb1    = (const float*)d_in[21];
    const float* vbn1g   = (const float*)d_in[22];
    const float* vbn1b   = (const float*)d_in[23];
    const float* vbn1m   = (const float*)d_in[24];
    const float* vbn1v   = (const float*)d_in[25];
    const float* vnW2    = (const float*)d_in[26];
    const float* vnb2    = (const float*)d_in[27];
    const float* vbn2g   = (const float*)d_in[28];
    const float* vbn2b   = (const float*)d_in[29];
    const float* vbn2m   = (const float*)d_in[30];
    const float* vbn2v   = (const float*)d_in[31];

    int n = in_sizes[3];
    int ecnt = in_sizes[1] / 2;

    float *h, *vn, *gsum;
    __half *h16, *zh, *th, *vth, *cb16, *Bhi, *Blo;
    int *cnt, *off, *rank;
    int2* csr;
    cudaGetSymbolAddress((void**)&h, g_h);
    cudaGetSymbolAddress((void**)&h16, g_h16);
    cudaGetSymbolAddress((void**)&zh, g_zh);
    cudaGetSymbolAddress((void**)&th, g_th);
    cudaGetSymbolAddress((void**)&vn, g_vn);
    cudaGetSymbolAddress((void**)&gsum, g_gsum);
    cudaGetSymbolAddress((void**)&vth, g_vth);
    cudaGetSymbolAddress((void**)&cb16, g_cb16);
    cudaGetSymbolAddress((void**)&cnt, g_cnt);
    cudaGetSymbolAddress((void**)&off, g_off);
    cudaGetSymbolAddress((void**)&rank, g_rank);
    cudaGetSymbolAddress((void**)&csr, g_csr);
    cudaGetSymbolAddress((void**)&Bhi, g_Bhi);
    cudaGetSymbolAddress((void**)&Blo, g_Blo);

    cudaFuncSetAttribute(gemm_uni_k, cudaFuncAttributeMaxDynamicSharedMemorySize,
                         SM_TOT);

    const int WSLOT = 32768;
    int gridND = (n * 32 + 255) / 256;

    int c1 = (10 * 32768 + 255) / 256;
    int c2 = c1 + (LL * 1000 * 32 + 255) / 256;
    int c3 = c2 + (n + 255) / 256;
    int c4b = c3 + (GG * 32 + 255) / 256;
    int c5 = c4b + gridND;
    int c6 = c5 + (GG * 32 + 255) / 256;
    fused_pre_k<<<c6, 256>>>(W1, W2, vnW1, vnW2, Bhi, Blo, bond, cb16,
                             cnt, gsum, x_atom, atomemb, h, vn0, vn,
                             n, c1, c2, c3, c4b, c5);
    count_k<<<(ecnt / 4 + 255) / 256, 256>>>(ei, cnt, rank, ecnt);
    scan_k<<<1, 1024>>>(cnt, off, n, ecnt);
    scatter_k<<<(ecnt + 255) / 256, 256>>>(ei, ea, off, rank, csr, ecnt);

    int gridM = (n + 127) / 128;
    int gxv = GG / 128;
    const int PERSIST = 296;   // 148 SMs x 2 CTAs
    for (int l = 0; l < LL; l++) {
        int hasVN = (l < LL - 1) ? 1 : 0;
        add_vn_k<<<gridND, 256>>>(h, h16, vn, batch, gsum, n, hasVN);
        edge_csr_k<<<gridND, 256>>>(off, csr, cb16 + (size_t)l * 1000 * DD,
                                    h, h16, eps + l, zh, n);
        {
            // GEMM1: single-limb W1; vn rider keeps 2 limbs.
            int ny0 = 4, ny1 = 4;
            int gx1 = hasVN ? gxv : 0;
            int total = gridM * ny0 + gx1 * ny1;
            int grid = total < PERSIST ? total : PERSIST;
            gemm_uni_k<<<grid, 256, SM_TOT>>>(
                gridM, ny0, n,
                zh,
                Bhi + (size_t)l * WSLOT, nullptr,
                b1v + l * 256, bn1g + l * 256, bn1b + l * 256,
                bn1m + l * 256, bn1v + l * 256,
                nullptr, th,
                gx1, ny1, hasVN ? GG : 0,
                vn, gsum, nullptr,
                Bhi + (size_t)(6 + l) * WSLOT, Blo + (size_t)(6 + l) * WSLOT,
                vnb1 + l * 256, vbn1g + l * 256, vbn1b + l * 256,
                vbn1m + l * 256, vbn1v + l * 256,
                nullptr, vth,
                nullptr, 0,
                256, 128, 1);
        }
        {
            // GEMM2: single-limb W2; vn rider keeps 2 limbs.
            float* outp = (l == LL - 1) ? (float*)d_out : h;
            int ny0 = 2, ny1 = 2;
            int gx1 = hasVN ? gxv : 0;
            int total = gridM * ny0 + gx1 * ny1;
            int grid = total < PERSIST ? total : PERSIST;
            gemm_uni_k<<<grid, 256, SM_TOT>>>(
                gridM, ny0, n,
                th,
                Bhi + (size_t)(3 + l) * WSLOT, nullptr,
                b2v + l * 128, bng + l * 128, bnb + l * 128,
                bnm + l * 128, bnv + l * 128,
                outp, nullptr,
                gx1, ny1, hasVN ? GG : 0,
                nullptr, nullptr, vth,
                Bhi + (size_t)(8 + l) * WSLOT, Blo + (size_t)(8 + l) * WSLOT,
                vnb2 + l * 128, vbn2g + l * 128, vbn2b + l * 128,
                vbn2m + l * 128, vbn2v + l * 128,
                vn, nullptr,
                (l == 0) ? (float4*)gsum : nullptr, GG * 32,
                128, 256, hasVN);
        }
    }
}